// round 9
// baseline (speedup 1.0000x reference)
#include <cuda_runtime.h>
#include <cuda_bf16.h>
#include <cstdint>

// ============================================================================
// AutoEncoder_BNN via mma.sync bf16. fp32 GEMMs emulated with K'=3K split:
//   A_cat = [A_hi | A_lo | A_hi],  B_cat = [B_hi | B_hi | B_lo]
// R5: Karatsuba mixing (3 GEMMs instead of 4).
// R8: engine = 128x128x64 tile, 256 thr, 3x32KB stages, 2 CTAs/SM; z-batching.
// R9: associativity — uw is LINEAR in h2, so
//       t1 = u@G^T        = h2 @ (G@Wyu)^T        + G@b_yu
//       t2 = w@Bm^T       = h2 @ (Bm@Wyw)^T       + Bm@b_yw
//       t3 = (u+w)@(G+Bm)^T = h2 @ ((G+Bm)@(Wyu+Wyw))^T + (G+Bm)@(b_yu+b_yw)
//     Mixing GEMMs drop from K=2048 to K=1024 (309 -> 154.5 split-GMAC); the
//     weight compositions are 3 small GEMMs (38.7 GMAC) outside the batch dim.
//     sumsplit and the stacked u/w split (MODE 2) are deleted.
// ============================================================================

// ---------------- device scratch (static; no runtime allocation) ------------
__device__ __nv_bfloat16 g_xcat [8192L  * 12288];
__device__ __nv_bfloat16 g_whcat[1024L  * 12288];
__device__ __nv_bfloat16 g_h1cat[8192L  * 3072];
__device__ __nv_bfloat16 g_wh2cat[1024L * 3072];
__device__ __nv_bfloat16 g_h2cat[8192L  * 3072];
__device__ __nv_bfloat16 g_wycat[4096L  * 3072];   // W_y B-side (for G3)
__device__ __nv_bfloat16 g_gacat[2048L  * 6144];   // G    A-side
__device__ __nv_bfloat16 g_bacat[2048L  * 6144];   // Bm   A-side
__device__ __nv_bfloat16 g_gpacat[2048L * 6144];   // G+Bm A-side
__device__ __nv_bfloat16 g_wytcat[3L * 1024 * 6144]; // WyuT | WywT | (Wyu+Wyw)T  B-side
__device__ float         g_wg   [3L * 2048 * 1024];  // composed weights fp32
__device__ __nv_bfloat16 g_wgcat[3L * 2048 * 3072];  // composed weights B-side
__device__ float         g_bg   [3L * 2048];         // composed biases
__device__ float         g_t    [3L * 8192 * 2048];  // t1|t2|t3
__device__ __nv_bfloat16 g_ppcat[8192L  * 6144];
__device__ __nv_bfloat16 g_qpcat[8192L  * 6144];
__device__ __nv_bfloat16 g_wpcat[2048L  * 6144];
__device__ __nv_bfloat16 g_wqcat[2048L  * 6144];

// ---------------- PTX helpers ------------------------------------------------
__device__ __forceinline__ uint32_t smem_u32(const void* p) {
    uint32_t a;
    asm("{ .reg .u64 t; cvta.to.shared.u64 t, %1; cvt.u32.u64 %0, t; }" : "=r"(a) : "l"(p));
    return a;
}
__device__ __forceinline__ void cp_async16(uint32_t dst, const void* src) {
    asm volatile("cp.async.cg.shared.global [%0], [%1], 16;" :: "r"(dst), "l"(src) : "memory");
}
__device__ __forceinline__ void cp_commit() {
    asm volatile("cp.async.commit_group;" ::: "memory");
}
__device__ __forceinline__ void cp_wait1() {
    asm volatile("cp.async.wait_group 1;" ::: "memory");
}
__device__ __forceinline__ void ldsm4(uint32_t* r, uint32_t addr) {
    asm volatile("ldmatrix.sync.aligned.m8n8.x4.shared.b16 {%0,%1,%2,%3}, [%4];"
                 : "=r"(r[0]), "=r"(r[1]), "=r"(r[2]), "=r"(r[3]) : "r"(addr));
}
__device__ __forceinline__ void mma16816(float* c, const uint32_t* a, uint32_t b0, uint32_t b1) {
    asm volatile(
        "mma.sync.aligned.m16n8k16.row.col.f32.bf16.bf16.f32 "
        "{%0,%1,%2,%3}, {%4,%5,%6,%7}, {%8,%9}, {%0,%1,%2,%3};"
        : "+f"(c[0]), "+f"(c[1]), "+f"(c[2]), "+f"(c[3])
        : "r"(a[0]), "r"(a[1]), "r"(a[2]), "r"(a[3]), "r"(b0), "r"(b1));
}
__device__ __forceinline__ void split2(float a, float b, __nv_bfloat162& h, __nv_bfloat162& l) {
    __nv_bfloat16 ha = __float2bfloat16(a);
    __nv_bfloat16 hb = __float2bfloat16(b);
    h.x = ha; h.y = hb;
    l.x = __float2bfloat16(a - __bfloat162float(ha));
    l.y = __float2bfloat16(b - __bfloat162float(hb));
}

// ---------------- mma.sync GEMM, tile 128x128x64, 256 threads (R8) -----------
// C[M,N] = act(A[M,K'] @ B[N,K']^T + bias); A,B bf16 K-major, fp32 accum.
// MODE 0: fp32 C.  MODE 1: bf16 split (hi|lo|hi) to S, stride 3*Nfull.
struct GemmArgs {
    const __nv_bfloat16* A;
    const __nv_bfloat16* B;
    const float* bias;
    float* C;
    __nv_bfloat16* S;
};

constexpr int SMEM_BYTES = 3 * 32768;   // 3 stages x (A 16KB + B 16KB)

template <int MODE, bool RELU, bool BIAS>
__global__ __launch_bounds__(256, 2)
void gemm_mma(GemmArgs g0, GemmArgs g1, GemmArgs g2,
              int lda, int ldb, int ldc, int Nfull, int K)
{
    const GemmArgs& g = (blockIdx.z == 0) ? g0 : (blockIdx.z == 1) ? g1 : g2;
    extern __shared__ __align__(1024) char smem[];
    const uint32_t sb = smem_u32(smem);
    const int tid = threadIdx.x, lane = tid & 31, wid = tid >> 5;
    const int wm = wid & 1, wn = wid >> 1;            // warp grid 2(m) x 4(n)
    const int m0 = blockIdx.y * 128, n0 = blockIdx.x * 128;

    // ---- global->shared loader mapping (16B chunks, SW128 swizzle) ----
    const int lrow = tid >> 3;        // 0..31 (4 waves of 32 rows)
    const int lc16 = tid & 7;         // 16B chunk within 128B row
    uint32_t ld_off[4];
#pragma unroll
    for (int w2 = 0; w2 < 4; ++w2) {
        const int r = lrow + w2 * 32;
        ld_off[w2] = r * 128 + ((lc16 * 16) ^ ((r & 7) << 4));
    }
    const __nv_bfloat16* Ag = g.A + (size_t)(m0 + lrow) * lda + lc16 * 8;
    const __nv_bfloat16* Bg = g.B + (size_t)(n0 + lrow) * ldb + lc16 * 8;

    // ---- ldmatrix address precompute ----
    uint32_t aTerm[4], aXor[4];
#pragma unroll
    for (int mt = 0; mt < 4; ++mt) {
        const int r = wm * 64 + mt * 16 + ((lane >> 3) & 1) * 8 + (lane & 7);
        aTerm[mt] = r * 128; aXor[mt] = (r & 7) << 4;
    }
    const uint32_t aCol = (lane >> 4) * 16;
    uint32_t bTerm[2], bXor[2];
#pragma unroll
    for (int nt = 0; nt < 2; ++nt) {
        const int r = wn * 32 + nt * 16 + (lane >> 4) * 8 + (lane & 7);
        bTerm[nt] = r * 128; bXor[nt] = (r & 7) << 4;
    }
    const uint32_t bCol = ((lane >> 3) & 1) * 16;

    float acc[4][4][4];
#pragma unroll
    for (int mt = 0; mt < 4; ++mt)
#pragma unroll
        for (int n8 = 0; n8 < 4; ++n8)
#pragma unroll
            for (int j = 0; j < 4; ++j) acc[mt][n8][j] = 0.0f;

    const int nst = K / 64;

    auto issue = [&](int s, int kt) {
        const uint32_t sa = sb + (uint32_t)s * 32768u;
#pragma unroll
        for (int w2 = 0; w2 < 4; ++w2)
            cp_async16(sa + ld_off[w2], Ag + (size_t)w2 * 32 * lda + kt);
#pragma unroll
        for (int w2 = 0; w2 < 4; ++w2)
            cp_async16(sa + 16384u + ld_off[w2], Bg + (size_t)w2 * 32 * ldb + kt);
        cp_commit();
    };

    issue(0, 0);
    issue(1, 64);

    for (int i = 0; i < nst; ++i) {
        cp_wait1();
        __syncthreads();
        if (i + 2 < nst) issue((i + 2) % 3, (i + 2) * 64);
        else             cp_commit();            // keep group counting uniform

        const uint32_t sa = sb + (uint32_t)(i % 3) * 32768u;
        const uint32_t sB = sa + 16384u;
#pragma unroll
        for (int kk = 0; kk < 4; ++kk) {
            uint32_t a[4][4], b[2][4];
#pragma unroll
            for (int mt = 0; mt < 4; ++mt)
                ldsm4(a[mt], sa + aTerm[mt] + ((kk * 32 + aCol) ^ aXor[mt]));
#pragma unroll
            for (int nt = 0; nt < 2; ++nt)
                ldsm4(b[nt], sB + bTerm[nt] + ((kk * 32 + bCol) ^ bXor[nt]));
#pragma unroll
            for (int mt = 0; mt < 4; ++mt)
#pragma unroll
                for (int n8 = 0; n8 < 4; ++n8)
                    mma16816(acc[mt][n8], a[mt],
                             b[n8 >> 1][(n8 & 1) * 2], b[n8 >> 1][(n8 & 1) * 2 + 1]);
        }
        __syncthreads();
    }

    // ---- epilogue ----
    float bb[4][2];
#pragma unroll
    for (int n8 = 0; n8 < 4; ++n8) {
        if (BIAS) {
            const int col = n0 + wn * 32 + n8 * 8 + (lane & 3) * 2;
            bb[n8][0] = __ldg(&g.bias[col]);
            bb[n8][1] = __ldg(&g.bias[col + 1]);
        } else { bb[n8][0] = 0.0f; bb[n8][1] = 0.0f; }
    }

#pragma unroll
    for (int mt = 0; mt < 4; ++mt) {
#pragma unroll
        for (int half = 0; half < 2; ++half) {
            const int r = m0 + wm * 64 + mt * 16 + (lane >> 2) + half * 8;
#pragma unroll
            for (int n8 = 0; n8 < 4; ++n8) {
                const int col = n0 + wn * 32 + n8 * 8 + (lane & 3) * 2;
                float v0 = acc[mt][n8][half * 2 + 0] + bb[n8][0];
                float v1 = acc[mt][n8][half * 2 + 1] + bb[n8][1];
                if (RELU) { v0 = fmaxf(v0, 0.0f); v1 = fmaxf(v1, 0.0f); }
                if (MODE == 0)
                    *reinterpret_cast<float2*>(g.C + (size_t)r * ldc + col) = make_float2(v0, v1);
                if (MODE == 1) {
                    __nv_bfloat162 h, l; split2(v0, v1, h, l);
                    __nv_bfloat16* Sr = g.S + (size_t)r * (3 * Nfull) + col;
                    *reinterpret_cast<__nv_bfloat162*>(Sr)             = h;
                    *reinterpret_cast<__nv_bfloat162*>(Sr + Nfull)     = l;
                    *reinterpret_cast<__nv_bfloat162*>(Sr + 2 * Nfull) = h;
                }
            }
        }
    }
}

// ------- pack: fp32 [R,C] -> bf16 split [R, 3C] -----------------------------
// B_SIDE=false (A operand): [hi | lo | hi].  B_SIDE=true (weights): [hi | hi | lo].
template <bool B_SIDE>
__global__ __launch_bounds__(256)
void pack2(const float* __restrict__ src, __nv_bfloat16* __restrict__ dst,
           int logC, long total)
{
    const long i = ((long)blockIdx.x * 256 + threadIdx.x) * 2;
    if (i >= total) return;
    const int  C = 1 << logC;
    const long r = i >> logC;
    const int  c = (int)(i & (C - 1));
    const float2 v = *reinterpret_cast<const float2*>(src + i);
    __nv_bfloat162 h, l; split2(v.x, v.y, h, l);
    __nv_bfloat16* d = dst + r * (3L * C) + c;
    if (B_SIDE) {
        *reinterpret_cast<__nv_bfloat162*>(d)         = h;
        *reinterpret_cast<__nv_bfloat162*>(d + C)     = h;
        *reinterpret_cast<__nv_bfloat162*>(d + 2 * C) = l;
    } else {
        *reinterpret_cast<__nv_bfloat162*>(d)         = h;
        *reinterpret_cast<__nv_bfloat162*>(d + C)     = l;
        *reinterpret_cast<__nv_bfloat162*>(d + 2 * C) = h;
    }
}

// ------- packadd2: (src0 + src1) -> split [R, 3C] ----------------------------
template <bool B_SIDE>
__global__ __launch_bounds__(256)
void packadd2(const float* __restrict__ s0, const float* __restrict__ s1,
              __nv_bfloat16* __restrict__ dst, int logC, long total)
{
    const long i = ((long)blockIdx.x * 256 + threadIdx.x) * 2;
    if (i >= total) return;
    const int  C = 1 << logC;
    const long r = i >> logC;
    const int  c = (int)(i & (C - 1));
    const float2 a = *reinterpret_cast<const float2*>(s0 + i);
    const float2 b = *reinterpret_cast<const float2*>(s1 + i);
    __nv_bfloat162 h, l; split2(a.x + b.x, a.y + b.y, h, l);
    __nv_bfloat16* d = dst + r * (3L * C) + c;
    if (B_SIDE) {
        *reinterpret_cast<__nv_bfloat162*>(d)         = h;
        *reinterpret_cast<__nv_bfloat162*>(d + C)     = h;
        *reinterpret_cast<__nv_bfloat162*>(d + 2 * C) = l;
    } else {
        *reinterpret_cast<__nv_bfloat162*>(d)         = h;
        *reinterpret_cast<__nv_bfloat162*>(d + C)     = l;
        *reinterpret_cast<__nv_bfloat162*>(d + 2 * C) = h;
    }
}

// ------- transpack: W_y halves -> transposed B-side split --------------------
// z=0: Wyu^T, z=1: Wyw^T, z=2: (Wyu+Wyw)^T.  Output [1024 rows, 3*2048] each.
// W_y is [4096, 1024]; Wyu = rows [0,2048), Wyw = rows [2048,4096).
__global__ __launch_bounds__(256)
void transpack(const float* __restrict__ Wy, __nv_bfloat16* __restrict__ dst)
{
    __shared__ float tile[32][33];
    const int z  = blockIdx.z;
    const int j0 = blockIdx.x * 32;     // output row block (j: 0..1023)
    const int k0 = blockIdx.y * 32;     // K block          (k: 0..2047)
    const int tx = threadIdx.x & 31, ty = threadIdx.x >> 5;   // 32 x 8

#pragma unroll
    for (int rr = ty; rr < 32; rr += 8) {
        const int k = k0 + rr, j = j0 + tx;
        float v;
        if (z == 0)      v = Wy[(size_t)k * 1024 + j];
        else if (z == 1) v = Wy[(size_t)(k + 2048) * 1024 + j];
        else             v = Wy[(size_t)k * 1024 + j] + Wy[(size_t)(k + 2048) * 1024 + j];
        tile[rr][tx] = v;
    }
    __syncthreads();
#pragma unroll
    for (int rr = ty; rr < 32; rr += 8) {
        const int j = j0 + rr;
        const float v = tile[tx][rr];
        const __nv_bfloat16 h = __float2bfloat16(v);
        const __nv_bfloat16 l = __float2bfloat16(v - __bfloat162float(h));
        __nv_bfloat16* d = dst + (size_t)z * 1024 * 6144 + (size_t)j * 6144 + k0 + tx;
        d[0] = h; d[2048] = h; d[4096] = l;
    }
}

// ------- biasdot: bg1=G@b_yu, bg2=Bm@b_yw, bg3=(G+Bm)@(b_yu+b_yw) -------------
__global__ __launch_bounds__(256)
void biasdot(const float* __restrict__ G, const float* __restrict__ Bm,
             const float* __restrict__ b_y, float* __restrict__ bg)
{
    const int c = blockIdx.x, tid = threadIdx.x, lane = tid & 31, w = tid >> 5;
    float s1 = 0, s2 = 0, s3 = 0;
    for (int k = tid; k < 2048; k += 256) {
        const float g = G[(size_t)c * 2048 + k], bm = Bm[(size_t)c * 2048 + k];
        const float byu = b_y[k], byw = b_y[2048 + k];
        s1 += g * byu; s2 += bm * byw; s3 += (g + bm) * (byu + byw);
    }
#pragma unroll
    for (int o = 16; o; o >>= 1) {
        s1 += __shfl_down_sync(0xFFFFFFFFu, s1, o);
        s2 += __shfl_down_sync(0xFFFFFFFFu, s2, o);
        s3 += __shfl_down_sync(0xFFFFFFFFu, s3, o);
    }
    __shared__ float sh[3][8];
    if (lane == 0) { sh[0][w] = s1; sh[1][w] = s2; sh[2][w] = s3; }
    __syncthreads();
    if (tid == 0) {
        float a = 0, b = 0, d = 0;
#pragma unroll
        for (int i = 0; i < 8; ++i) { a += sh[0][i]; b += sh[1][i]; d += sh[2][i]; }
        bg[c] = a; bg[2048 + c] = b; bg[4096 + c] = d;
    }
}

// ---------------- polar combine (Karatsuba) -> split pp/qp -------------------
__global__ __launch_bounds__(256)
void combine(const float* __restrict__ uw, const float* __restrict__ t,
             const float* __restrict__ bias_p, const float* __restrict__ bias_q,
             __nv_bfloat16* __restrict__ ppcat, __nv_bfloat16* __restrict__ qpcat)
{
    const long i = ((long)blockIdx.x * 256 + threadIdx.x) * 2;
    const long r = i >> 11;
    const int  c = (int)(i & 2047);
    const float2 u2 = *reinterpret_cast<const float2*>(uw + r * 4096 + c);
    const float2 w2 = *reinterpret_cast<const float2*>(uw + r * 4096 + 2048 + c);
    const float2 t1 = *reinterpret_cast<const float2*>(t + i);
    const float2 t2 = *reinterpret_cast<const float2*>(t + 8192L * 2048 + i);
    const float2 t3 = *reinterpret_cast<const float2*>(t + 2L * 8192 * 2048 + i);
    const float2 bp = *reinterpret_cast<const float2*>(bias_p + c);
    const float2 bq = *reinterpret_cast<const float2*>(bias_q + c);
    const float re0 = t1.x - t2.x, re1 = t1.y - t2.y;
    const float im0 = t3.x - t1.x - t2.x, im1 = t3.y - t1.y - t2.y;
    const float p0 = u2.x * re0 + w2.x * im0 + bp.x;
    const float p1 = u2.y * re1 + w2.y * im1 + bp.y;
    const float q0 = w2.x * re0 - u2.x * im0 + bq.x;
    const float q1 = w2.y * re1 - u2.y * im1 + bq.y;
    __nv_bfloat162 h, l;
    __nv_bfloat16* d = ppcat + r * 6144 + c;
    split2(p0, p1, h, l);
    *reinterpret_cast<__nv_bfloat162*>(d)        = h;
    *reinterpret_cast<__nv_bfloat162*>(d + 2048) = l;
    *reinterpret_cast<__nv_bfloat162*>(d + 4096) = h;
    d = qpcat + r * 6144 + c;
    split2(q0, q1, h, l);
    *reinterpret_cast<__nv_bfloat162*>(d)        = h;
    *reinterpret_cast<__nv_bfloat162*>(d + 2048) = l;
    *reinterpret_cast<__nv_bfloat162*>(d + 4096) = h;
}

// ---------------- host side --------------------------------------------------
extern "C" void kernel_launch(void* const* d_in, const int* in_sizes, int n_in,
                              void* d_out, int out_size)
{
    const float* x      = (const float*)d_in[0];
    const float* W_h    = (const float*)d_in[1];
    const float* b_h    = (const float*)d_in[2];
    const float* W_h2   = (const float*)d_in[3];
    const float* b_h2   = (const float*)d_in[4];
    const float* W_y    = (const float*)d_in[5];
    const float* b_y    = (const float*)d_in[6];
    const float* G      = (const float*)d_in[7];
    const float* Bm     = (const float*)d_in[8];
    const float* bias_p = (const float*)d_in[9];
    const float* bias_q = (const float*)d_in[10];
    const float* W_p    = (const float*)d_in[11];
    const float* b_p    = (const float*)d_in[12];
    const float* W_q    = (const float*)d_in[13];
    const float* b_q    = (const float*)d_in[14];

    float* out = (float*)d_out;
    float* uw  = out;
    float* p   = out + (size_t)8192 * 4096;
    float* q   = p   + (size_t)8192 * 2048;

    __nv_bfloat16 *xcat, *whcat, *h1cat, *wh2cat, *h2cat, *wycat,
                  *gacat, *bacat, *gpacat, *wytcat, *wgcat,
                  *ppcat, *qpcat, *wpcat, *wqcat;
    float *t, *wg, *bg;
    cudaGetSymbolAddress((void**)&xcat,  g_xcat);
    cudaGetSymbolAddress((void**)&whcat, g_whcat);
    cudaGetSymbolAddress((void**)&h1cat, g_h1cat);
    cudaGetSymbolAddress((void**)&wh2cat,g_wh2cat);
    cudaGetSymbolAddress((void**)&h2cat, g_h2cat);
    cudaGetSymbolAddress((void**)&wycat, g_wycat);
    cudaGetSymbolAddress((void**)&gacat, g_gacat);
    cudaGetSymbolAddress((void**)&bacat, g_bacat);
    cudaGetSymbolAddress((void**)&gpacat,g_gpacat);
    cudaGetSymbolAddress((void**)&wytcat,g_wytcat);
    cudaGetSymbolAddress((void**)&wg,    g_wg);
    cudaGetSymbolAddress((void**)&wgcat, g_wgcat);
    cudaGetSymbolAddress((void**)&bg,    g_bg);
    cudaGetSymbolAddress((void**)&t,     g_t);
    cudaGetSymbolAddress((void**)&ppcat, g_ppcat);
    cudaGetSymbolAddress((void**)&qpcat, g_qpcat);
    cudaGetSymbolAddress((void**)&wpcat, g_wpcat);
    cudaGetSymbolAddress((void**)&wqcat, g_wqcat);

    cudaFuncSetAttribute(gemm_mma<1, true,  true >, cudaFuncAttributeMaxDynamicSharedMemorySize, SMEM_BYTES);
    cudaFuncSetAttribute(gemm_mma<0, false, false>, cudaFuncAttributeMaxDynamicSharedMemorySize, SMEM_BYTES);
    cudaFuncSetAttribute(gemm_mma<0, false, true >, cudaFuncAttributeMaxDynamicSharedMemorySize, SMEM_BYTES);

    // ---- packs ----
    pack2<false><<<(8192L * 4096 / 2 + 255) / 256, 256>>>(x,    xcat,   12, 8192L * 4096);
    pack2<true ><<<(1024L * 4096 / 2 + 255) / 256, 256>>>(W_h,  whcat,  12, 1024L * 4096);
    pack2<true ><<<(1024L * 1024 / 2 + 255) / 256, 256>>>(W_h2, wh2cat, 10, 1024L * 1024);
    pack2<true ><<<(4096L * 1024 / 2 + 255) / 256, 256>>>(W_y,  wycat,  10, 4096L * 1024);
    pack2<false><<<(2048L * 2048 / 2 + 255) / 256, 256>>>(G,    gacat,  11, 2048L * 2048);
    pack2<false><<<(2048L * 2048 / 2 + 255) / 256, 256>>>(Bm,   bacat,  11, 2048L * 2048);
    packadd2<false><<<(2048L * 2048 / 2 + 255) / 256, 256>>>(G, Bm, gpacat, 11, 2048L * 2048);
    transpack<<<dim3(32, 64, 3), 256>>>(W_y, wytcat);
    biasdot<<<2048, 256>>>(G, Bm, b_y, bg);
    pack2<true ><<<(2048L * 2048 / 2 + 255) / 256, 256>>>(W_p,  wpcat,  11, 2048L * 2048);
    pack2<true ><<<(2048L * 2048 / 2 + 255) / 256, 256>>>(W_q,  wqcat,  11, 2048L * 2048);

    const dim3 blk(256);
    // Weight composition: Wg = G@Wyu, Wb = Bm@Wyw, Ws = (G+Bm)@(Wyu+Wyw)
    // [2048, 1024], K'=6144.  One z=3 launch.
    {
        GemmArgs a0{gacat,  wytcat,                nullptr, wg,                 nullptr};
        GemmArgs a1{bacat,  wytcat + 1024L * 6144, nullptr, wg + 2048L * 1024,  nullptr};
        GemmArgs a2{gpacat, wytcat + 2048L * 6144, nullptr, wg + 2L * 2048 * 1024, nullptr};
        gemm_mma<0, false, false><<<dim3(1024 / 128, 2048 / 128, 3), blk, SMEM_BYTES>>>(
            a0, a1, a2, 6144, 6144, 1024, 1024, 6144);
    }
    // pack composed weights (3 stacked as 6144 rows of 1024) -> B-side split
    pack2<true ><<<(6144L * 1024 / 2 + 255) / 256, 256>>>(wg, wgcat, 10, 6144L * 1024);

    // G1: h1 = relu(x @ W_h^T + b_h) -> split h1cat
    {
        GemmArgs a{xcat, whcat, b_h, nullptr, h1cat};
        gemm_mma<1, true, true><<<dim3(1024 / 128, 8192 / 128, 1), blk, SMEM_BYTES>>>(
            a, a, a, 12288, 12288, 0, 1024, 12288);
    }
    // G2: h2 = relu(h1 @ W_h2^T + b_h2) -> split h2cat
    {
        GemmArgs a{h1cat, wh2cat, b_h2, nullptr, h2cat};
        gemm_mma<1, true, true><<<dim3(1024 / 128, 8192 / 128, 1), blk, SMEM_BYTES>>>(
            a, a, a, 3072, 3072, 0, 1024, 3072);
    }
    // G3: uw = h2 @ W_y^T + b_y -> fp32 uw (d_out)
    {
        GemmArgs a{h2cat, wycat, b_y, uw, nullptr};
        gemm_mma<0, false, true><<<dim3(4096 / 128, 8192 / 128, 1), blk, SMEM_BYTES>>>(
            a, a, a, 3072, 3072, 4096, 4096, 3072);
    }
    // Mixing (composed): t_i = h2 @ Wg_i^T + bg_i   [8192, 2048], K'=3072, z=3
    {
        GemmArgs a0{h2cat, wgcat,                bg,        t,                    nullptr};
        GemmArgs a1{h2cat, wgcat + 2048L * 3072, bg + 2048, t + 8192L * 2048,     nullptr};
        GemmArgs a2{h2cat, wgcat + 2L * 2048 * 3072, bg + 4096, t + 2L * 8192 * 2048, nullptr};
        gemm_mma<0, false, true><<<dim3(2048 / 128, 8192 / 128, 3), blk, SMEM_BYTES>>>(
            a0, a1, a2, 3072, 3072, 2048, 2048, 3072);
    }
    // combine -> split pp/qp
    combine<<<(8192L * 2048 / 2) / 256, 256>>>(uw, t, bias_p, bias_q, ppcat, qpcat);
    // G5/G6: final projections (one launch)
    {
        GemmArgs a0{ppcat, wpcat, b_p, p, nullptr};
        GemmArgs a1{qpcat, wqcat, b_q, q, nullptr};
        gemm_mma<0, false, true><<<dim3(2048 / 128, 8192 / 128, 2), blk, SMEM_BYTES>>>(
            a0, a1, a0, 6144, 6144, 2048, 2048, 6144);
    }
}

// round 10
// speedup vs baseline: 1.5202x; 1.5202x over previous
#include <cuda_runtime.h>
#include <cuda_bf16.h>
#include <cstdint>

// ============================================================================
// AutoEncoder_BNN via mma.sync bf16. fp32 GEMMs emulated with K'=3K split:
//   A_cat = [A_hi | A_lo | A_hi],  B_cat = [B_hi | B_hi | B_lo]
// R5: Karatsuba mixing (3 GEMMs instead of 4).
// R8: engine = 128x128x64 tile, 256 thr, 3x32KB stages, 2 CTAs/SM; z-batching.
// R9/R10: associativity — uw is LINEAR in h2, so
//       t1 = u@G^T          = h2 @ (G@Wyu)^T             + G@b_yu
//       t2 = w@Bm^T         = h2 @ (Bm@Wyw)^T            + Bm@b_yw
//       t3 = (u+w)@(G+Bm)^T = h2 @ ((G+Bm)@(Wyu+Wyw))^T  + (G+Bm)@(b_yu+b_yw)
//     Mixing GEMMs drop K 2048 -> 1024 (-155 split-GMAC); compositions cost
//     +39 split-GMAC outside the batch dim. R10 = re-bench of R9: the R9 run
//     showed a 30% slowdown on a byte-identical pack kernel (clock throttle),
//     so the +1.16ms result is attributed to environment pending this repeat.
// ============================================================================

// ---------------- device scratch (static; no runtime allocation) ------------
__device__ __nv_bfloat16 g_xcat [8192L  * 12288];
__device__ __nv_bfloat16 g_whcat[1024L  * 12288];
__device__ __nv_bfloat16 g_h1cat[8192L  * 3072];
__device__ __nv_bfloat16 g_wh2cat[1024L * 3072];
__device__ __nv_bfloat16 g_h2cat[8192L  * 3072];
__device__ __nv_bfloat16 g_wycat[4096L  * 3072];   // W_y B-side (for G3)
__device__ __nv_bfloat16 g_gacat[2048L  * 6144];   // G    A-side
__device__ __nv_bfloat16 g_bacat[2048L  * 6144];   // Bm   A-side
__device__ __nv_bfloat16 g_gpacat[2048L * 6144];   // G+Bm A-side
__device__ __nv_bfloat16 g_wytcat[3L * 1024 * 6144]; // WyuT | WywT | (Wyu+Wyw)T  B-side
__device__ float         g_wg   [3L * 2048 * 1024];  // composed weights fp32
__device__ __nv_bfloat16 g_wgcat[3L * 2048 * 3072];  // composed weights B-side
__device__ float         g_bg   [3L * 2048];         // composed biases
__device__ float         g_t    [3L * 8192 * 2048];  // t1|t2|t3
__device__ __nv_bfloat16 g_ppcat[8192L  * 6144];
__device__ __nv_bfloat16 g_qpcat[8192L  * 6144];
__device__ __nv_bfloat16 g_wpcat[2048L  * 6144];
__device__ __nv_bfloat16 g_wqcat[2048L  * 6144];

// ---------------- PTX helpers ------------------------------------------------
__device__ __forceinline__ uint32_t smem_u32(const void* p) {
    uint32_t a;
    asm("{ .reg .u64 t; cvta.to.shared.u64 t, %1; cvt.u32.u64 %0, t; }" : "=r"(a) : "l"(p));
    return a;
}
__device__ __forceinline__ void cp_async16(uint32_t dst, const void* src) {
    asm volatile("cp.async.cg.shared.global [%0], [%1], 16;" :: "r"(dst), "l"(src) : "memory");
}
__device__ __forceinline__ void cp_commit() {
    asm volatile("cp.async.commit_group;" ::: "memory");
}
__device__ __forceinline__ void cp_wait1() {
    asm volatile("cp.async.wait_group 1;" ::: "memory");
}
__device__ __forceinline__ void ldsm4(uint32_t* r, uint32_t addr) {
    asm volatile("ldmatrix.sync.aligned.m8n8.x4.shared.b16 {%0,%1,%2,%3}, [%4];"
                 : "=r"(r[0]), "=r"(r[1]), "=r"(r[2]), "=r"(r[3]) : "r"(addr));
}
__device__ __forceinline__ void mma16816(float* c, const uint32_t* a, uint32_t b0, uint32_t b1) {
    asm volatile(
        "mma.sync.aligned.m16n8k16.row.col.f32.bf16.bf16.f32 "
        "{%0,%1,%2,%3}, {%4,%5,%6,%7}, {%8,%9}, {%0,%1,%2,%3};"
        : "+f"(c[0]), "+f"(c[1]), "+f"(c[2]), "+f"(c[3])
        : "r"(a[0]), "r"(a[1]), "r"(a[2]), "r"(a[3]), "r"(b0), "r"(b1));
}
__device__ __forceinline__ void split2(float a, float b, __nv_bfloat162& h, __nv_bfloat162& l) {
    __nv_bfloat16 ha = __float2bfloat16(a);
    __nv_bfloat16 hb = __float2bfloat16(b);
    h.x = ha; h.y = hb;
    l.x = __float2bfloat16(a - __bfloat162float(ha));
    l.y = __float2bfloat16(b - __bfloat162float(hb));
}

// ---------------- mma.sync GEMM, tile 128x128x64, 256 threads (R8) -----------
// C[M,N] = act(A[M,K'] @ B[N,K']^T + bias); A,B bf16 K-major, fp32 accum.
// MODE 0: fp32 C.  MODE 1: bf16 split (hi|lo|hi) to S, stride 3*Nfull.
struct GemmArgs {
    const __nv_bfloat16* A;
    const __nv_bfloat16* B;
    const float* bias;
    float* C;
    __nv_bfloat16* S;
};

constexpr int SMEM_BYTES = 3 * 32768;   // 3 stages x (A 16KB + B 16KB)

template <int MODE, bool RELU, bool BIAS>
__global__ __launch_bounds__(256, 2)
void gemm_mma(GemmArgs g0, GemmArgs g1, GemmArgs g2,
              int lda, int ldb, int ldc, int Nfull, int K)
{
    const GemmArgs& g = (blockIdx.z == 0) ? g0 : (blockIdx.z == 1) ? g1 : g2;
    extern __shared__ __align__(1024) char smem[];
    const uint32_t sb = smem_u32(smem);
    const int tid = threadIdx.x, lane = tid & 31, wid = tid >> 5;
    const int wm = wid & 1, wn = wid >> 1;            // warp grid 2(m) x 4(n)
    const int m0 = blockIdx.y * 128, n0 = blockIdx.x * 128;

    // ---- global->shared loader mapping (16B chunks, SW128 swizzle) ----
    const int lrow = tid >> 3;        // 0..31 (4 waves of 32 rows)
    const int lc16 = tid & 7;         // 16B chunk within 128B row
    uint32_t ld_off[4];
#pragma unroll
    for (int w2 = 0; w2 < 4; ++w2) {
        const int r = lrow + w2 * 32;
        ld_off[w2] = r * 128 + ((lc16 * 16) ^ ((r & 7) << 4));
    }
    const __nv_bfloat16* Ag = g.A + (size_t)(m0 + lrow) * lda + lc16 * 8;
    const __nv_bfloat16* Bg = g.B + (size_t)(n0 + lrow) * ldb + lc16 * 8;

    // ---- ldmatrix address precompute ----
    uint32_t aTerm[4], aXor[4];
#pragma unroll
    for (int mt = 0; mt < 4; ++mt) {
        const int r = wm * 64 + mt * 16 + ((lane >> 3) & 1) * 8 + (lane & 7);
        aTerm[mt] = r * 128; aXor[mt] = (r & 7) << 4;
    }
    const uint32_t aCol = (lane >> 4) * 16;
    uint32_t bTerm[2], bXor[2];
#pragma unroll
    for (int nt = 0; nt < 2; ++nt) {
        const int r = wn * 32 + nt * 16 + (lane >> 4) * 8 + (lane & 7);
        bTerm[nt] = r * 128; bXor[nt] = (r & 7) << 4;
    }
    const uint32_t bCol = ((lane >> 3) & 1) * 16;

    float acc[4][4][4];
#pragma unroll
    for (int mt = 0; mt < 4; ++mt)
#pragma unroll
        for (int n8 = 0; n8 < 4; ++n8)
#pragma unroll
            for (int j = 0; j < 4; ++j) acc[mt][n8][j] = 0.0f;

    const int nst = K / 64;

    auto issue = [&](int s, int kt) {
        const uint32_t sa = sb + (uint32_t)s * 32768u;
#pragma unroll
        for (int w2 = 0; w2 < 4; ++w2)
            cp_async16(sa + ld_off[w2], Ag + (size_t)w2 * 32 * lda + kt);
#pragma unroll
        for (int w2 = 0; w2 < 4; ++w2)
            cp_async16(sa + 16384u + ld_off[w2], Bg + (size_t)w2 * 32 * ldb + kt);
        cp_commit();
    };

    issue(0, 0);
    issue(1, 64);

    for (int i = 0; i < nst; ++i) {
        cp_wait1();
        __syncthreads();
        if (i + 2 < nst) issue((i + 2) % 3, (i + 2) * 64);
        else             cp_commit();            // keep group counting uniform

        const uint32_t sa = sb + (uint32_t)(i % 3) * 32768u;
        const uint32_t sB = sa + 16384u;
#pragma unroll
        for (int kk = 0; kk < 4; ++kk) {
            uint32_t a[4][4], b[2][4];
#pragma unroll
            for (int mt = 0; mt < 4; ++mt)
                ldsm4(a[mt], sa + aTerm[mt] + ((kk * 32 + aCol) ^ aXor[mt]));
#pragma unroll
            for (int nt = 0; nt < 2; ++nt)
                ldsm4(b[nt], sB + bTerm[nt] + ((kk * 32 + bCol) ^ bXor[nt]));
#pragma unroll
            for (int mt = 0; mt < 4; ++mt)
#pragma unroll
                for (int n8 = 0; n8 < 4; ++n8)
                    mma16816(acc[mt][n8], a[mt],
                             b[n8 >> 1][(n8 & 1) * 2], b[n8 >> 1][(n8 & 1) * 2 + 1]);
        }
        __syncthreads();
    }

    // ---- epilogue ----
    float bb[4][2];
#pragma unroll
    for (int n8 = 0; n8 < 4; ++n8) {
        if (BIAS) {
            const int col = n0 + wn * 32 + n8 * 8 + (lane & 3) * 2;
            bb[n8][0] = __ldg(&g.bias[col]);
            bb[n8][1] = __ldg(&g.bias[col + 1]);
        } else { bb[n8][0] = 0.0f; bb[n8][1] = 0.0f; }
    }

#pragma unroll
    for (int mt = 0; mt < 4; ++mt) {
#pragma unroll
        for (int half = 0; half < 2; ++half) {
            const int r = m0 + wm * 64 + mt * 16 + (lane >> 2) + half * 8;
#pragma unroll
            for (int n8 = 0; n8 < 4; ++n8) {
                const int col = n0 + wn * 32 + n8 * 8 + (lane & 3) * 2;
                float v0 = acc[mt][n8][half * 2 + 0] + bb[n8][0];
                float v1 = acc[mt][n8][half * 2 + 1] + bb[n8][1];
                if (RELU) { v0 = fmaxf(v0, 0.0f); v1 = fmaxf(v1, 0.0f); }
                if (MODE == 0)
                    *reinterpret_cast<float2*>(g.C + (size_t)r * ldc + col) = make_float2(v0, v1);
                if (MODE == 1) {
                    __nv_bfloat162 h, l; split2(v0, v1, h, l);
                    __nv_bfloat16* Sr = g.S + (size_t)r * (3 * Nfull) + col;
                    *reinterpret_cast<__nv_bfloat162*>(Sr)             = h;
                    *reinterpret_cast<__nv_bfloat162*>(Sr + Nfull)     = l;
                    *reinterpret_cast<__nv_bfloat162*>(Sr + 2 * Nfull) = h;
                }
            }
        }
    }
}

// ------- pack: fp32 [R,C] -> bf16 split [R, 3C] -----------------------------
// B_SIDE=false (A operand): [hi | lo | hi].  B_SIDE=true (weights): [hi | hi | lo].
template <bool B_SIDE>
__global__ __launch_bounds__(256)
void pack2(const float* __restrict__ src, __nv_bfloat16* __restrict__ dst,
           int logC, long total)
{
    const long i = ((long)blockIdx.x * 256 + threadIdx.x) * 2;
    if (i >= total) return;
    const int  C = 1 << logC;
    const long r = i >> logC;
    const int  c = (int)(i & (C - 1));
    const float2 v = *reinterpret_cast<const float2*>(src + i);
    __nv_bfloat162 h, l; split2(v.x, v.y, h, l);
    __nv_bfloat16* d = dst + r * (3L * C) + c;
    if (B_SIDE) {
        *reinterpret_cast<__nv_bfloat162*>(d)         = h;
        *reinterpret_cast<__nv_bfloat162*>(d + C)     = h;
        *reinterpret_cast<__nv_bfloat162*>(d + 2 * C) = l;
    } else {
        *reinterpret_cast<__nv_bfloat162*>(d)         = h;
        *reinterpret_cast<__nv_bfloat162*>(d + C)     = l;
        *reinterpret_cast<__nv_bfloat162*>(d + 2 * C) = h;
    }
}

// ------- packadd2: (src0 + src1) -> split [R, 3C] ----------------------------
template <bool B_SIDE>
__global__ __launch_bounds__(256)
void packadd2(const float* __restrict__ s0, const float* __restrict__ s1,
              __nv_bfloat16* __restrict__ dst, int logC, long total)
{
    const long i = ((long)blockIdx.x * 256 + threadIdx.x) * 2;
    if (i >= total) return;
    const int  C = 1 << logC;
    const long r = i >> logC;
    const int  c = (int)(i & (C - 1));
    const float2 a = *reinterpret_cast<const float2*>(s0 + i);
    const float2 b = *reinterpret_cast<const float2*>(s1 + i);
    __nv_bfloat162 h, l; split2(a.x + b.x, a.y + b.y, h, l);
    __nv_bfloat16* d = dst + r * (3L * C) + c;
    if (B_SIDE) {
        *reinterpret_cast<__nv_bfloat162*>(d)         = h;
        *reinterpret_cast<__nv_bfloat162*>(d + C)     = h;
        *reinterpret_cast<__nv_bfloat162*>(d + 2 * C) = l;
    } else {
        *reinterpret_cast<__nv_bfloat162*>(d)         = h;
        *reinterpret_cast<__nv_bfloat162*>(d + C)     = l;
        *reinterpret_cast<__nv_bfloat162*>(d + 2 * C) = h;
    }
}

// ------- transpack: W_y halves -> transposed B-side split --------------------
// z=0: Wyu^T, z=1: Wyw^T, z=2: (Wyu+Wyw)^T.  Output [1024 rows, 3*2048] each.
// W_y is [4096, 1024]; Wyu = rows [0,2048), Wyw = rows [2048,4096).
__global__ __launch_bounds__(256)
void transpack(const float* __restrict__ Wy, __nv_bfloat16* __restrict__ dst)
{
    __shared__ float tile[32][33];
    const int z  = blockIdx.z;
    const int j0 = blockIdx.x * 32;     // output row block (j: 0..1023)
    const int k0 = blockIdx.y * 32;     // K block          (k: 0..2047)
    const int tx = threadIdx.x & 31, ty = threadIdx.x >> 5;   // 32 x 8

#pragma unroll
    for (int rr = ty; rr < 32; rr += 8) {
        const int k = k0 + rr, j = j0 + tx;
        float v;
        if (z == 0)      v = Wy[(size_t)k * 1024 + j];
        else if (z == 1) v = Wy[(size_t)(k + 2048) * 1024 + j];
        else             v = Wy[(size_t)k * 1024 + j] + Wy[(size_t)(k + 2048) * 1024 + j];
        tile[rr][tx] = v;
    }
    __syncthreads();
#pragma unroll
    for (int rr = ty; rr < 32; rr += 8) {
        const int j = j0 + rr;
        const float v = tile[tx][rr];
        const __nv_bfloat16 h = __float2bfloat16(v);
        const __nv_bfloat16 l = __float2bfloat16(v - __bfloat162float(h));
        __nv_bfloat16* d = dst + (size_t)z * 1024 * 6144 + (size_t)j * 6144 + k0 + tx;
        d[0] = h; d[2048] = h; d[4096] = l;
    }
}

// ------- biasdot: bg1=G@b_yu, bg2=Bm@b_yw, bg3=(G+Bm)@(b_yu+b_yw) -------------
__global__ __launch_bounds__(256)
void biasdot(const float* __restrict__ G, const float* __restrict__ Bm,
             const float* __restrict__ b_y, float* __restrict__ bg)
{
    const int c = blockIdx.x, tid = threadIdx.x, lane = tid & 31, w = tid >> 5;
    float s1 = 0, s2 = 0, s3 = 0;
    for (int k = tid; k < 2048; k += 256) {
        const float g = G[(size_t)c * 2048 + k], bm = Bm[(size_t)c * 2048 + k];
        const float byu = b_y[k], byw = b_y[2048 + k];
        s1 += g * byu; s2 += bm * byw; s3 += (g + bm) * (byu + byw);
    }
#pragma unroll
    for (int o = 16; o; o >>= 1) {
        s1 += __shfl_down_sync(0xFFFFFFFFu, s1, o);
        s2 += __shfl_down_sync(0xFFFFFFFFu, s2, o);
        s3 += __shfl_down_sync(0xFFFFFFFFu, s3, o);
    }
    __shared__ float sh[3][8];
    if (lane == 0) { sh[0][w] = s1; sh[1][w] = s2; sh[2][w] = s3; }
    __syncthreads();
    if (tid == 0) {
        float a = 0, b = 0, d = 0;
#pragma unroll
        for (int i = 0; i < 8; ++i) { a += sh[0][i]; b += sh[1][i]; d += sh[2][i]; }
        bg[c] = a; bg[2048 + c] = b; bg[4096 + c] = d;
    }
}

// ---------------- polar combine (Karatsuba) -> split pp/qp -------------------
__global__ __launch_bounds__(256)
void combine(const float* __restrict__ uw, const float* __restrict__ t,
             const float* __restrict__ bias_p, const float* __restrict__ bias_q,
             __nv_bfloat16* __restrict__ ppcat, __nv_bfloat16* __restrict__ qpcat)
{
    const long i = ((long)blockIdx.x * 256 + threadIdx.x) * 2;
    const long r = i >> 11;
    const int  c = (int)(i & 2047);
    const float2 u2 = *reinterpret_cast<const float2*>(uw + r * 4096 + c);
    const float2 w2 = *reinterpret_cast<const float2*>(uw + r * 4096 + 2048 + c);
    const float2 t1 = *reinterpret_cast<const float2*>(t + i);
    const float2 t2 = *reinterpret_cast<const float2*>(t + 8192L * 2048 + i);
    const float2 t3 = *reinterpret_cast<const float2*>(t + 2L * 8192 * 2048 + i);
    const float2 bp = *reinterpret_cast<const float2*>(bias_p + c);
    const float2 bq = *reinterpret_cast<const float2*>(bias_q + c);
    const float re0 = t1.x - t2.x, re1 = t1.y - t2.y;
    const float im0 = t3.x - t1.x - t2.x, im1 = t3.y - t1.y - t2.y;
    const float p0 = u2.x * re0 + w2.x * im0 + bp.x;
    const float p1 = u2.y * re1 + w2.y * im1 + bp.y;
    const float q0 = w2.x * re0 - u2.x * im0 + bq.x;
    const float q1 = w2.y * re1 - u2.y * im1 + bq.y;
    __nv_bfloat162 h, l;
    __nv_bfloat16* d = ppcat + r * 6144 + c;
    split2(p0, p1, h, l);
    *reinterpret_cast<__nv_bfloat162*>(d)        = h;
    *reinterpret_cast<__nv_bfloat162*>(d + 2048) = l;
    *reinterpret_cast<__nv_bfloat162*>(d + 4096) = h;
    d = qpcat + r * 6144 + c;
    split2(q0, q1, h, l);
    *reinterpret_cast<__nv_bfloat162*>(d)        = h;
    *reinterpret_cast<__nv_bfloat162*>(d + 2048) = l;
    *reinterpret_cast<__nv_bfloat162*>(d + 4096) = h;
}

// ---------------- host side --------------------------------------------------
extern "C" void kernel_launch(void* const* d_in, const int* in_sizes, int n_in,
                              void* d_out, int out_size)
{
    const float* x      = (const float*)d_in[0];
    const float* W_h    = (const float*)d_in[1];
    const float* b_h    = (const float*)d_in[2];
    const float* W_h2   = (const float*)d_in[3];
    const float* b_h2   = (const float*)d_in[4];
    const float* W_y    = (const float*)d_in[5];
    const float* b_y    = (const float*)d_in[6];
    const float* G      = (const float*)d_in[7];
    const float* Bm     = (const float*)d_in[8];
    const float* bias_p = (const float*)d_in[9];
    const float* bias_q = (const float*)d_in[10];
    const float* W_p    = (const float*)d_in[11];
    const float* b_p    = (const float*)d_in[12];
    const float* W_q    = (const float*)d_in[13];
    const float* b_q    = (const float*)d_in[14];

    float* out = (float*)d_out;
    float* uw  = out;
    float* p   = out + (size_t)8192 * 4096;
    float* q   = p   + (size_t)8192 * 2048;

    __nv_bfloat16 *xcat, *whcat, *h1cat, *wh2cat, *h2cat, *wycat,
                  *gacat, *bacat, *gpacat, *wytcat, *wgcat,
                  *ppcat, *qpcat, *wpcat, *wqcat;
    float *t, *wg, *bg;
    cudaGetSymbolAddress((void**)&xcat,  g_xcat);
    cudaGetSymbolAddress((void**)&whcat, g_whcat);
    cudaGetSymbolAddress((void**)&h1cat, g_h1cat);
    cudaGetSymbolAddress((void**)&wh2cat,g_wh2cat);
    cudaGetSymbolAddress((void**)&h2cat, g_h2cat);
    cudaGetSymbolAddress((void**)&wycat, g_wycat);
    cudaGetSymbolAddress((void**)&gacat, g_gacat);
    cudaGetSymbolAddress((void**)&bacat, g_bacat);
    cudaGetSymbolAddress((void**)&gpacat,g_gpacat);
    cudaGetSymbolAddress((void**)&wytcat,g_wytcat);
    cudaGetSymbolAddress((void**)&wg,    g_wg);
    cudaGetSymbolAddress((void**)&wgcat, g_wgcat);
    cudaGetSymbolAddress((void**)&bg,    g_bg);
    cudaGetSymbolAddress((void**)&t,     g_t);
    cudaGetSymbolAddress((void**)&ppcat, g_ppcat);
    cudaGetSymbolAddress((void**)&qpcat, g_qpcat);
    cudaGetSymbolAddress((void**)&wpcat, g_wpcat);
    cudaGetSymbolAddress((void**)&wqcat, g_wqcat);

    cudaFuncSetAttribute(gemm_mma<1, true,  true >, cudaFuncAttributeMaxDynamicSharedMemorySize, SMEM_BYTES);
    cudaFuncSetAttribute(gemm_mma<0, false, false>, cudaFuncAttributeMaxDynamicSharedMemorySize, SMEM_BYTES);
    cudaFuncSetAttribute(gemm_mma<0, false, true >, cudaFuncAttributeMaxDynamicSharedMemorySize, SMEM_BYTES);

    // ---- packs ----
    pack2<false><<<(8192L * 4096 / 2 + 255) / 256, 256>>>(x,    xcat,   12, 8192L * 4096);
    pack2<true ><<<(1024L * 4096 / 2 + 255) / 256, 256>>>(W_h,  whcat,  12, 1024L * 4096);
    pack2<true ><<<(1024L * 1024 / 2 + 255) / 256, 256>>>(W_h2, wh2cat, 10, 1024L * 1024);
    pack2<true ><<<(4096L * 1024 / 2 + 255) / 256, 256>>>(W_y,  wycat,  10, 4096L * 1024);
    pack2<false><<<(2048L * 2048 / 2 + 255) / 256, 256>>>(G,    gacat,  11, 2048L * 2048);
    pack2<false><<<(2048L * 2048 / 2 + 255) / 256, 256>>>(Bm,   bacat,  11, 2048L * 2048);
    packadd2<false><<<(2048L * 2048 / 2 + 255) / 256, 256>>>(G, Bm, gpacat, 11, 2048L * 2048);
    transpack<<<dim3(32, 64, 3), 256>>>(W_y, wytcat);
    biasdot<<<2048, 256>>>(G, Bm, b_y, bg);
    pack2<true ><<<(2048L * 2048 / 2 + 255) / 256, 256>>>(W_p,  wpcat,  11, 2048L * 2048);
    pack2<true ><<<(2048L * 2048 / 2 + 255) / 256, 256>>>(W_q,  wqcat,  11, 2048L * 2048);

    const dim3 blk(256);
    // Weight composition: Wg = G@Wyu, Wb = Bm@Wyw, Ws = (G+Bm)@(Wyu+Wyw)
    // [2048, 1024], K'=6144.  One z=3 launch.
    {
        GemmArgs a0{gacat,  wytcat,                nullptr, wg,                 nullptr};
        GemmArgs a1{bacat,  wytcat + 1024L * 6144, nullptr, wg + 2048L * 1024,  nullptr};
        GemmArgs a2{gpacat, wytcat + 2048L * 6144, nullptr, wg + 2L * 2048 * 1024, nullptr};
        gemm_mma<0, false, false><<<dim3(1024 / 128, 2048 / 128, 3), blk, SMEM_BYTES>>>(
            a0, a1, a2, 6144, 6144, 1024, 1024, 6144);
    }
    // pack composed weights (3 stacked as 6144 rows of 1024) -> B-side split
    pack2<true ><<<(6144L * 1024 / 2 + 255) / 256, 256>>>(wg, wgcat, 10, 6144L * 1024);

    // G1: h1 = relu(x @ W_h^T + b_h) -> split h1cat
    {
        GemmArgs a{xcat, whcat, b_h, nullptr, h1cat};
        gemm_mma<1, true, true><<<dim3(1024 / 128, 8192 / 128, 1), blk, SMEM_BYTES>>>(
            a, a, a, 12288, 12288, 0, 1024, 12288);
    }
    // G2: h2 = relu(h1 @ W_h2^T + b_h2) -> split h2cat
    {
        GemmArgs a{h1cat, wh2cat, b_h2, nullptr, h2cat};
        gemm_mma<1, true, true><<<dim3(1024 / 128, 8192 / 128, 1), blk, SMEM_BYTES>>>(
            a, a, a, 3072, 3072, 0, 1024, 3072);
    }
    // G3: uw = h2 @ W_y^T + b_y -> fp32 uw (d_out)
    {
        GemmArgs a{h2cat, wycat, b_y, uw, nullptr};
        gemm_mma<0, false, true><<<dim3(4096 / 128, 8192 / 128, 1), blk, SMEM_BYTES>>>(
            a, a, a, 3072, 3072, 4096, 4096, 3072);
    }
    // Mixing (composed): t_i = h2 @ Wg_i^T + bg_i   [8192, 2048], K'=3072, z=3
    {
        GemmArgs a0{h2cat, wgcat,                bg,        t,                    nullptr};
        GemmArgs a1{h2cat, wgcat + 2048L * 3072, bg + 2048, t + 8192L * 2048,     nullptr};
        GemmArgs a2{h2cat, wgcat + 2L * 2048 * 3072, bg + 4096, t + 2L * 8192 * 2048, nullptr};
        gemm_mma<0, false, true><<<dim3(2048 / 128, 8192 / 128, 3), blk, SMEM_BYTES>>>(
            a0, a1, a2, 3072, 3072, 2048, 2048, 3072);
    }
    // combine -> split pp/qp
    combine<<<(8192L * 2048 / 2) / 256, 256>>>(uw, t, bias_p, bias_q, ppcat, qpcat);
    // G5/G6: final projections (one launch)
    {
        GemmArgs a0{ppcat, wpcat, b_p, p, nullptr};
        GemmArgs a1{qpcat, wqcat, b_q, q, nullptr};
        gemm_mma<0, false, true><<<dim3(2048 / 128, 8192 / 128, 2), blk, SMEM_BYTES>>>(
            a0, a1, a0, 6144, 6144, 2048, 2048, 6144);
    }
}

// round 11
// speedup vs baseline: 1.5344x; 1.0093x over previous
#include <cuda_runtime.h>
#include <cuda_bf16.h>
#include <cstdint>

// ============================================================================
// AutoEncoder_BNN via mma.sync bf16. fp32 GEMMs emulated with K'=3K split:
//   A_cat = [A_hi | A_lo | A_hi],  B_cat = [B_hi | B_hi | B_lo]
// R5: Karatsuba mixing. R8: engine 128x128x64/256thr/3stage/2CTA-SM + z-batch.
// R9/R10: weight composition via associativity (mixing K 2048 -> 1024).
// R11: (a) drop redundant trailing __syncthreads in GEMM mainloop (sync#1 of
//      the next iteration already orders stage reuse); (b) elementwise kernels
//      widened to 4 elems/thread (float4); (c) mixing as ONE [8192,6144] GEMM
//      (wgcat/bg already row-stacked) -> t1|t2|t3 land in the same row.
// ============================================================================

// ---------------- device scratch (static; no runtime allocation) ------------
__device__ __nv_bfloat16 g_xcat [8192L  * 12288];
__device__ __nv_bfloat16 g_whcat[1024L  * 12288];
__device__ __nv_bfloat16 g_h1cat[8192L  * 3072];
__device__ __nv_bfloat16 g_wh2cat[1024L * 3072];
__device__ __nv_bfloat16 g_h2cat[8192L  * 3072];
__device__ __nv_bfloat16 g_wycat[4096L  * 3072];   // W_y B-side (for G3)
__device__ __nv_bfloat16 g_gacat[2048L  * 6144];   // G    A-side
__device__ __nv_bfloat16 g_bacat[2048L  * 6144];   // Bm   A-side
__device__ __nv_bfloat16 g_gpacat[2048L * 6144];   // G+Bm A-side
__device__ __nv_bfloat16 g_wytcat[3L * 1024 * 6144]; // WyuT | WywT | (Wyu+Wyw)T
__device__ float         g_wg   [3L * 2048 * 1024];  // composed weights fp32 (stacked rows)
__device__ __nv_bfloat16 g_wgcat[3L * 2048 * 3072];  // composed weights B-side (stacked rows)
__device__ float         g_bg   [3L * 2048];         // composed biases (stacked)
__device__ float         g_t    [8192L * 6144];      // [t1|t2|t3] row-major
__device__ __nv_bfloat16 g_ppcat[8192L  * 6144];
__device__ __nv_bfloat16 g_qpcat[8192L  * 6144];
__device__ __nv_bfloat16 g_wpcat[2048L  * 6144];
__device__ __nv_bfloat16 g_wqcat[2048L  * 6144];

// ---------------- PTX helpers ------------------------------------------------
__device__ __forceinline__ uint32_t smem_u32(const void* p) {
    uint32_t a;
    asm("{ .reg .u64 t; cvta.to.shared.u64 t, %1; cvt.u32.u64 %0, t; }" : "=r"(a) : "l"(p));
    return a;
}
__device__ __forceinline__ void cp_async16(uint32_t dst, const void* src) {
    asm volatile("cp.async.cg.shared.global [%0], [%1], 16;" :: "r"(dst), "l"(src) : "memory");
}
__device__ __forceinline__ void cp_commit() {
    asm volatile("cp.async.commit_group;" ::: "memory");
}
__device__ __forceinline__ void cp_wait1() {
    asm volatile("cp.async.wait_group 1;" ::: "memory");
}
__device__ __forceinline__ void ldsm4(uint32_t* r, uint32_t addr) {
    asm volatile("ldmatrix.sync.aligned.m8n8.x4.shared.b16 {%0,%1,%2,%3}, [%4];"
                 : "=r"(r[0]), "=r"(r[1]), "=r"(r[2]), "=r"(r[3]) : "r"(addr));
}
__device__ __forceinline__ void mma16816(float* c, const uint32_t* a, uint32_t b0, uint32_t b1) {
    asm volatile(
        "mma.sync.aligned.m16n8k16.row.col.f32.bf16.bf16.f32 "
        "{%0,%1,%2,%3}, {%4,%5,%6,%7}, {%8,%9}, {%0,%1,%2,%3};"
        : "+f"(c[0]), "+f"(c[1]), "+f"(c[2]), "+f"(c[3])
        : "r"(a[0]), "r"(a[1]), "r"(a[2]), "r"(a[3]), "r"(b0), "r"(b1));
}
__device__ __forceinline__ void split2(float a, float b, __nv_bfloat162& h, __nv_bfloat162& l) {
    __nv_bfloat16 ha = __float2bfloat16(a);
    __nv_bfloat16 hb = __float2bfloat16(b);
    h.x = ha; h.y = hb;
    l.x = __float2bfloat16(a - __bfloat162float(ha));
    l.y = __float2bfloat16(b - __bfloat162float(hb));
}
// pack two bf162 into one 8B store
__device__ __forceinline__ uint2 pack8(__nv_bfloat162 a, __nv_bfloat162 b) {
    uint2 r;
    r.x = *reinterpret_cast<uint32_t*>(&a);
    r.y = *reinterpret_cast<uint32_t*>(&b);
    return r;
}

// ---------------- mma.sync GEMM, tile 128x128x64, 256 threads ----------------
// C[M,N] = act(A[M,K'] @ B[N,K']^T + bias); A,B bf16 K-major, fp32 accum.
// MODE 0: fp32 C.  MODE 1: bf16 split (hi|lo|hi) to S, stride 3*Nfull.
struct GemmArgs {
    const __nv_bfloat16* A;
    const __nv_bfloat16* B;
    const float* bias;
    float* C;
    __nv_bfloat16* S;
};

constexpr int SMEM_BYTES = 3 * 32768;   // 3 stages x (A 16KB + B 16KB)

template <int MODE, bool RELU, bool BIAS>
__global__ __launch_bounds__(256, 2)
void gemm_mma(GemmArgs g0, GemmArgs g1, GemmArgs g2,
              int lda, int ldb, int ldc, int Nfull, int K)
{
    const GemmArgs& g = (blockIdx.z == 0) ? g0 : (blockIdx.z == 1) ? g1 : g2;
    extern __shared__ __align__(1024) char smem[];
    const uint32_t sb = smem_u32(smem);
    const int tid = threadIdx.x, lane = tid & 31, wid = tid >> 5;
    const int wm = wid & 1, wn = wid >> 1;            // warp grid 2(m) x 4(n)
    const int m0 = blockIdx.y * 128, n0 = blockIdx.x * 128;

    // ---- global->shared loader mapping (16B chunks, SW128 swizzle) ----
    const int lrow = tid >> 3;        // 0..31 (4 waves of 32 rows)
    const int lc16 = tid & 7;         // 16B chunk within 128B row
    uint32_t ld_off[4];
#pragma unroll
    for (int w2 = 0; w2 < 4; ++w2) {
        const int r = lrow + w2 * 32;
        ld_off[w2] = r * 128 + ((lc16 * 16) ^ ((r & 7) << 4));
    }
    const __nv_bfloat16* Ag = g.A + (size_t)(m0 + lrow) * lda + lc16 * 8;
    const __nv_bfloat16* Bg = g.B + (size_t)(n0 + lrow) * ldb + lc16 * 8;

    // ---- ldmatrix address precompute ----
    uint32_t aTerm[4], aXor[4];
#pragma unroll
    for (int mt = 0; mt < 4; ++mt) {
        const int r = wm * 64 + mt * 16 + ((lane >> 3) & 1) * 8 + (lane & 7);
        aTerm[mt] = r * 128; aXor[mt] = (r & 7) << 4;
    }
    const uint32_t aCol = (lane >> 4) * 16;
    uint32_t bTerm[2], bXor[2];
#pragma unroll
    for (int nt = 0; nt < 2; ++nt) {
        const int r = wn * 32 + nt * 16 + (lane >> 4) * 8 + (lane & 7);
        bTerm[nt] = r * 128; bXor[nt] = (r & 7) << 4;
    }
    const uint32_t bCol = ((lane >> 3) & 1) * 16;

    float acc[4][4][4];
#pragma unroll
    for (int mt = 0; mt < 4; ++mt)
#pragma unroll
        for (int n8 = 0; n8 < 4; ++n8)
#pragma unroll
            for (int j = 0; j < 4; ++j) acc[mt][n8][j] = 0.0f;

    const int nst = K / 64;

    auto issue = [&](int s, int kt) {
        const uint32_t sa = sb + (uint32_t)s * 32768u;
#pragma unroll
        for (int w2 = 0; w2 < 4; ++w2)
            cp_async16(sa + ld_off[w2], Ag + (size_t)w2 * 32 * lda + kt);
#pragma unroll
        for (int w2 = 0; w2 < 4; ++w2)
            cp_async16(sa + 16384u + ld_off[w2], Bg + (size_t)w2 * 32 * ldb + kt);
        cp_commit();
    };

    issue(0, 0);
    issue(1, 64);

    for (int i = 0; i < nst; ++i) {
        cp_wait1();
        __syncthreads();   // orders: all warps done reading stage (i-1)%3 == (i+2)%3
        if (i + 2 < nst) issue((i + 2) % 3, (i + 2) * 64);
        else             cp_commit();            // keep group counting uniform

        const uint32_t sa = sb + (uint32_t)(i % 3) * 32768u;
        const uint32_t sB = sa + 16384u;
#pragma unroll
        for (int kk = 0; kk < 4; ++kk) {
            uint32_t a[4][4], b[2][4];
#pragma unroll
            for (int mt = 0; mt < 4; ++mt)
                ldsm4(a[mt], sa + aTerm[mt] + ((kk * 32 + aCol) ^ aXor[mt]));
#pragma unroll
            for (int nt = 0; nt < 2; ++nt)
                ldsm4(b[nt], sB + bTerm[nt] + ((kk * 32 + bCol) ^ bXor[nt]));
#pragma unroll
            for (int mt = 0; mt < 4; ++mt)
#pragma unroll
                for (int n8 = 0; n8 < 4; ++n8)
                    mma16816(acc[mt][n8], a[mt],
                             b[n8 >> 1][(n8 & 1) * 2], b[n8 >> 1][(n8 & 1) * 2 + 1]);
        }
        // NOTE: no trailing __syncthreads — next iteration's sync#1 already
        // guarantees stage (i+2)%3 is not rewritten before all reads finish.
    }

    // ---- epilogue ----
    float bb[4][2];
#pragma unroll
    for (int n8 = 0; n8 < 4; ++n8) {
        if (BIAS) {
            const int col = n0 + wn * 32 + n8 * 8 + (lane & 3) * 2;
            bb[n8][0] = __ldg(&g.bias[col]);
            bb[n8][1] = __ldg(&g.bias[col + 1]);
        } else { bb[n8][0] = 0.0f; bb[n8][1] = 0.0f; }
    }

#pragma unroll
    for (int mt = 0; mt < 4; ++mt) {
#pragma unroll
        for (int half = 0; half < 2; ++half) {
            const int r = m0 + wm * 64 + mt * 16 + (lane >> 2) + half * 8;
#pragma unroll
            for (int n8 = 0; n8 < 4; ++n8) {
                const int col = n0 + wn * 32 + n8 * 8 + (lane & 3) * 2;
                float v0 = acc[mt][n8][half * 2 + 0] + bb[n8][0];
                float v1 = acc[mt][n8][half * 2 + 1] + bb[n8][1];
                if (RELU) { v0 = fmaxf(v0, 0.0f); v1 = fmaxf(v1, 0.0f); }
                if (MODE == 0)
                    *reinterpret_cast<float2*>(g.C + (size_t)r * ldc + col) = make_float2(v0, v1);
                if (MODE == 1) {
                    __nv_bfloat162 h, l; split2(v0, v1, h, l);
                    __nv_bfloat16* Sr = g.S + (size_t)r * (3 * Nfull) + col;
                    *reinterpret_cast<__nv_bfloat162*>(Sr)             = h;
                    *reinterpret_cast<__nv_bfloat162*>(Sr + Nfull)     = l;
                    *reinterpret_cast<__nv_bfloat162*>(Sr + 2 * Nfull) = h;
                }
            }
        }
    }
}

// ------- pack: fp32 [R,C] -> bf16 split [R, 3C], 4 elems/thread --------------
// B_SIDE=false (A operand): [hi | lo | hi].  B_SIDE=true (weights): [hi | hi | lo].
template <bool B_SIDE>
__global__ __launch_bounds__(256)
void pack2(const float* __restrict__ src, __nv_bfloat16* __restrict__ dst,
           int logC, long total)
{
    const long i = ((long)blockIdx.x * 256 + threadIdx.x) * 4;
    if (i >= total) return;
    const int  C = 1 << logC;
    const long r = i >> logC;
    const int  c = (int)(i & (C - 1));
    const float4 v = *reinterpret_cast<const float4*>(src + i);
    __nv_bfloat162 h0, l0, h1, l1;
    split2(v.x, v.y, h0, l0);
    split2(v.z, v.w, h1, l1);
    const uint2 H = pack8(h0, h1), L = pack8(l0, l1);
    __nv_bfloat16* d = dst + r * (3L * C) + c;
    if (B_SIDE) {
        *reinterpret_cast<uint2*>(d)         = H;
        *reinterpret_cast<uint2*>(d + C)     = H;
        *reinterpret_cast<uint2*>(d + 2 * C) = L;
    } else {
        *reinterpret_cast<uint2*>(d)         = H;
        *reinterpret_cast<uint2*>(d + C)     = L;
        *reinterpret_cast<uint2*>(d + 2 * C) = H;
    }
}

// ------- packadd2: (src0 + src1) -> split, 4 elems/thread --------------------
template <bool B_SIDE>
__global__ __launch_bounds__(256)
void packadd2(const float* __restrict__ s0, const float* __restrict__ s1,
              __nv_bfloat16* __restrict__ dst, int logC, long total)
{
    const long i = ((long)blockIdx.x * 256 + threadIdx.x) * 4;
    if (i >= total) return;
    const int  C = 1 << logC;
    const long r = i >> logC;
    const int  c = (int)(i & (C - 1));
    const float4 a = *reinterpret_cast<const float4*>(s0 + i);
    const float4 b = *reinterpret_cast<const float4*>(s1 + i);
    __nv_bfloat162 h0, l0, h1, l1;
    split2(a.x + b.x, a.y + b.y, h0, l0);
    split2(a.z + b.z, a.w + b.w, h1, l1);
    const uint2 H = pack8(h0, h1), L = pack8(l0, l1);
    __nv_bfloat16* d = dst + r * (3L * C) + c;
    if (B_SIDE) {
        *reinterpret_cast<uint2*>(d)         = H;
        *reinterpret_cast<uint2*>(d + C)     = H;
        *reinterpret_cast<uint2*>(d + 2 * C) = L;
    } else {
        *reinterpret_cast<uint2*>(d)         = H;
        *reinterpret_cast<uint2*>(d + C)     = L;
        *reinterpret_cast<uint2*>(d + 2 * C) = H;
    }
}

// ------- transpack: W_y halves -> transposed B-side split --------------------
// z=0: Wyu^T, z=1: Wyw^T, z=2: (Wyu+Wyw)^T.  Output [1024 rows, 3*2048] each.
__global__ __launch_bounds__(256)
void transpack(const float* __restrict__ Wy, __nv_bfloat16* __restrict__ dst)
{
    __shared__ float tile[32][33];
    const int z  = blockIdx.z;
    const int j0 = blockIdx.x * 32;
    const int k0 = blockIdx.y * 32;
    const int tx = threadIdx.x & 31, ty = threadIdx.x >> 5;

#pragma unroll
    for (int rr = ty; rr < 32; rr += 8) {
        const int k = k0 + rr, j = j0 + tx;
        float v;
        if (z == 0)      v = Wy[(size_t)k * 1024 + j];
        else if (z == 1) v = Wy[(size_t)(k + 2048) * 1024 + j];
        else             v = Wy[(size_t)k * 1024 + j] + Wy[(size_t)(k + 2048) * 1024 + j];
        tile[rr][tx] = v;
    }
    __syncthreads();
#pragma unroll
    for (int rr = ty; rr < 32; rr += 8) {
        const int j = j0 + rr;
        const float v = tile[tx][rr];
        const __nv_bfloat16 h = __float2bfloat16(v);
        const __nv_bfloat16 l = __float2bfloat16(v - __bfloat162float(h));
        __nv_bfloat16* d = dst + (size_t)z * 1024 * 6144 + (size_t)j * 6144 + k0 + tx;
        d[0] = h; d[2048] = h; d[4096] = l;
    }
}

// ------- biasdot: bg1=G@b_yu, bg2=Bm@b_yw, bg3=(G+Bm)@(b_yu+b_yw) -------------
__global__ __launch_bounds__(256)
void biasdot(const float* __restrict__ G, const float* __restrict__ Bm,
             const float* __restrict__ b_y, float* __restrict__ bg)
{
    const int c = blockIdx.x, tid = threadIdx.x, lane = tid & 31, w = tid >> 5;
    float s1 = 0, s2 = 0, s3 = 0;
    for (int k = tid; k < 2048; k += 256) {
        const float g = G[(size_t)c * 2048 + k], bm = Bm[(size_t)c * 2048 + k];
        const float byu = b_y[k], byw = b_y[2048 + k];
        s1 += g * byu; s2 += bm * byw; s3 += (g + bm) * (byu + byw);
    }
#pragma unroll
    for (int o = 16; o; o >>= 1) {
        s1 += __shfl_down_sync(0xFFFFFFFFu, s1, o);
        s2 += __shfl_down_sync(0xFFFFFFFFu, s2, o);
        s3 += __shfl_down_sync(0xFFFFFFFFu, s3, o);
    }
    __shared__ float sh[3][8];
    if (lane == 0) { sh[0][w] = s1; sh[1][w] = s2; sh[2][w] = s3; }
    __syncthreads();
    if (tid == 0) {
        float a = 0, b = 0, d = 0;
#pragma unroll
        for (int i = 0; i < 8; ++i) { a += sh[0][i]; b += sh[1][i]; d += sh[2][i]; }
        bg[c] = a; bg[2048 + c] = b; bg[4096 + c] = d;
    }
}

// ---------------- polar combine (Karatsuba) -> split pp/qp, 4 elems/thread ---
// t layout: [8192, 6144] with t1 = cols [0,2048), t2 = [2048,4096), t3 = [4096,6144)
__global__ __launch_bounds__(256)
void combine(const float* __restrict__ uw, const float* __restrict__ t,
             const float* __restrict__ bias_p, const float* __restrict__ bias_q,
             __nv_bfloat16* __restrict__ ppcat, __nv_bfloat16* __restrict__ qpcat)
{
    const long i = ((long)blockIdx.x * 256 + threadIdx.x) * 4;   // [0, 8192*2048)
    const long r = i >> 11;
    const int  c = (int)(i & 2047);
    const float4 u4 = *reinterpret_cast<const float4*>(uw + r * 4096 + c);
    const float4 w4 = *reinterpret_cast<const float4*>(uw + r * 4096 + 2048 + c);
    const float4 t1 = *reinterpret_cast<const float4*>(t + r * 6144 + c);
    const float4 t2 = *reinterpret_cast<const float4*>(t + r * 6144 + 2048 + c);
    const float4 t3 = *reinterpret_cast<const float4*>(t + r * 6144 + 4096 + c);
    const float4 bp = *reinterpret_cast<const float4*>(bias_p + c);
    const float4 bq = *reinterpret_cast<const float4*>(bias_q + c);

    float pv[4], qv[4];
    const float uu[4] = {u4.x, u4.y, u4.z, u4.w};
    const float ww[4] = {w4.x, w4.y, w4.z, w4.w};
    const float a1[4] = {t1.x, t1.y, t1.z, t1.w};
    const float a2[4] = {t2.x, t2.y, t2.z, t2.w};
    const float a3[4] = {t3.x, t3.y, t3.z, t3.w};
    const float bpv[4] = {bp.x, bp.y, bp.z, bp.w};
    const float bqv[4] = {bq.x, bq.y, bq.z, bq.w};
#pragma unroll
    for (int j = 0; j < 4; ++j) {
        const float re = a1[j] - a2[j];
        const float im = a3[j] - a1[j] - a2[j];
        pv[j] = uu[j] * re + ww[j] * im + bpv[j];
        qv[j] = ww[j] * re - uu[j] * im + bqv[j];
    }

    __nv_bfloat162 h0, l0, h1, l1;
    split2(pv[0], pv[1], h0, l0); split2(pv[2], pv[3], h1, l1);
    {
        const uint2 H = pack8(h0, h1), L = pack8(l0, l1);
        __nv_bfloat16* d = ppcat + r * 6144 + c;
        *reinterpret_cast<uint2*>(d)        = H;
        *reinterpret_cast<uint2*>(d + 2048) = L;
        *reinterpret_cast<uint2*>(d + 4096) = H;
    }
    split2(qv[0], qv[1], h0, l0); split2(qv[2], qv[3], h1, l1);
    {
        const uint2 H = pack8(h0, h1), L = pack8(l0, l1);
        __nv_bfloat16* d = qpcat + r * 6144 + c;
        *reinterpret_cast<uint2*>(d)        = H;
        *reinterpret_cast<uint2*>(d + 2048) = L;
        *reinterpret_cast<uint2*>(d + 4096) = H;
    }
}

// ---------------- host side --------------------------------------------------
extern "C" void kernel_launch(void* const* d_in, const int* in_sizes, int n_in,
                              void* d_out, int out_size)
{
    const float* x      = (const float*)d_in[0];
    const float* W_h    = (const float*)d_in[1];
    const float* b_h    = (const float*)d_in[2];
    const float* W_h2   = (const float*)d_in[3];
    const float* b_h2   = (const float*)d_in[4];
    const float* W_y    = (const float*)d_in[5];
    const float* b_y    = (const float*)d_in[6];
    const float* G      = (const float*)d_in[7];
    const float* Bm     = (const float*)d_in[8];
    const float* bias_p = (const float*)d_in[9];
    const float* bias_q = (const float*)d_in[10];
    const float* W_p    = (const float*)d_in[11];
    const float* b_p    = (const float*)d_in[12];
    const float* W_q    = (const float*)d_in[13];
    const float* b_q    = (const float*)d_in[14];

    float* out = (float*)d_out;
    float* uw  = out;
    float* p   = out + (size_t)8192 * 4096;
    float* q   = p   + (size_t)8192 * 2048;

    __nv_bfloat16 *xcat, *whcat, *h1cat, *wh2cat, *h2cat, *wycat,
                  *gacat, *bacat, *gpacat, *wytcat, *wgcat,
                  *ppcat, *qpcat, *wpcat, *wqcat;
    float *t, *wg, *bg;
    cudaGetSymbolAddress((void**)&xcat,  g_xcat);
    cudaGetSymbolAddress((void**)&whcat, g_whcat);
    cudaGetSymbolAddress((void**)&h1cat, g_h1cat);
    cudaGetSymbolAddress((void**)&wh2cat,g_wh2cat);
    cudaGetSymbolAddress((void**)&h2cat, g_h2cat);
    cudaGetSymbolAddress((void**)&wycat, g_wycat);
    cudaGetSymbolAddress((void**)&gacat, g_gacat);
    cudaGetSymbolAddress((void**)&bacat, g_bacat);
    cudaGetSymbolAddress((void**)&gpacat,g_gpacat);
    cudaGetSymbolAddress((void**)&wytcat,g_wytcat);
    cudaGetSymbolAddress((void**)&wg,    g_wg);
    cudaGetSymbolAddress((void**)&wgcat, g_wgcat);
    cudaGetSymbolAddress((void**)&bg,    g_bg);
    cudaGetSymbolAddress((void**)&t,     g_t);
    cudaGetSymbolAddress((void**)&ppcat, g_ppcat);
    cudaGetSymbolAddress((void**)&qpcat, g_qpcat);
    cudaGetSymbolAddress((void**)&wpcat, g_wpcat);
    cudaGetSymbolAddress((void**)&wqcat, g_wqcat);

    cudaFuncSetAttribute(gemm_mma<1, true,  true >, cudaFuncAttributeMaxDynamicSharedMemorySize, SMEM_BYTES);
    cudaFuncSetAttribute(gemm_mma<0, false, false>, cudaFuncAttributeMaxDynamicSharedMemorySize, SMEM_BYTES);
    cudaFuncSetAttribute(gemm_mma<0, false, true >, cudaFuncAttributeMaxDynamicSharedMemorySize, SMEM_BYTES);

    // ---- packs (4 elems/thread) ----
    pack2<false><<<(8192L * 4096 / 4 + 255) / 256, 256>>>(x,    xcat,   12, 8192L * 4096);
    pack2<true ><<<(1024L * 4096 / 4 + 255) / 256, 256>>>(W_h,  whcat,  12, 1024L * 4096);
    pack2<true ><<<(1024L * 1024 / 4 + 255) / 256, 256>>>(W_h2, wh2cat, 10, 1024L * 1024);
    pack2<true ><<<(4096L * 1024 / 4 + 255) / 256, 256>>>(W_y,  wycat,  10, 4096L * 1024);
    pack2<false><<<(2048L * 2048 / 4 + 255) / 256, 256>>>(G,    gacat,  11, 2048L * 2048);
    pack2<false><<<(2048L * 2048 / 4 + 255) / 256, 256>>>(Bm,   bacat,  11, 2048L * 2048);
    packadd2<false><<<(2048L * 2048 / 4 + 255) / 256, 256>>>(G, Bm, gpacat, 11, 2048L * 2048);
    transpack<<<dim3(32, 64, 3), 256>>>(W_y, wytcat);
    biasdot<<<2048, 256>>>(G, Bm, b_y, bg);
    pack2<true ><<<(2048L * 2048 / 4 + 255) / 256, 256>>>(W_p,  wpcat,  11, 2048L * 2048);
    pack2<true ><<<(2048L * 2048 / 4 + 255) / 256, 256>>>(W_q,  wqcat,  11, 2048L * 2048);

    const dim3 blk(256);
    // Weight composition: Wg = G@Wyu, Wb = Bm@Wyw, Ws = (G+Bm)@(Wyu+Wyw)
    // [2048, 1024] each, K'=6144. One z=3 launch; outputs stacked in wg rows.
    {
        GemmArgs a0{gacat,  wytcat,                nullptr, wg,                 nullptr};
        GemmArgs a1{bacat,  wytcat + 1024L * 6144, nullptr, wg + 2048L * 1024,  nullptr};
        GemmArgs a2{gpacat, wytcat + 2048L * 6144, nullptr, wg + 2L * 2048 * 1024, nullptr};
        gemm_mma<0, false, false><<<dim3(1024 / 128, 2048 / 128, 3), blk, SMEM_BYTES>>>(
            a0, a1, a2, 6144, 6144, 1024, 1024, 6144);
    }
    // pack composed weights (stacked: 6144 rows of 1024) -> B-side split
    pack2<true ><<<(6144L * 1024 / 4 + 255) / 256, 256>>>(wg, wgcat, 10, 6144L * 1024);

    // G1: h1 = relu(x @ W_h^T + b_h) -> split h1cat
    {
        GemmArgs a{xcat, whcat, b_h, nullptr, h1cat};
        gemm_mma<1, true, true><<<dim3(1024 / 128, 8192 / 128, 1), blk, SMEM_BYTES>>>(
            a, a, a, 12288, 12288, 0, 1024, 12288);
    }
    // G2: h2 = relu(h1 @ W_h2^T + b_h2) -> split h2cat
    {
        GemmArgs a{h1cat, wh2cat, b_h2, nullptr, h2cat};
        gemm_mma<1, true, true><<<dim3(1024 / 128, 8192 / 128, 1), blk, SMEM_BYTES>>>(
            a, a, a, 3072, 3072, 0, 1024, 3072);
    }
    // G3: uw = h2 @ W_y^T + b_y -> fp32 uw (d_out)
    {
        GemmArgs a{h2cat, wycat, b_y, uw, nullptr};
        gemm_mma<0, false, true><<<dim3(4096 / 128, 8192 / 128, 1), blk, SMEM_BYTES>>>(
            a, a, a, 3072, 3072, 4096, 4096, 3072);
    }
    // Mixing (composed, single launch): t = h2 @ [Wg;Wb;Ws]^T + [bg]  [8192,6144]
    {
        GemmArgs a{h2cat, wgcat, bg, t, nullptr};
        gemm_mma<0, false, true><<<dim3(6144 / 128, 8192 / 128, 1), blk, SMEM_BYTES>>>(
            a, a, a, 3072, 3072, 6144, 6144, 3072);
    }
    // combine -> split pp/qp
    combine<<<(8192L * 2048 / 4) / 256, 256>>>(uw, t, bias_p, bias_q, ppcat, qpcat);
    // G5/G6: final projections (one launch)
    {
        GemmArgs a0{ppcat, wpcat, b_p, p, nullptr};
        GemmArgs a1{qpcat, wqcat, b_q, q, nullptr};
        gemm_mma<0, false, true><<<dim3(2048 / 128, 8192 / 128, 2), blk, SMEM_BYTES>>>(
            a0, a1, a0, 6144, 6144, 2048, 2048, 6144);
    }
}

// round 12
// speedup vs baseline: 1.8966x; 1.2360x over previous
#include <cuda_runtime.h>
#include <cuda_bf16.h>
#include <cuda_fp16.h>
#include <cstdint>

// ============================================================================
// AutoEncoder_BNN via mma.sync. fp32 GEMMs emulated with K'=3K bf16 split:
//   A_cat = [A_hi | A_lo | A_hi],  B_cat = [B_hi | B_hi | B_lo]
// R5: Karatsuba mixing. R8: engine 128x128x64/256thr/3stage/2CTA-SM + z-batch.
// R9/R10: weight composition via associativity (mixing K 2048 -> 1024).
// R11: no trailing sync, float4 elementwise, single mixing launch.
// R12: final projections G5/G6 in PLAIN fp16 (K=2048, no split): last-stage
//      errors don't propagate; expected +~3e-4 on outputs p,q (budget 1e-3).
//      Saves 137.5 of 631.5 split-GMAC (-22%). Trunk/mixing stay 3-term bf16
//      (chain amplification ~10x; Im=t3-t1-t2 cancellation ~3x).
// ============================================================================

// ---------------- device scratch (static; no runtime allocation) ------------
__device__ __nv_bfloat16 g_xcat [8192L  * 12288];
__device__ __nv_bfloat16 g_whcat[1024L  * 12288];
__device__ __nv_bfloat16 g_h1cat[8192L  * 3072];
__device__ __nv_bfloat16 g_wh2cat[1024L * 3072];
__device__ __nv_bfloat16 g_h2cat[8192L  * 3072];
__device__ __nv_bfloat16 g_wycat[4096L  * 3072];   // W_y B-side (for G3)
__device__ __nv_bfloat16 g_gacat[2048L  * 6144];   // G    A-side
__device__ __nv_bfloat16 g_bacat[2048L  * 6144];   // Bm   A-side
__device__ __nv_bfloat16 g_gpacat[2048L * 6144];   // G+Bm A-side
__device__ __nv_bfloat16 g_wytcat[3L * 1024 * 6144]; // WyuT | WywT | (Wyu+Wyw)T
__device__ float         g_wg   [3L * 2048 * 1024];  // composed weights fp32
__device__ __nv_bfloat16 g_wgcat[3L * 2048 * 3072];  // composed weights B-side
__device__ float         g_bg   [3L * 2048];         // composed biases
__device__ float         g_t    [8192L * 6144];      // [t1|t2|t3] row-major
__device__ __half        g_pph  [8192L * 2048];      // pp plain fp16
__device__ __half        g_qph  [8192L * 2048];      // qp plain fp16
__device__ __half        g_wph  [2048L * 2048];      // W_p plain fp16
__device__ __half        g_wqh  [2048L * 2048];      // W_q plain fp16

// ---------------- PTX helpers ------------------------------------------------
__device__ __forceinline__ uint32_t smem_u32(const void* p) {
    uint32_t a;
    asm("{ .reg .u64 t; cvta.to.shared.u64 t, %1; cvt.u32.u64 %0, t; }" : "=r"(a) : "l"(p));
    return a;
}
__device__ __forceinline__ void cp_async16(uint32_t dst, const void* src) {
    asm volatile("cp.async.cg.shared.global [%0], [%1], 16;" :: "r"(dst), "l"(src) : "memory");
}
__device__ __forceinline__ void cp_commit() {
    asm volatile("cp.async.commit_group;" ::: "memory");
}
__device__ __forceinline__ void cp_wait1() {
    asm volatile("cp.async.wait_group 1;" ::: "memory");
}
__device__ __forceinline__ void ldsm4(uint32_t* r, uint32_t addr) {
    asm volatile("ldmatrix.sync.aligned.m8n8.x4.shared.b16 {%0,%1,%2,%3}, [%4];"
                 : "=r"(r[0]), "=r"(r[1]), "=r"(r[2]), "=r"(r[3]) : "r"(addr));
}
__device__ __forceinline__ void mma16816_bf(float* c, const uint32_t* a, uint32_t b0, uint32_t b1) {
    asm volatile(
        "mma.sync.aligned.m16n8k16.row.col.f32.bf16.bf16.f32 "
        "{%0,%1,%2,%3}, {%4,%5,%6,%7}, {%8,%9}, {%0,%1,%2,%3};"
        : "+f"(c[0]), "+f"(c[1]), "+f"(c[2]), "+f"(c[3])
        : "r"(a[0]), "r"(a[1]), "r"(a[2]), "r"(a[3]), "r"(b0), "r"(b1));
}
__device__ __forceinline__ void mma16816_fp(float* c, const uint32_t* a, uint32_t b0, uint32_t b1) {
    asm volatile(
        "mma.sync.aligned.m16n8k16.row.col.f32.f16.f16.f32 "
        "{%0,%1,%2,%3}, {%4,%5,%6,%7}, {%8,%9}, {%0,%1,%2,%3};"
        : "+f"(c[0]), "+f"(c[1]), "+f"(c[2]), "+f"(c[3])
        : "r"(a[0]), "r"(a[1]), "r"(a[2]), "r"(a[3]), "r"(b0), "r"(b1));
}
__device__ __forceinline__ void split2(float a, float b, __nv_bfloat162& h, __nv_bfloat162& l) {
    __nv_bfloat16 ha = __float2bfloat16(a);
    __nv_bfloat16 hb = __float2bfloat16(b);
    h.x = ha; h.y = hb;
    l.x = __float2bfloat16(a - __bfloat162float(ha));
    l.y = __float2bfloat16(b - __bfloat162float(hb));
}
__device__ __forceinline__ uint2 pack8(__nv_bfloat162 a, __nv_bfloat162 b) {
    uint2 r;
    r.x = *reinterpret_cast<uint32_t*>(&a);
    r.y = *reinterpret_cast<uint32_t*>(&b);
    return r;
}
__device__ __forceinline__ uint2 pack8h(__half2 a, __half2 b) {
    uint2 r;
    r.x = *reinterpret_cast<uint32_t*>(&a);
    r.y = *reinterpret_cast<uint32_t*>(&b);
    return r;
}

// ---------------- mma.sync GEMM, tile 128x128x64, 256 threads ----------------
// C[M,N] = act(A[M,K'] @ B[N,K']^T + bias); 16-bit K-major ops, fp32 accum.
// DT 0: bf16 operands.  DT 1: fp16 operands.
// MODE 0: fp32 C.  MODE 1: bf16 split (hi|lo|hi) to S, stride 3*Nfull.
struct GemmArgs {
    const void* A;
    const void* B;
    const float* bias;
    float* C;
    __nv_bfloat16* S;
};

constexpr int SMEM_BYTES = 3 * 32768;   // 3 stages x (A 16KB + B 16KB)

template <int MODE, bool RELU, bool BIAS, int DT>
__global__ __launch_bounds__(256, 2)
void gemm_mma(GemmArgs g0, GemmArgs g1, GemmArgs g2,
              int lda, int ldb, int ldc, int Nfull, int K)
{
    const GemmArgs& g = (blockIdx.z == 0) ? g0 : (blockIdx.z == 1) ? g1 : g2;
    extern __shared__ __align__(1024) char smem[];
    const uint32_t sb = smem_u32(smem);
    const int tid = threadIdx.x, lane = tid & 31, wid = tid >> 5;
    const int wm = wid & 1, wn = wid >> 1;            // warp grid 2(m) x 4(n)
    const int m0 = blockIdx.y * 128, n0 = blockIdx.x * 128;

    // ---- global->shared loader mapping (16B chunks, SW128 swizzle) ----
    const int lrow = tid >> 3;
    const int lc16 = tid & 7;
    uint32_t ld_off[4];
#pragma unroll
    for (int w2 = 0; w2 < 4; ++w2) {
        const int r = lrow + w2 * 32;
        ld_off[w2] = r * 128 + ((lc16 * 16) ^ ((r & 7) << 4));
    }
    const uint16_t* Ag = (const uint16_t*)g.A + (size_t)(m0 + lrow) * lda + lc16 * 8;
    const uint16_t* Bg = (const uint16_t*)g.B + (size_t)(n0 + lrow) * ldb + lc16 * 8;

    // ---- ldmatrix address precompute ----
    uint32_t aTerm[4], aXor[4];
#pragma unroll
    for (int mt = 0; mt < 4; ++mt) {
        const int r = wm * 64 + mt * 16 + ((lane >> 3) & 1) * 8 + (lane & 7);
        aTerm[mt] = r * 128; aXor[mt] = (r & 7) << 4;
    }
    const uint32_t aCol = (lane >> 4) * 16;
    uint32_t bTerm[2], bXor[2];
#pragma unroll
    for (int nt = 0; nt < 2; ++nt) {
        const int r = wn * 32 + nt * 16 + (lane >> 4) * 8 + (lane & 7);
        bTerm[nt] = r * 128; bXor[nt] = (r & 7) << 4;
    }
    const uint32_t bCol = ((lane >> 3) & 1) * 16;

    float acc[4][4][4];
#pragma unroll
    for (int mt = 0; mt < 4; ++mt)
#pragma unroll
        for (int n8 = 0; n8 < 4; ++n8)
#pragma unroll
            for (int j = 0; j < 4; ++j) acc[mt][n8][j] = 0.0f;

    const int nst = K / 64;

    auto issue = [&](int s, int kt) {
        const uint32_t sa = sb + (uint32_t)s * 32768u;
#pragma unroll
        for (int w2 = 0; w2 < 4; ++w2)
            cp_async16(sa + ld_off[w2], Ag + (size_t)w2 * 32 * lda + kt);
#pragma unroll
        for (int w2 = 0; w2 < 4; ++w2)
            cp_async16(sa + 16384u + ld_off[w2], Bg + (size_t)w2 * 32 * ldb + kt);
        cp_commit();
    };

    issue(0, 0);
    issue(1, 64);

    for (int i = 0; i < nst; ++i) {
        cp_wait1();
        __syncthreads();
        if (i + 2 < nst) issue((i + 2) % 3, (i + 2) * 64);
        else             cp_commit();

        const uint32_t sa = sb + (uint32_t)(i % 3) * 32768u;
        const uint32_t sB = sa + 16384u;
#pragma unroll
        for (int kk = 0; kk < 4; ++kk) {
            uint32_t a[4][4], b[2][4];
#pragma unroll
            for (int mt = 0; mt < 4; ++mt)
                ldsm4(a[mt], sa + aTerm[mt] + ((kk * 32 + aCol) ^ aXor[mt]));
#pragma unroll
            for (int nt = 0; nt < 2; ++nt)
                ldsm4(b[nt], sB + bTerm[nt] + ((kk * 32 + bCol) ^ bXor[nt]));
#pragma unroll
            for (int mt = 0; mt < 4; ++mt)
#pragma unroll
                for (int n8 = 0; n8 < 4; ++n8) {
                    if (DT == 0)
                        mma16816_bf(acc[mt][n8], a[mt],
                                    b[n8 >> 1][(n8 & 1) * 2], b[n8 >> 1][(n8 & 1) * 2 + 1]);
                    else
                        mma16816_fp(acc[mt][n8], a[mt],
                                    b[n8 >> 1][(n8 & 1) * 2], b[n8 >> 1][(n8 & 1) * 2 + 1]);
                }
        }
        // no trailing sync (next iteration's sync orders stage reuse)
    }

    // ---- epilogue ----
    float bb[4][2];
#pragma unroll
    for (int n8 = 0; n8 < 4; ++n8) {
        if (BIAS) {
            const int col = n0 + wn * 32 + n8 * 8 + (lane & 3) * 2;
            bb[n8][0] = __ldg(&g.bias[col]);
            bb[n8][1] = __ldg(&g.bias[col + 1]);
        } else { bb[n8][0] = 0.0f; bb[n8][1] = 0.0f; }
    }

#pragma unroll
    for (int mt = 0; mt < 4; ++mt) {
#pragma unroll
        for (int half = 0; half < 2; ++half) {
            const int r = m0 + wm * 64 + mt * 16 + (lane >> 2) + half * 8;
#pragma unroll
            for (int n8 = 0; n8 < 4; ++n8) {
                const int col = n0 + wn * 32 + n8 * 8 + (lane & 3) * 2;
                float v0 = acc[mt][n8][half * 2 + 0] + bb[n8][0];
                float v1 = acc[mt][n8][half * 2 + 1] + bb[n8][1];
                if (RELU) { v0 = fmaxf(v0, 0.0f); v1 = fmaxf(v1, 0.0f); }
                if (MODE == 0)
                    *reinterpret_cast<float2*>(g.C + (size_t)r * ldc + col) = make_float2(v0, v1);
                if (MODE == 1) {
                    __nv_bfloat162 h, l; split2(v0, v1, h, l);
                    __nv_bfloat16* Sr = g.S + (size_t)r * (3 * Nfull) + col;
                    *reinterpret_cast<__nv_bfloat162*>(Sr)             = h;
                    *reinterpret_cast<__nv_bfloat162*>(Sr + Nfull)     = l;
                    *reinterpret_cast<__nv_bfloat162*>(Sr + 2 * Nfull) = h;
                }
            }
        }
    }
}

// ------- pack: fp32 [R,C] -> bf16 split [R, 3C], 4 elems/thread --------------
template <bool B_SIDE>
__global__ __launch_bounds__(256)
void pack2(const float* __restrict__ src, __nv_bfloat16* __restrict__ dst,
           int logC, long total)
{
    const long i = ((long)blockIdx.x * 256 + threadIdx.x) * 4;
    if (i >= total) return;
    const int  C = 1 << logC;
    const long r = i >> logC;
    const int  c = (int)(i & (C - 1));
    const float4 v = *reinterpret_cast<const float4*>(src + i);
    __nv_bfloat162 h0, l0, h1, l1;
    split2(v.x, v.y, h0, l0);
    split2(v.z, v.w, h1, l1);
    const uint2 H = pack8(h0, h1), L = pack8(l0, l1);
    __nv_bfloat16* d = dst + r * (3L * C) + c;
    if (B_SIDE) {
        *reinterpret_cast<uint2*>(d)         = H;
        *reinterpret_cast<uint2*>(d + C)     = H;
        *reinterpret_cast<uint2*>(d + 2 * C) = L;
    } else {
        *reinterpret_cast<uint2*>(d)         = H;
        *reinterpret_cast<uint2*>(d + C)     = L;
        *reinterpret_cast<uint2*>(d + 2 * C) = H;
    }
}

// ------- packh: fp32 -> plain fp16, 4 elems/thread ---------------------------
__global__ __launch_bounds__(256)
void packh(const float* __restrict__ src, __half* __restrict__ dst, long total)
{
    const long i = ((long)blockIdx.x * 256 + threadIdx.x) * 4;
    if (i >= total) return;
    const float4 v = *reinterpret_cast<const float4*>(src + i);
    const __half2 a = __floats2half2_rn(v.x, v.y);
    const __half2 b = __floats2half2_rn(v.z, v.w);
    *reinterpret_cast<uint2*>(dst + i) = pack8h(a, b);
}

// ------- packadd2: (src0 + src1) -> split, 4 elems/thread --------------------
template <bool B_SIDE>
__global__ __launch_bounds__(256)
void packadd2(const float* __restrict__ s0, const float* __restrict__ s1,
              __nv_bfloat16* __restrict__ dst, int logC, long total)
{
    const long i = ((long)blockIdx.x * 256 + threadIdx.x) * 4;
    if (i >= total) return;
    const int  C = 1 << logC;
    const long r = i >> logC;
    const int  c = (int)(i & (C - 1));
    const float4 a = *reinterpret_cast<const float4*>(s0 + i);
    const float4 b = *reinterpret_cast<const float4*>(s1 + i);
    __nv_bfloat162 h0, l0, h1, l1;
    split2(a.x + b.x, a.y + b.y, h0, l0);
    split2(a.z + b.z, a.w + b.w, h1, l1);
    const uint2 H = pack8(h0, h1), L = pack8(l0, l1);
    __nv_bfloat16* d = dst + r * (3L * C) + c;
    if (B_SIDE) {
        *reinterpret_cast<uint2*>(d)         = H;
        *reinterpret_cast<uint2*>(d + C)     = H;
        *reinterpret_cast<uint2*>(d + 2 * C) = L;
    } else {
        *reinterpret_cast<uint2*>(d)         = H;
        *reinterpret_cast<uint2*>(d + C)     = L;
        *reinterpret_cast<uint2*>(d + 2 * C) = H;
    }
}

// ------- transpack: W_y halves -> transposed B-side split --------------------
__global__ __launch_bounds__(256)
void transpack(const float* __restrict__ Wy, __nv_bfloat16* __restrict__ dst)
{
    __shared__ float tile[32][33];
    const int z  = blockIdx.z;
    const int j0 = blockIdx.x * 32;
    const int k0 = blockIdx.y * 32;
    const int tx = threadIdx.x & 31, ty = threadIdx.x >> 5;

#pragma unroll
    for (int rr = ty; rr < 32; rr += 8) {
        const int k = k0 + rr, j = j0 + tx;
        float v;
        if (z == 0)      v = Wy[(size_t)k * 1024 + j];
        else if (z == 1) v = Wy[(size_t)(k + 2048) * 1024 + j];
        else             v = Wy[(size_t)k * 1024 + j] + Wy[(size_t)(k + 2048) * 1024 + j];
        tile[rr][tx] = v;
    }
    __syncthreads();
#pragma unroll
    for (int rr = ty; rr < 32; rr += 8) {
        const int j = j0 + rr;
        const float v = tile[tx][rr];
        const __nv_bfloat16 h = __float2bfloat16(v);
        const __nv_bfloat16 l = __float2bfloat16(v - __bfloat162float(h));
        __nv_bfloat16* d = dst + (size_t)z * 1024 * 6144 + (size_t)j * 6144 + k0 + tx;
        d[0] = h; d[2048] = h; d[4096] = l;
    }
}

// ------- biasdot: bg1=G@b_yu, bg2=Bm@b_yw, bg3=(G+Bm)@(b_yu+b_yw) -------------
__global__ __launch_bounds__(256)
void biasdot(const float* __restrict__ G, const float* __restrict__ Bm,
             const float* __restrict__ b_y, float* __restrict__ bg)
{
    const int c = blockIdx.x, tid = threadIdx.x, lane = tid & 31, w = tid >> 5;
    float s1 = 0, s2 = 0, s3 = 0;
    for (int k = tid; k < 2048; k += 256) {
        const float g = G[(size_t)c * 2048 + k], bm = Bm[(size_t)c * 2048 + k];
        const float byu = b_y[k], byw = b_y[2048 + k];
        s1 += g * byu; s2 += bm * byw; s3 += (g + bm) * (byu + byw);
    }
#pragma unroll
    for (int o = 16; o; o >>= 1) {
        s1 += __shfl_down_sync(0xFFFFFFFFu, s1, o);
        s2 += __shfl_down_sync(0xFFFFFFFFu, s2, o);
        s3 += __shfl_down_sync(0xFFFFFFFFu, s3, o);
    }
    __shared__ float sh[3][8];
    if (lane == 0) { sh[0][w] = s1; sh[1][w] = s2; sh[2][w] = s3; }
    __syncthreads();
    if (tid == 0) {
        float a = 0, b = 0, d = 0;
#pragma unroll
        for (int i = 0; i < 8; ++i) { a += sh[0][i]; b += sh[1][i]; d += sh[2][i]; }
        bg[c] = a; bg[2048 + c] = b; bg[4096 + c] = d;
    }
}

// ---------------- polar combine (Karatsuba) -> plain fp16 pp/qp --------------
// t layout: [8192, 6144] with t1 = cols [0,2048), t2 = [2048,4096), t3 = [4096,6144)
__global__ __launch_bounds__(256)
void combine(const float* __restrict__ uw, const float* __restrict__ t,
             const float* __restrict__ bias_p, const float* __restrict__ bias_q,
             __half* __restrict__ pph, __half* __restrict__ qph)
{
    const long i = ((long)blockIdx.x * 256 + threadIdx.x) * 4;   // [0, 8192*2048)
    const long r = i >> 11;
    const int  c = (int)(i & 2047);
    const float4 u4 = *reinterpret_cast<const float4*>(uw + r * 4096 + c);
    const float4 w4 = *reinterpret_cast<const float4*>(uw + r * 4096 + 2048 + c);
    const float4 t1 = *reinterpret_cast<const float4*>(t + r * 6144 + c);
    const float4 t2 = *reinterpret_cast<const float4*>(t + r * 6144 + 2048 + c);
    const float4 t3 = *reinterpret_cast<const float4*>(t + r * 6144 + 4096 + c);
    const float4 bp = *reinterpret_cast<const float4*>(bias_p + c);
    const float4 bq = *reinterpret_cast<const float4*>(bias_q + c);

    float pv[4], qv[4];
    const float uu[4] = {u4.x, u4.y, u4.z, u4.w};
    const float ww[4] = {w4.x, w4.y, w4.z, w4.w};
    const float a1[4] = {t1.x, t1.y, t1.z, t1.w};
    const float a2[4] = {t2.x, t2.y, t2.z, t2.w};
    const float a3[4] = {t3.x, t3.y, t3.z, t3.w};
    const float bpv[4] = {bp.x, bp.y, bp.z, bp.w};
    const float bqv[4] = {bq.x, bq.y, bq.z, bq.w};
#pragma unroll
    for (int j = 0; j < 4; ++j) {
        const float re = a1[j] - a2[j];
        const float im = a3[j] - a1[j] - a2[j];
        pv[j] = uu[j] * re + ww[j] * im + bpv[j];
        qv[j] = ww[j] * re - uu[j] * im + bqv[j];
    }
    *reinterpret_cast<uint2*>(pph + i) =
        pack8h(__floats2half2_rn(pv[0], pv[1]), __floats2half2_rn(pv[2], pv[3]));
    *reinterpret_cast<uint2*>(qph + i) =
        pack8h(__floats2half2_rn(qv[0], qv[1]), __floats2half2_rn(qv[2], qv[3]));
}

// ---------------- host side --------------------------------------------------
extern "C" void kernel_launch(void* const* d_in, const int* in_sizes, int n_in,
                              void* d_out, int out_size)
{
    const float* x      = (const float*)d_in[0];
    const float* W_h    = (const float*)d_in[1];
    const float* b_h    = (const float*)d_in[2];
    const float* W_h2   = (const float*)d_in[3];
    const float* b_h2   = (const float*)d_in[4];
    const float* W_y    = (const float*)d_in[5];
    const float* b_y    = (const float*)d_in[6];
    const float* G      = (const float*)d_in[7];
    const float* Bm     = (const float*)d_in[8];
    const float* bias_p = (const float*)d_in[9];
    const float* bias_q = (const float*)d_in[10];
    const float* W_p    = (const float*)d_in[11];
    const float* b_p    = (const float*)d_in[12];
    const float* W_q    = (const float*)d_in[13];
    const float* b_q    = (const float*)d_in[14];

    float* out = (float*)d_out;
    float* uw  = out;
    float* p   = out + (size_t)8192 * 4096;
    float* q   = p   + (size_t)8192 * 2048;

    __nv_bfloat16 *xcat, *whcat, *h1cat, *wh2cat, *h2cat, *wycat,
                  *gacat, *bacat, *gpacat, *wytcat, *wgcat;
    __half *pph, *qph, *wph, *wqh;
    float *t, *wg, *bg;
    cudaGetSymbolAddress((void**)&xcat,  g_xcat);
    cudaGetSymbolAddress((void**)&whcat, g_whcat);
    cudaGetSymbolAddress((void**)&h1cat, g_h1cat);
    cudaGetSymbolAddress((void**)&wh2cat,g_wh2cat);
    cudaGetSymbolAddress((void**)&h2cat, g_h2cat);
    cudaGetSymbolAddress((void**)&wycat, g_wycat);
    cudaGetSymbolAddress((void**)&gacat, g_gacat);
    cudaGetSymbolAddress((void**)&bacat, g_bacat);
    cudaGetSymbolAddress((void**)&gpacat,g_gpacat);
    cudaGetSymbolAddress((void**)&wytcat,g_wytcat);
    cudaGetSymbolAddress((void**)&wg,    g_wg);
    cudaGetSymbolAddress((void**)&wgcat, g_wgcat);
    cudaGetSymbolAddress((void**)&bg,    g_bg);
    cudaGetSymbolAddress((void**)&t,     g_t);
    cudaGetSymbolAddress((void**)&pph,   g_pph);
    cudaGetSymbolAddress((void**)&qph,   g_qph);
    cudaGetSymbolAddress((void**)&wph,   g_wph);
    cudaGetSymbolAddress((void**)&wqh,   g_wqh);

    cudaFuncSetAttribute(gemm_mma<1, true,  true,  0>, cudaFuncAttributeMaxDynamicSharedMemorySize, SMEM_BYTES);
    cudaFuncSetAttribute(gemm_mma<0, false, false, 0>, cudaFuncAttributeMaxDynamicSharedMemorySize, SMEM_BYTES);
    cudaFuncSetAttribute(gemm_mma<0, false, true,  0>, cudaFuncAttributeMaxDynamicSharedMemorySize, SMEM_BYTES);
    cudaFuncSetAttribute(gemm_mma<0, false, true,  1>, cudaFuncAttributeMaxDynamicSharedMemorySize, SMEM_BYTES);

    // ---- packs ----
    pack2<false><<<(8192L * 4096 / 4 + 255) / 256, 256>>>(x,    xcat,   12, 8192L * 4096);
    pack2<true ><<<(1024L * 4096 / 4 + 255) / 256, 256>>>(W_h,  whcat,  12, 1024L * 4096);
    pack2<true ><<<(1024L * 1024 / 4 + 255) / 256, 256>>>(W_h2, wh2cat, 10, 1024L * 1024);
    pack2<true ><<<(4096L * 1024 / 4 + 255) / 256, 256>>>(W_y,  wycat,  10, 4096L * 1024);
    pack2<false><<<(2048L * 2048 / 4 + 255) / 256, 256>>>(G,    gacat,  11, 2048L * 2048);
    pack2<false><<<(2048L * 2048 / 4 + 255) / 256, 256>>>(Bm,   bacat,  11, 2048L * 2048);
    packadd2<false><<<(2048L * 2048 / 4 + 255) / 256, 256>>>(G, Bm, gpacat, 11, 2048L * 2048);
    transpack<<<dim3(32, 64, 3), 256>>>(W_y, wytcat);
    biasdot<<<2048, 256>>>(G, Bm, b_y, bg);
    packh<<<(2048L * 2048 / 4 + 255) / 256, 256>>>(W_p, wph, 2048L * 2048);
    packh<<<(2048L * 2048 / 4 + 255) / 256, 256>>>(W_q, wqh, 2048L * 2048);

    const dim3 blk(256);
    // Weight composition: Wg = G@Wyu, Wb = Bm@Wyw, Ws = (G+Bm)@(Wyu+Wyw)
    {
        GemmArgs a0{gacat,  wytcat,                nullptr, wg,                 nullptr};
        GemmArgs a1{bacat,  wytcat + 1024L * 6144, nullptr, wg + 2048L * 1024,  nullptr};
        GemmArgs a2{gpacat, wytcat + 2048L * 6144, nullptr, wg + 2L * 2048 * 1024, nullptr};
        gemm_mma<0, false, false, 0><<<dim3(1024 / 128, 2048 / 128, 3), blk, SMEM_BYTES>>>(
            a0, a1, a2, 6144, 6144, 1024, 1024, 6144);
    }
    pack2<true ><<<(6144L * 1024 / 4 + 255) / 256, 256>>>(wg, wgcat, 10, 6144L * 1024);

    // G1: h1 = relu(x @ W_h^T + b_h) -> split h1cat
    {
        GemmArgs a{xcat, whcat, b_h, nullptr, h1cat};
        gemm_mma<1, true, true, 0><<<dim3(1024 / 128, 8192 / 128, 1), blk, SMEM_BYTES>>>(
            a, a, a, 12288, 12288, 0, 1024, 12288);
    }
    // G2: h2 = relu(h1 @ W_h2^T + b_h2) -> split h2cat
    {
        GemmArgs a{h1cat, wh2cat, b_h2, nullptr, h2cat};
        gemm_mma<1, true, true, 0><<<dim3(1024 / 128, 8192 / 128, 1), blk, SMEM_BYTES>>>(
            a, a, a, 3072, 3072, 0, 1024, 3072);
    }
    // G3: uw = h2 @ W_y^T + b_y -> fp32 uw (d_out)
    {
        GemmArgs a{h2cat, wycat, b_y, uw, nullptr};
        gemm_mma<0, false, true, 0><<<dim3(4096 / 128, 8192 / 128, 1), blk, SMEM_BYTES>>>(
            a, a, a, 3072, 3072, 4096, 4096, 3072);
    }
    // Mixing (composed, single launch): t = h2 @ [Wg;Wb;Ws]^T + [bg]  [8192,6144]
    {
        GemmArgs a{h2cat, wgcat, bg, t, nullptr};
        gemm_mma<0, false, true, 0><<<dim3(6144 / 128, 8192 / 128, 1), blk, SMEM_BYTES>>>(
            a, a, a, 3072, 3072, 6144, 6144, 3072);
    }
    // combine -> plain fp16 pp/qp
    combine<<<(8192L * 2048 / 4) / 256, 256>>>(uw, t, bias_p, bias_q, pph, qph);
    // G5/G6: final projections, PLAIN fp16, K=2048 (one launch)
    {
        GemmArgs a0{pph, wph, b_p, p, nullptr};
        GemmArgs a1{qph, wqh, b_q, q, nullptr};
        gemm_mma<0, false, true, 1><<<dim3(2048 / 128, 8192 / 128, 2), blk, SMEM_BYTES>>>(
            a0, a1, a0, 2048, 2048, 2048, 2048, 2048);
    }
}

// round 13
// speedup vs baseline: 2.2017x; 1.1609x over previous
#include <cuda_runtime.h>
#include <cuda_fp16.h>
#include <cstdint>

// ============================================================================
// AutoEncoder_BNN via mma.sync fp16, fp32 accumulate.
// fp32 GEMMs emulated with split operands (base type fp16, eps=4.9e-4):
//   3-term (K'=3K): A=[hi|lo|hi], B=[hi|hi|lo] -> residual lo*lo ~ eps^2 (negl.)
//   2-term (K'=2K): SAME buffers, first two segments: A=[hi|lo], B=[hi|hi]
//                   -> residual hi*lo ~ eps/sqrt(3)/2 ~ 1.5e-4 per GEMM
// R5 Karatsuba; R8 engine 128x128x64/256thr/3stage/2CTA-SM + z-batch;
// R9/R10 weight composition (mixing K 2048->1024); R11 micro-opts;
// R12 plain-fp16 final projections (calibrated: 3e-4/GEMM);
// R13 base type bf16->fp16 everywhere + 2-term trunk (G1/G2/G3 at K'=2K):
//     494 -> 416.5 GMAC. Mixing/composition stay 3-term (Im cancellation x3).
// ============================================================================

// ---------------- device scratch (static; no runtime allocation) ------------
__device__ __half g_xcat [8192L  * 12288];
__device__ __half g_whcat[1024L  * 12288];
__device__ __half g_h1cat[8192L  * 3072];
__device__ __half g_wh2cat[1024L * 3072];
__device__ __half g_h2cat[8192L  * 3072];
__device__ __half g_wycat[4096L  * 3072];     // W_y B-side (for G3)
__device__ __half g_gacat[2048L  * 6144];     // G    A-side
__device__ __half g_bacat[2048L  * 6144];     // Bm   A-side
__device__ __half g_gpacat[2048L * 6144];     // G+Bm A-side
__device__ __half g_wytcat[3L * 1024 * 6144]; // WyuT | WywT | (Wyu+Wyw)T
__device__ float  g_wg   [3L * 2048 * 1024];  // composed weights fp32
__device__ __half g_wgcat[3L * 2048 * 3072];  // composed weights B-side
__device__ float  g_bg   [3L * 2048];         // composed biases
__device__ float  g_t    [8192L * 6144];      // [t1|t2|t3] row-major
__device__ __half g_pph  [8192L * 2048];      // pp plain fp16
__device__ __half g_qph  [8192L * 2048];      // qp plain fp16
__device__ __half g_wph  [2048L * 2048];      // W_p plain fp16
__device__ __half g_wqh  [2048L * 2048];      // W_q plain fp16

// ---------------- PTX helpers ------------------------------------------------
__device__ __forceinline__ uint32_t smem_u32(const void* p) {
    uint32_t a;
    asm("{ .reg .u64 t; cvta.to.shared.u64 t, %1; cvt.u32.u64 %0, t; }" : "=r"(a) : "l"(p));
    return a;
}
__device__ __forceinline__ void cp_async16(uint32_t dst, const void* src) {
    asm volatile("cp.async.cg.shared.global [%0], [%1], 16;" :: "r"(dst), "l"(src) : "memory");
}
__device__ __forceinline__ void cp_commit() {
    asm volatile("cp.async.commit_group;" ::: "memory");
}
__device__ __forceinline__ void cp_wait1() {
    asm volatile("cp.async.wait_group 1;" ::: "memory");
}
__device__ __forceinline__ void ldsm4(uint32_t* r, uint32_t addr) {
    asm volatile("ldmatrix.sync.aligned.m8n8.x4.shared.b16 {%0,%1,%2,%3}, [%4];"
                 : "=r"(r[0]), "=r"(r[1]), "=r"(r[2]), "=r"(r[3]) : "r"(addr));
}
__device__ __forceinline__ void mma16816(float* c, const uint32_t* a, uint32_t b0, uint32_t b1) {
    asm volatile(
        "mma.sync.aligned.m16n8k16.row.col.f32.f16.f16.f32 "
        "{%0,%1,%2,%3}, {%4,%5,%6,%7}, {%8,%9}, {%0,%1,%2,%3};"
        : "+f"(c[0]), "+f"(c[1]), "+f"(c[2]), "+f"(c[3])
        : "r"(a[0]), "r"(a[1]), "r"(a[2]), "r"(a[3]), "r"(b0), "r"(b1));
}
__device__ __forceinline__ void split2h(float a, float b, __half2& h, __half2& l) {
    const __half ha = __float2half_rn(a);
    const __half hb = __float2half_rn(b);
    h = __halves2half2(ha, hb);
    l = __halves2half2(__float2half_rn(a - __half2float(ha)),
                       __float2half_rn(b - __half2float(hb)));
}
__device__ __forceinline__ uint2 pack8h(__half2 a, __half2 b) {
    uint2 r;
    r.x = *reinterpret_cast<uint32_t*>(&a);
    r.y = *reinterpret_cast<uint32_t*>(&b);
    return r;
}

// ---------------- mma.sync GEMM, tile 128x128x64, 256 threads ----------------
// C[M,N] = act(A[M,K'] @ B[N,K']^T + bias); fp16 K-major operands, fp32 accum.
// MODE 0: fp32 C.  MODE 1: fp16 split (hi|lo|hi) to S, stride 3*Nfull.
struct GemmArgs {
    const __half* A;
    const __half* B;
    const float* bias;
    float* C;
    __half* S;
};

constexpr int SMEM_BYTES = 3 * 32768;   // 3 stages x (A 16KB + B 16KB)

template <int MODE, bool RELU, bool BIAS>
__global__ __launch_bounds__(256, 2)
void gemm_mma(GemmArgs g0, GemmArgs g1, GemmArgs g2,
              int lda, int ldb, int ldc, int Nfull, int K)
{
    const GemmArgs& g = (blockIdx.z == 0) ? g0 : (blockIdx.z == 1) ? g1 : g2;
    extern __shared__ __align__(1024) char smem[];
    const uint32_t sb = smem_u32(smem);
    const int tid = threadIdx.x, lane = tid & 31, wid = tid >> 5;
    const int wm = wid & 1, wn = wid >> 1;            // warp grid 2(m) x 4(n)
    const int m0 = blockIdx.y * 128, n0 = blockIdx.x * 128;

    // ---- global->shared loader mapping (16B chunks, SW128 swizzle) ----
    const int lrow = tid >> 3;
    const int lc16 = tid & 7;
    uint32_t ld_off[4];
#pragma unroll
    for (int w2 = 0; w2 < 4; ++w2) {
        const int r = lrow + w2 * 32;
        ld_off[w2] = r * 128 + ((lc16 * 16) ^ ((r & 7) << 4));
    }
    const __half* Ag = g.A + (size_t)(m0 + lrow) * lda + lc16 * 8;
    const __half* Bg = g.B + (size_t)(n0 + lrow) * ldb + lc16 * 8;

    // ---- ldmatrix address precompute ----
    uint32_t aTerm[4], aXor[4];
#pragma unroll
    for (int mt = 0; mt < 4; ++mt) {
        const int r = wm * 64 + mt * 16 + ((lane >> 3) & 1) * 8 + (lane & 7);
        aTerm[mt] = r * 128; aXor[mt] = (r & 7) << 4;
    }
    const uint32_t aCol = (lane >> 4) * 16;
    uint32_t bTerm[2], bXor[2];
#pragma unroll
    for (int nt = 0; nt < 2; ++nt) {
        const int r = wn * 32 + nt * 16 + (lane >> 4) * 8 + (lane & 7);
        bTerm[nt] = r * 128; bXor[nt] = (r & 7) << 4;
    }
    const uint32_t bCol = ((lane >> 3) & 1) * 16;

    float acc[4][4][4];
#pragma unroll
    for (int mt = 0; mt < 4; ++mt)
#pragma unroll
        for (int n8 = 0; n8 < 4; ++n8)
#pragma unroll
            for (int j = 0; j < 4; ++j) acc[mt][n8][j] = 0.0f;

    const int nst = K / 64;

    auto issue = [&](int s, int kt) {
        const uint32_t sa = sb + (uint32_t)s * 32768u;
#pragma unroll
        for (int w2 = 0; w2 < 4; ++w2)
            cp_async16(sa + ld_off[w2], Ag + (size_t)w2 * 32 * lda + kt);
#pragma unroll
        for (int w2 = 0; w2 < 4; ++w2)
            cp_async16(sa + 16384u + ld_off[w2], Bg + (size_t)w2 * 32 * ldb + kt);
        cp_commit();
    };

    issue(0, 0);
    issue(1, 64);

    for (int i = 0; i < nst; ++i) {
        cp_wait1();
        __syncthreads();
        if (i + 2 < nst) issue((i + 2) % 3, (i + 2) * 64);
        else             cp_commit();

        const uint32_t sa = sb + (uint32_t)(i % 3) * 32768u;
        const uint32_t sB = sa + 16384u;
#pragma unroll
        for (int kk = 0; kk < 4; ++kk) {
            uint32_t a[4][4], b[2][4];
#pragma unroll
            for (int mt = 0; mt < 4; ++mt)
                ldsm4(a[mt], sa + aTerm[mt] + ((kk * 32 + aCol) ^ aXor[mt]));
#pragma unroll
            for (int nt = 0; nt < 2; ++nt)
                ldsm4(b[nt], sB + bTerm[nt] + ((kk * 32 + bCol) ^ bXor[nt]));
#pragma unroll
            for (int mt = 0; mt < 4; ++mt)
#pragma unroll
                for (int n8 = 0; n8 < 4; ++n8)
                    mma16816(acc[mt][n8], a[mt],
                             b[n8 >> 1][(n8 & 1) * 2], b[n8 >> 1][(n8 & 1) * 2 + 1]);
        }
        // no trailing sync (next iteration's sync orders stage reuse)
    }

    // ---- epilogue ----
    float bb[4][2];
#pragma unroll
    for (int n8 = 0; n8 < 4; ++n8) {
        if (BIAS) {
            const int col = n0 + wn * 32 + n8 * 8 + (lane & 3) * 2;
            bb[n8][0] = __ldg(&g.bias[col]);
            bb[n8][1] = __ldg(&g.bias[col + 1]);
        } else { bb[n8][0] = 0.0f; bb[n8][1] = 0.0f; }
    }

#pragma unroll
    for (int mt = 0; mt < 4; ++mt) {
#pragma unroll
        for (int half = 0; half < 2; ++half) {
            const int r = m0 + wm * 64 + mt * 16 + (lane >> 2) + half * 8;
#pragma unroll
            for (int n8 = 0; n8 < 4; ++n8) {
                const int col = n0 + wn * 32 + n8 * 8 + (lane & 3) * 2;
                float v0 = acc[mt][n8][half * 2 + 0] + bb[n8][0];
                float v1 = acc[mt][n8][half * 2 + 1] + bb[n8][1];
                if (RELU) { v0 = fmaxf(v0, 0.0f); v1 = fmaxf(v1, 0.0f); }
                if (MODE == 0)
                    *reinterpret_cast<float2*>(g.C + (size_t)r * ldc + col) = make_float2(v0, v1);
                if (MODE == 1) {
                    __half2 h, l; split2h(v0, v1, h, l);
                    __half* Sr = g.S + (size_t)r * (3 * Nfull) + col;
                    *reinterpret_cast<__half2*>(Sr)             = h;
                    *reinterpret_cast<__half2*>(Sr + Nfull)     = l;
                    *reinterpret_cast<__half2*>(Sr + 2 * Nfull) = h;
                }
            }
        }
    }
}

// ------- pack: fp32 [R,C] -> fp16 split [R, 3C], 4 elems/thread --------------
// B_SIDE=false (A operand): [hi | lo | hi].  B_SIDE=true (weights): [hi | hi | lo].
template <bool B_SIDE>
__global__ __launch_bounds__(256)
void pack2(const float* __restrict__ src, __half* __restrict__ dst,
           int logC, long total)
{
    const long i = ((long)blockIdx.x * 256 + threadIdx.x) * 4;
    if (i >= total) return;
    const int  C = 1 << logC;
    const long r = i >> logC;
    const int  c = (int)(i & (C - 1));
    const float4 v = *reinterpret_cast<const float4*>(src + i);
    __half2 h0, l0, h1, l1;
    split2h(v.x, v.y, h0, l0);
    split2h(v.z, v.w, h1, l1);
    const uint2 H = pack8h(h0, h1), L = pack8h(l0, l1);
    __half* d = dst + r * (3L * C) + c;
    if (B_SIDE) {
        *reinterpret_cast<uint2*>(d)         = H;
        *reinterpret_cast<uint2*>(d + C)     = H;
        *reinterpret_cast<uint2*>(d + 2 * C) = L;
    } else {
        *reinterpret_cast<uint2*>(d)         = H;
        *reinterpret_cast<uint2*>(d + C)     = L;
        *reinterpret_cast<uint2*>(d + 2 * C) = H;
    }
}

// ------- packh: fp32 -> plain fp16, 4 elems/thread ---------------------------
__global__ __launch_bounds__(256)
void packh(const float* __restrict__ src, __half* __restrict__ dst, long total)
{
    const long i = ((long)blockIdx.x * 256 + threadIdx.x) * 4;
    if (i >= total) return;
    const float4 v = *reinterpret_cast<const float4*>(src + i);
    *reinterpret_cast<uint2*>(dst + i) =
        pack8h(__floats2half2_rn(v.x, v.y), __floats2half2_rn(v.z, v.w));
}

// ------- packadd2: (src0 + src1) -> A-side split, 4 elems/thread -------------
template <bool B_SIDE>
__global__ __launch_bounds__(256)
void packadd2(const float* __restrict__ s0, const float* __restrict__ s1,
              __half* __restrict__ dst, int logC, long total)
{
    const long i = ((long)blockIdx.x * 256 + threadIdx.x) * 4;
    if (i >= total) return;
    const int  C = 1 << logC;
    const long r = i >> logC;
    const int  c = (int)(i & (C - 1));
    const float4 a = *reinterpret_cast<const float4*>(s0 + i);
    const float4 b = *reinterpret_cast<const float4*>(s1 + i);
    __half2 h0, l0, h1, l1;
    split2h(a.x + b.x, a.y + b.y, h0, l0);
    split2h(a.z + b.z, a.w + b.w, h1, l1);
    const uint2 H = pack8h(h0, h1), L = pack8h(l0, l1);
    __half* d = dst + r * (3L * C) + c;
    if (B_SIDE) {
        *reinterpret_cast<uint2*>(d)         = H;
        *reinterpret_cast<uint2*>(d + C)     = H;
        *reinterpret_cast<uint2*>(d + 2 * C) = L;
    } else {
        *reinterpret_cast<uint2*>(d)         = H;
        *reinterpret_cast<uint2*>(d + C)     = L;
        *reinterpret_cast<uint2*>(d + 2 * C) = H;
    }
}

// ------- transpack: W_y halves -> transposed B-side split --------------------
// z=0: Wyu^T, z=1: Wyw^T, z=2: (Wyu+Wyw)^T.  Output [1024 rows, 3*2048] each.
__global__ __launch_bounds__(256)
void transpack(const float* __restrict__ Wy, __half* __restrict__ dst)
{
    __shared__ float tile[32][33];
    const int z  = blockIdx.z;
    const int j0 = blockIdx.x * 32;
    const int k0 = blockIdx.y * 32;
    const int tx = threadIdx.x & 31, ty = threadIdx.x >> 5;

#pragma unroll
    for (int rr = ty; rr < 32; rr += 8) {
        const int k = k0 + rr, j = j0 + tx;
        float v;
        if (z == 0)      v = Wy[(size_t)k * 1024 + j];
        else if (z == 1) v = Wy[(size_t)(k + 2048) * 1024 + j];
        else             v = Wy[(size_t)k * 1024 + j] + Wy[(size_t)(k + 2048) * 1024 + j];
        tile[rr][tx] = v;
    }
    __syncthreads();
#pragma unroll
    for (int rr = ty; rr < 32; rr += 8) {
        const int j = j0 + rr;
        const float v = tile[tx][rr];
        const __half h = __float2half_rn(v);
        const __half l = __float2half_rn(v - __half2float(h));
        __half* d = dst + (size_t)z * 1024 * 6144 + (size_t)j * 6144 + k0 + tx;
        d[0] = h; d[2048] = h; d[4096] = l;
    }
}

// ------- biasdot: bg1=G@b_yu, bg2=Bm@b_yw, bg3=(G+Bm)@(b_yu+b_yw) -------------
__global__ __launch_bounds__(256)
void biasdot(const float* __restrict__ G, const float* __restrict__ Bm,
             const float* __restrict__ b_y, float* __restrict__ bg)
{
    const int c = blockIdx.x, tid = threadIdx.x, lane = tid & 31, w = tid >> 5;
    float s1 = 0, s2 = 0, s3 = 0;
    for (int k = tid; k < 2048; k += 256) {
        const float g = G[(size_t)c * 2048 + k], bm = Bm[(size_t)c * 2048 + k];
        const float byu = b_y[k], byw = b_y[2048 + k];
        s1 += g * byu; s2 += bm * byw; s3 += (g + bm) * (byu + byw);
    }
#pragma unroll
    for (int o = 16; o; o >>= 1) {
        s1 += __shfl_down_sync(0xFFFFFFFFu, s1, o);
        s2 += __shfl_down_sync(0xFFFFFFFFu, s2, o);
        s3 += __shfl_down_sync(0xFFFFFFFFu, s3, o);
    }
    __shared__ float sh[3][8];
    if (lane == 0) { sh[0][w] = s1; sh[1][w] = s2; sh[2][w] = s3; }
    __syncthreads();
    if (tid == 0) {
        float a = 0, b = 0, d = 0;
#pragma unroll
        for (int i = 0; i < 8; ++i) { a += sh[0][i]; b += sh[1][i]; d += sh[2][i]; }
        bg[c] = a; bg[2048 + c] = b; bg[4096 + c] = d;
    }
}

// ---------------- polar combine (Karatsuba) -> plain fp16 pp/qp --------------
__global__ __launch_bounds__(256)
void combine(const float* __restrict__ uw, const float* __restrict__ t,
             const float* __restrict__ bias_p, const float* __restrict__ bias_q,
             __half* __restrict__ pph, __half* __restrict__ qph)
{
    const long i = ((long)blockIdx.x * 256 + threadIdx.x) * 4;   // [0, 8192*2048)
    const long r = i >> 11;
    const int  c = (int)(i & 2047);
    const float4 u4 = *reinterpret_cast<const float4*>(uw + r * 4096 + c);
    const float4 w4 = *reinterpret_cast<const float4*>(uw + r * 4096 + 2048 + c);
    const float4 t1 = *reinterpret_cast<const float4*>(t + r * 6144 + c);
    const float4 t2 = *reinterpret_cast<const float4*>(t + r * 6144 + 2048 + c);
    const float4 t3 = *reinterpret_cast<const float4*>(t + r * 6144 + 4096 + c);
    const float4 bp = *reinterpret_cast<const float4*>(bias_p + c);
    const float4 bq = *reinterpret_cast<const float4*>(bias_q + c);

    float pv[4], qv[4];
    const float uu[4] = {u4.x, u4.y, u4.z, u4.w};
    const float ww[4] = {w4.x, w4.y, w4.z, w4.w};
    const float a1[4] = {t1.x, t1.y, t1.z, t1.w};
    const float a2[4] = {t2.x, t2.y, t2.z, t2.w};
    const float a3[4] = {t3.x, t3.y, t3.z, t3.w};
    const float bpv[4] = {bp.x, bp.y, bp.z, bp.w};
    const float bqv[4] = {bq.x, bq.y, bq.z, bq.w};
#pragma unroll
    for (int j = 0; j < 4; ++j) {
        const float re = a1[j] - a2[j];
        const float im = a3[j] - a1[j] - a2[j];
        pv[j] = uu[j] * re + ww[j] * im + bpv[j];
        qv[j] = ww[j] * re - uu[j] * im + bqv[j];
    }
    *reinterpret_cast<uint2*>(pph + i) =
        pack8h(__floats2half2_rn(pv[0], pv[1]), __floats2half2_rn(pv[2], pv[3]));
    *reinterpret_cast<uint2*>(qph + i) =
        pack8h(__floats2half2_rn(qv[0], qv[1]), __floats2half2_rn(qv[2], qv[3]));
}

// ---------------- host side --------------------------------------------------
extern "C" void kernel_launch(void* const* d_in, const int* in_sizes, int n_in,
                              void* d_out, int out_size)
{
    const float* x      = (const float*)d_in[0];
    const float* W_h    = (const float*)d_in[1];
    const float* b_h    = (const float*)d_in[2];
    const float* W_h2   = (const float*)d_in[3];
    const float* b_h2   = (const float*)d_in[4];
    const float* W_y    = (const float*)d_in[5];
    const float* b_y    = (const float*)d_in[6];
    const float* G      = (const float*)d_in[7];
    const float* Bm     = (const float*)d_in[8];
    const float* bias_p = (const float*)d_in[9];
    const float* bias_q = (const float*)d_in[10];
    const float* W_p    = (const float*)d_in[11];
    const float* b_p    = (const float*)d_in[12];
    const float* W_q    = (const float*)d_in[13];
    const float* b_q    = (const float*)d_in[14];

    float* out = (float*)d_out;
    float* uw  = out;
    float* p   = out + (size_t)8192 * 4096;
    float* q   = p   + (size_t)8192 * 2048;

    __half *xcat, *whcat, *h1cat, *wh2cat, *h2cat, *wycat,
           *gacat, *bacat, *gpacat, *wytcat, *wgcat,
           *pph, *qph, *wph, *wqh;
    float *t, *wg, *bg;
    cudaGetSymbolAddress((void**)&xcat,  g_xcat);
    cudaGetSymbolAddress((void**)&whcat, g_whcat);
    cudaGetSymbolAddress((void**)&h1cat, g_h1cat);
    cudaGetSymbolAddress((void**)&wh2cat,g_wh2cat);
    cudaGetSymbolAddress((void**)&h2cat, g_h2cat);
    cudaGetSymbolAddress((void**)&wycat, g_wycat);
    cudaGetSymbolAddress((void**)&gacat, g_gacat);
    cudaGetSymbolAddress((void**)&bacat, g_bacat);
    cudaGetSymbolAddress((void**)&gpacat,g_gpacat);
    cudaGetSymbolAddress((void**)&wytcat,g_wytcat);
    cudaGetSymbolAddress((void**)&wg,    g_wg);
    cudaGetSymbolAddress((void**)&wgcat, g_wgcat);
    cudaGetSymbolAddress((void**)&bg,    g_bg);
    cudaGetSymbolAddress((void**)&t,     g_t);
    cudaGetSymbolAddress((void**)&pph,   g_pph);
    cudaGetSymbolAddress((void**)&qph,   g_qph);
    cudaGetSymbolAddress((void**)&wph,   g_wph);
    cudaGetSymbolAddress((void**)&wqh,   g_wqh);

    cudaFuncSetAttribute(gemm_mma<1, true,  true >, cudaFuncAttributeMaxDynamicSharedMemorySize, SMEM_BYTES);
    cudaFuncSetAttribute(gemm_mma<0, false, false>, cudaFuncAttributeMaxDynamicSharedMemorySize, SMEM_BYTES);
    cudaFuncSetAttribute(gemm_mma<0, false, true >, cudaFuncAttributeMaxDynamicSharedMemorySize, SMEM_BYTES);

    // ---- packs ----
    pack2<false><<<(8192L * 4096 / 4 + 255) / 256, 256>>>(x,    xcat,   12, 8192L * 4096);
    pack2<true ><<<(1024L * 4096 / 4 + 255) / 256, 256>>>(W_h,  whcat,  12, 1024L * 4096);
    pack2<true ><<<(1024L * 1024 / 4 + 255) / 256, 256>>>(W_h2, wh2cat, 10, 1024L * 1024);
    pack2<true ><<<(4096L * 1024 / 4 + 255) / 256, 256>>>(W_y,  wycat,  10, 4096L * 1024);
    pack2<false><<<(2048L * 2048 / 4 + 255) / 256, 256>>>(G,    gacat,  11, 2048L * 2048);
    pack2<false><<<(2048L * 2048 / 4 + 255) / 256, 256>>>(Bm,   bacat,  11, 2048L * 2048);
    packadd2<false><<<(2048L * 2048 / 4 + 255) / 256, 256>>>(G, Bm, gpacat, 11, 2048L * 2048);
    transpack<<<dim3(32, 64, 3), 256>>>(W_y, wytcat);
    biasdot<<<2048, 256>>>(G, Bm, b_y, bg);
    packh<<<(2048L * 2048 / 4 + 255) / 256, 256>>>(W_p, wph, 2048L * 2048);
    packh<<<(2048L * 2048 / 4 + 255) / 256, 256>>>(W_q, wqh, 2048L * 2048);

    const dim3 blk(256);
    // Weight composition (3-term, K'=6144): Wg=G@Wyu, Wb=Bm@Wyw, Ws=(G+Bm)@(Wyu+Wyw)
    {
        GemmArgs a0{gacat,  wytcat,                nullptr, wg,                 nullptr};
        GemmArgs a1{bacat,  wytcat + 1024L * 6144, nullptr, wg + 2048L * 1024,  nullptr};
        GemmArgs a2{gpacat, wytcat + 2048L * 6144, nullptr, wg + 2L * 2048 * 1024, nullptr};
        gemm_mma<0, false, false><<<dim3(1024 / 128, 2048 / 128, 3), blk, SMEM_BYTES>>>(
            a0, a1, a2, 6144, 6144, 1024, 1024, 6144);
    }
    pack2<true ><<<(6144L * 1024 / 4 + 255) / 256, 256>>>(wg, wgcat, 10, 6144L * 1024);

    // G1: h1 = relu(x @ W_h^T + b_h) -> split h1cat.  2-TERM: K'=2*4096=8192.
    {
        GemmArgs a{xcat, whcat, b_h, nullptr, h1cat};
        gemm_mma<1, true, true><<<dim3(1024 / 128, 8192 / 128, 1), blk, SMEM_BYTES>>>(
            a, a, a, 12288, 12288, 0, 1024, 8192);
    }
    // G2: h2 = relu(h1 @ W_h2^T + b_h2) -> split h2cat.  2-TERM: K'=2048.
    {
        GemmArgs a{h1cat, wh2cat, b_h2, nullptr, h2cat};
        gemm_mma<1, true, true><<<dim3(1024 / 128, 8192 / 128, 1), blk, SMEM_BYTES>>>(
            a, a, a, 3072, 3072, 0, 1024, 2048);
    }
    // G3: uw = h2 @ W_y^T + b_y -> fp32 uw (d_out).  2-TERM: K'=2048.
    {
        GemmArgs a{h2cat, wycat, b_y, uw, nullptr};
        gemm_mma<0, false, true><<<dim3(4096 / 128, 8192 / 128, 1), blk, SMEM_BYTES>>>(
            a, a, a, 3072, 3072, 4096, 4096, 2048);
    }
    // Mixing (composed, 3-term K'=3072): t = h2 @ [Wg;Wb;Ws]^T + bg  [8192,6144]
    {
        GemmArgs a{h2cat, wgcat, bg, t, nullptr};
        gemm_mma<0, false, true><<<dim3(6144 / 128, 8192 / 128, 1), blk, SMEM_BYTES>>>(
            a, a, a, 3072, 3072, 6144, 6144, 3072);
    }
    // combine -> plain fp16 pp/qp
    combine<<<(8192L * 2048 / 4) / 256, 256>>>(uw, t, bias_p, bias_q, pph, qph);
    // G5/G6: final projections, plain fp16, K=2048 (one launch)
    {
        GemmArgs a0{pph, wph, b_p, p, nullptr};
        GemmArgs a1{qph, wqh, b_q, q, nullptr};
        gemm_mma<0, false, true><<<dim3(2048 / 128, 8192 / 128, 2), blk, SMEM_BYTES>>>(
            a0, a1, a0, 2048, 2048, 2048, 2048, 2048);
    }
}

// round 14
// speedup vs baseline: 2.4730x; 1.1232x over previous
#include <cuda_runtime.h>
#include <cuda_fp16.h>
#include <cstdint>

// ============================================================================
// AutoEncoder_BNN via mma.sync fp16, fp32 accumulate.
// fp32 GEMMs emulated with split operands (fp16 base, eps=4.9e-4):
//   3-term (K'=3K): A=[hi|lo|hi], B=[hi|hi|lo] -> residual ~eps^2 (negligible)
//   2-term (K'=2K): same buffers, segs [hi|lo]x[hi|hi] -> residual ~1.4e-4/GEMM
// R5 Karatsuba; R8 engine 128x128x64/256thr/3stage/2CTA-SM + z-batch;
// R9/R10 weight composition; R11 micro-opts; R12 plain-fp16 finals;
// R13 fp16 splits + 2-term trunk;
// R14 2-term MIXING (K'=2048): Im=t3-t1-t2 cancellation is only sqrt(2) (t3 =
//     Gu+Bu+Gw+Bw, Im = Bu+Gw), so +~2e-4 -> ~5.5e-4 total. 416.5 -> 365 GMAC.
//     Also: unread third split segments are no longer written (SEGS=2 packs,
//     2-segment MODE-1 epilogue). Compositions stay 3-term.
// ============================================================================

// ---------------- device scratch (static; no runtime allocation) ------------
__device__ __half g_xcat [8192L  * 12288];
__device__ __half g_whcat[1024L  * 12288];
__device__ __half g_h1cat[8192L  * 3072];
__device__ __half g_wh2cat[1024L * 3072];
__device__ __half g_h2cat[8192L  * 3072];
__device__ __half g_wycat[4096L  * 3072];     // W_y B-side (for G3)
__device__ __half g_gacat[2048L  * 6144];     // G    A-side (3-term)
__device__ __half g_bacat[2048L  * 6144];     // Bm   A-side (3-term)
__device__ __half g_gpacat[2048L * 6144];     // G+Bm A-side (3-term)
__device__ __half g_wytcat[3L * 1024 * 6144]; // WyuT | WywT | (Wyu+Wyw)T (3-term)
__device__ float  g_wg   [3L * 2048 * 1024];  // composed weights fp32
__device__ __half g_wgcat[3L * 2048 * 3072];  // composed weights B-side
__device__ float  g_bg   [3L * 2048];         // composed biases
__device__ float  g_t    [8192L * 6144];      // [t1|t2|t3] row-major
__device__ __half g_pph  [8192L * 2048];      // pp plain fp16
__device__ __half g_qph  [8192L * 2048];      // qp plain fp16
__device__ __half g_wph  [2048L * 2048];      // W_p plain fp16
__device__ __half g_wqh  [2048L * 2048];      // W_q plain fp16

// ---------------- PTX helpers ------------------------------------------------
__device__ __forceinline__ uint32_t smem_u32(const void* p) {
    uint32_t a;
    asm("{ .reg .u64 t; cvta.to.shared.u64 t, %1; cvt.u32.u64 %0, t; }" : "=r"(a) : "l"(p));
    return a;
}
__device__ __forceinline__ void cp_async16(uint32_t dst, const void* src) {
    asm volatile("cp.async.cg.shared.global [%0], [%1], 16;" :: "r"(dst), "l"(src) : "memory");
}
__device__ __forceinline__ void cp_commit() {
    asm volatile("cp.async.commit_group;" ::: "memory");
}
__device__ __forceinline__ void cp_wait1() {
    asm volatile("cp.async.wait_group 1;" ::: "memory");
}
__device__ __forceinline__ void ldsm4(uint32_t* r, uint32_t addr) {
    asm volatile("ldmatrix.sync.aligned.m8n8.x4.shared.b16 {%0,%1,%2,%3}, [%4];"
                 : "=r"(r[0]), "=r"(r[1]), "=r"(r[2]), "=r"(r[3]) : "r"(addr));
}
__device__ __forceinline__ void mma16816(float* c, const uint32_t* a, uint32_t b0, uint32_t b1) {
    asm volatile(
        "mma.sync.aligned.m16n8k16.row.col.f32.f16.f16.f32 "
        "{%0,%1,%2,%3}, {%4,%5,%6,%7}, {%8,%9}, {%0,%1,%2,%3};"
        : "+f"(c[0]), "+f"(c[1]), "+f"(c[2]), "+f"(c[3])
        : "r"(a[0]), "r"(a[1]), "r"(a[2]), "r"(a[3]), "r"(b0), "r"(b1));
}
__device__ __forceinline__ void split2h(float a, float b, __half2& h, __half2& l) {
    const __half ha = __float2half_rn(a);
    const __half hb = __float2half_rn(b);
    h = __halves2half2(ha, hb);
    l = __halves2half2(__float2half_rn(a - __half2float(ha)),
                       __float2half_rn(b - __half2float(hb)));
}
__device__ __forceinline__ uint2 pack8h(__half2 a, __half2 b) {
    uint2 r;
    r.x = *reinterpret_cast<uint32_t*>(&a);
    r.y = *reinterpret_cast<uint32_t*>(&b);
    return r;
}

// ---------------- mma.sync GEMM, tile 128x128x64, 256 threads ----------------
// C[M,N] = act(A[M,K'] @ B[N,K']^T + bias); fp16 K-major operands, fp32 accum.
// MODE 0: fp32 C.  MODE 1: fp16 2-seg split [hi|lo] to S, row stride 3*Nfull.
struct GemmArgs {
    const __half* A;
    const __half* B;
    const float* bias;
    float* C;
    __half* S;
};

constexpr int SMEM_BYTES = 3 * 32768;   // 3 stages x (A 16KB + B 16KB)

template <int MODE, bool RELU, bool BIAS>
__global__ __launch_bounds__(256, 2)
void gemm_mma(GemmArgs g0, GemmArgs g1, GemmArgs g2,
              int lda, int ldb, int ldc, int Nfull, int K)
{
    const GemmArgs& g = (blockIdx.z == 0) ? g0 : (blockIdx.z == 1) ? g1 : g2;
    extern __shared__ __align__(1024) char smem[];
    const uint32_t sb = smem_u32(smem);
    const int tid = threadIdx.x, lane = tid & 31, wid = tid >> 5;
    const int wm = wid & 1, wn = wid >> 1;            // warp grid 2(m) x 4(n)
    const int m0 = blockIdx.y * 128, n0 = blockIdx.x * 128;

    // ---- global->shared loader mapping (16B chunks, SW128 swizzle) ----
    const int lrow = tid >> 3;
    const int lc16 = tid & 7;
    uint32_t ld_off[4];
#pragma unroll
    for (int w2 = 0; w2 < 4; ++w2) {
        const int r = lrow + w2 * 32;
        ld_off[w2] = r * 128 + ((lc16 * 16) ^ ((r & 7) << 4));
    }
    const __half* Ag = g.A + (size_t)(m0 + lrow) * lda + lc16 * 8;
    const __half* Bg = g.B + (size_t)(n0 + lrow) * ldb + lc16 * 8;

    // ---- ldmatrix address precompute ----
    uint32_t aTerm[4], aXor[4];
#pragma unroll
    for (int mt = 0; mt < 4; ++mt) {
        const int r = wm * 64 + mt * 16 + ((lane >> 3) & 1) * 8 + (lane & 7);
        aTerm[mt] = r * 128; aXor[mt] = (r & 7) << 4;
    }
    const uint32_t aCol = (lane >> 4) * 16;
    uint32_t bTerm[2], bXor[2];
#pragma unroll
    for (int nt = 0; nt < 2; ++nt) {
        const int r = wn * 32 + nt * 16 + (lane >> 4) * 8 + (lane & 7);
        bTerm[nt] = r * 128; bXor[nt] = (r & 7) << 4;
    }
    const uint32_t bCol = ((lane >> 3) & 1) * 16;

    float acc[4][4][4];
#pragma unroll
    for (int mt = 0; mt < 4; ++mt)
#pragma unroll
        for (int n8 = 0; n8 < 4; ++n8)
#pragma unroll
            for (int j = 0; j < 4; ++j) acc[mt][n8][j] = 0.0f;

    const int nst = K / 64;

    auto issue = [&](int s, int kt) {
        const uint32_t sa = sb + (uint32_t)s * 32768u;
#pragma unroll
        for (int w2 = 0; w2 < 4; ++w2)
            cp_async16(sa + ld_off[w2], Ag + (size_t)w2 * 32 * lda + kt);
#pragma unroll
        for (int w2 = 0; w2 < 4; ++w2)
            cp_async16(sa + 16384u + ld_off[w2], Bg + (size_t)w2 * 32 * ldb + kt);
        cp_commit();
    };

    issue(0, 0);
    issue(1, 64);

    for (int i = 0; i < nst; ++i) {
        cp_wait1();
        __syncthreads();
        if (i + 2 < nst) issue((i + 2) % 3, (i + 2) * 64);
        else             cp_commit();

        const uint32_t sa = sb + (uint32_t)(i % 3) * 32768u;
        const uint32_t sB = sa + 16384u;
#pragma unroll
        for (int kk = 0; kk < 4; ++kk) {
            uint32_t a[4][4], b[2][4];
#pragma unroll
            for (int mt = 0; mt < 4; ++mt)
                ldsm4(a[mt], sa + aTerm[mt] + ((kk * 32 + aCol) ^ aXor[mt]));
#pragma unroll
            for (int nt = 0; nt < 2; ++nt)
                ldsm4(b[nt], sB + bTerm[nt] + ((kk * 32 + bCol) ^ bXor[nt]));
#pragma unroll
            for (int mt = 0; mt < 4; ++mt)
#pragma unroll
                for (int n8 = 0; n8 < 4; ++n8)
                    mma16816(acc[mt][n8], a[mt],
                             b[n8 >> 1][(n8 & 1) * 2], b[n8 >> 1][(n8 & 1) * 2 + 1]);
        }
        // no trailing sync (next iteration's sync orders stage reuse)
    }

    // ---- epilogue ----
    float bb[4][2];
#pragma unroll
    for (int n8 = 0; n8 < 4; ++n8) {
        if (BIAS) {
            const int col = n0 + wn * 32 + n8 * 8 + (lane & 3) * 2;
            bb[n8][0] = __ldg(&g.bias[col]);
            bb[n8][1] = __ldg(&g.bias[col + 1]);
        } else { bb[n8][0] = 0.0f; bb[n8][1] = 0.0f; }
    }

#pragma unroll
    for (int mt = 0; mt < 4; ++mt) {
#pragma unroll
        for (int half = 0; half < 2; ++half) {
            const int r = m0 + wm * 64 + mt * 16 + (lane >> 2) + half * 8;
#pragma unroll
            for (int n8 = 0; n8 < 4; ++n8) {
                const int col = n0 + wn * 32 + n8 * 8 + (lane & 3) * 2;
                float v0 = acc[mt][n8][half * 2 + 0] + bb[n8][0];
                float v1 = acc[mt][n8][half * 2 + 1] + bb[n8][1];
                if (RELU) { v0 = fmaxf(v0, 0.0f); v1 = fmaxf(v1, 0.0f); }
                if (MODE == 0)
                    *reinterpret_cast<float2*>(g.C + (size_t)r * ldc + col) = make_float2(v0, v1);
                if (MODE == 1) {   // 2-segment split: consumers are all 2-term
                    __half2 h, l; split2h(v0, v1, h, l);
                    __half* Sr = g.S + (size_t)r * (3 * Nfull) + col;
                    *reinterpret_cast<__half2*>(Sr)         = h;
                    *reinterpret_cast<__half2*>(Sr + Nfull) = l;
                }
            }
        }
    }
}

// ------- pack: fp32 [R,C] -> fp16 split [R, 3C stride], 4 elems/thread -------
// B_SIDE=false: [hi | lo | hi].  B_SIDE=true: [hi | hi | lo].
// SEGS=2 skips the third segment store (consumer is 2-term).
template <bool B_SIDE, int SEGS>
__global__ __launch_bounds__(256)
void pack2(const float* __restrict__ src, __half* __restrict__ dst,
           int logC, long total)
{
    const long i = ((long)blockIdx.x * 256 + threadIdx.x) * 4;
    if (i >= total) return;
    const int  C = 1 << logC;
    const long r = i >> logC;
    const int  c = (int)(i & (C - 1));
    const float4 v = *reinterpret_cast<const float4*>(src + i);
    __half2 h0, l0, h1, l1;
    split2h(v.x, v.y, h0, l0);
    split2h(v.z, v.w, h1, l1);
    const uint2 H = pack8h(h0, h1), L = pack8h(l0, l1);
    __half* d = dst + r * (3L * C) + c;
    if (B_SIDE) {
        *reinterpret_cast<uint2*>(d)     = H;
        *reinterpret_cast<uint2*>(d + C) = H;
        if (SEGS == 3) *reinterpret_cast<uint2*>(d + 2 * C) = L;
    } else {
        *reinterpret_cast<uint2*>(d)     = H;
        *reinterpret_cast<uint2*>(d + C) = L;
        if (SEGS == 3) *reinterpret_cast<uint2*>(d + 2 * C) = H;
    }
}

// ------- packh: fp32 -> plain fp16, 4 elems/thread ---------------------------
__global__ __launch_bounds__(256)
void packh(const float* __restrict__ src, __half* __restrict__ dst, long total)
{
    const long i = ((long)blockIdx.x * 256 + threadIdx.x) * 4;
    if (i >= total) return;
    const float4 v = *reinterpret_cast<const float4*>(src + i);
    *reinterpret_cast<uint2*>(dst + i) =
        pack8h(__floats2half2_rn(v.x, v.y), __floats2half2_rn(v.z, v.w));
}

// ------- packadd2: (src0 + src1) -> A-side 3-term split, 4 elems/thread ------
__global__ __launch_bounds__(256)
void packadd2(const float* __restrict__ s0, const float* __restrict__ s1,
              __half* __restrict__ dst, int logC, long total)
{
    const long i = ((long)blockIdx.x * 256 + threadIdx.x) * 4;
    if (i >= total) return;
    const int  C = 1 << logC;
    const long r = i >> logC;
    const int  c = (int)(i & (C - 1));
    const float4 a = *reinterpret_cast<const float4*>(s0 + i);
    const float4 b = *reinterpret_cast<const float4*>(s1 + i);
    __half2 h0, l0, h1, l1;
    split2h(a.x + b.x, a.y + b.y, h0, l0);
    split2h(a.z + b.z, a.w + b.w, h1, l1);
    const uint2 H = pack8h(h0, h1), L = pack8h(l0, l1);
    __half* d = dst + r * (3L * C) + c;
    *reinterpret_cast<uint2*>(d)         = H;
    *reinterpret_cast<uint2*>(d + C)     = L;
    *reinterpret_cast<uint2*>(d + 2 * C) = H;
}

// ------- transpack: W_y halves -> transposed B-side 3-term split --------------
// z=0: Wyu^T, z=1: Wyw^T, z=2: (Wyu+Wyw)^T.  Output [1024 rows, 3*2048] each.
__global__ __launch_bounds__(256)
void transpack(const float* __restrict__ Wy, __half* __restrict__ dst)
{
    __shared__ float tile[32][33];
    const int z  = blockIdx.z;
    const int j0 = blockIdx.x * 32;
    const int k0 = blockIdx.y * 32;
    const int tx = threadIdx.x & 31, ty = threadIdx.x >> 5;

#pragma unroll
    for (int rr = ty; rr < 32; rr += 8) {
        const int k = k0 + rr, j = j0 + tx;
        float v;
        if (z == 0)      v = Wy[(size_t)k * 1024 + j];
        else if (z == 1) v = Wy[(size_t)(k + 2048) * 1024 + j];
        else             v = Wy[(size_t)k * 1024 + j] + Wy[(size_t)(k + 2048) * 1024 + j];
        tile[rr][tx] = v;
    }
    __syncthreads();
#pragma unroll
    for (int rr = ty; rr < 32; rr += 8) {
        const int j = j0 + rr;
        const float v = tile[tx][rr];
        const __half h = __float2half_rn(v);
        const __half l = __float2half_rn(v - __half2float(h));
        __half* d = dst + (size_t)z * 1024 * 6144 + (size_t)j * 6144 + k0 + tx;
        d[0] = h; d[2048] = h; d[4096] = l;
    }
}

// ------- biasdot: bg1=G@b_yu, bg2=Bm@b_yw, bg3=(G+Bm)@(b_yu+b_yw) -------------
__global__ __launch_bounds__(256)
void biasdot(const float* __restrict__ G, const float* __restrict__ Bm,
             const float* __restrict__ b_y, float* __restrict__ bg)
{
    const int c = blockIdx.x, tid = threadIdx.x, lane = tid & 31, w = tid >> 5;
    float s1 = 0, s2 = 0, s3 = 0;
    for (int k = tid; k < 2048; k += 256) {
        const float g = G[(size_t)c * 2048 + k], bm = Bm[(size_t)c * 2048 + k];
        const float byu = b_y[k], byw = b_y[2048 + k];
        s1 += g * byu; s2 += bm * byw; s3 += (g + bm) * (byu + byw);
    }
#pragma unroll
    for (int o = 16; o; o >>= 1) {
        s1 += __shfl_down_sync(0xFFFFFFFFu, s1, o);
        s2 += __shfl_down_sync(0xFFFFFFFFu, s2, o);
        s3 += __shfl_down_sync(0xFFFFFFFFu, s3, o);
    }
    __shared__ float sh[3][8];
    if (lane == 0) { sh[0][w] = s1; sh[1][w] = s2; sh[2][w] = s3; }
    __syncthreads();
    if (tid == 0) {
        float a = 0, b = 0, d = 0;
#pragma unroll
        for (int i = 0; i < 8; ++i) { a += sh[0][i]; b += sh[1][i]; d += sh[2][i]; }
        bg[c] = a; bg[2048 + c] = b; bg[4096 + c] = d;
    }
}

// ---------------- polar combine (Karatsuba) -> plain fp16 pp/qp --------------
__global__ __launch_bounds__(256)
void combine(const float* __restrict__ uw, const float* __restrict__ t,
             const float* __restrict__ bias_p, const float* __restrict__ bias_q,
             __half* __restrict__ pph, __half* __restrict__ qph)
{
    const long i = ((long)blockIdx.x * 256 + threadIdx.x) * 4;   // [0, 8192*2048)
    const long r = i >> 11;
    const int  c = (int)(i & 2047);
    const float4 u4 = *reinterpret_cast<const float4*>(uw + r * 4096 + c);
    const float4 w4 = *reinterpret_cast<const float4*>(uw + r * 4096 + 2048 + c);
    const float4 t1 = *reinterpret_cast<const float4*>(t + r * 6144 + c);
    const float4 t2 = *reinterpret_cast<const float4*>(t + r * 6144 + 2048 + c);
    const float4 t3 = *reinterpret_cast<const float4*>(t + r * 6144 + 4096 + c);
    const float4 bp = *reinterpret_cast<const float4*>(bias_p + c);
    const float4 bq = *reinterpret_cast<const float4*>(bias_q + c);

    float pv[4], qv[4];
    const float uu[4] = {u4.x, u4.y, u4.z, u4.w};
    const float ww[4] = {w4.x, w4.y, w4.z, w4.w};
    const float a1[4] = {t1.x, t1.y, t1.z, t1.w};
    const float a2[4] = {t2.x, t2.y, t2.z, t2.w};
    const float a3[4] = {t3.x, t3.y, t3.z, t3.w};
    const float bpv[4] = {bp.x, bp.y, bp.z, bp.w};
    const float bqv[4] = {bq.x, bq.y, bq.z, bq.w};
#pragma unroll
    for (int j = 0; j < 4; ++j) {
        const float re = a1[j] - a2[j];
        const float im = a3[j] - a1[j] - a2[j];
        pv[j] = uu[j] * re + ww[j] * im + bpv[j];
        qv[j] = ww[j] * re - uu[j] * im + bqv[j];
    }
    *reinterpret_cast<uint2*>(pph + i) =
        pack8h(__floats2half2_rn(pv[0], pv[1]), __floats2half2_rn(pv[2], pv[3]));
    *reinterpret_cast<uint2*>(qph + i) =
        pack8h(__floats2half2_rn(qv[0], qv[1]), __floats2half2_rn(qv[2], qv[3]));
}

// ---------------- host side --------------------------------------------------
extern "C" void kernel_launch(void* const* d_in, const int* in_sizes, int n_in,
                              void* d_out, int out_size)
{
    const float* x      = (const float*)d_in[0];
    const float* W_h    = (const float*)d_in[1];
    const float* b_h    = (const float*)d_in[2];
    const float* W_h2   = (const float*)d_in[3];
    const float* b_h2   = (const float*)d_in[4];
    const float* W_y    = (const float*)d_in[5];
    const float* b_y    = (const float*)d_in[6];
    const float* G      = (const float*)d_in[7];
    const float* Bm     = (const float*)d_in[8];
    const float* bias_p = (const float*)d_in[9];
    const float* bias_q = (const float*)d_in[10];
    const float* W_p    = (const float*)d_in[11];
    const float* b_p    = (const float*)d_in[12];
    const float* W_q    = (const float*)d_in[13];
    const float* b_q    = (const float*)d_in[14];

    float* out = (float*)d_out;
    float* uw  = out;
    float* p   = out + (size_t)8192 * 4096;
    float* q   = p   + (size_t)8192 * 2048;

    __half *xcat, *whcat, *h1cat, *wh2cat, *h2cat, *wycat,
           *gacat, *bacat, *gpacat, *wytcat, *wgcat,
           *pph, *qph, *wph, *wqh;
    float *t, *wg, *bg;
    cudaGetSymbolAddress((void**)&xcat,  g_xcat);
    cudaGetSymbolAddress((void**)&whcat, g_whcat);
    cudaGetSymbolAddress((void**)&h1cat, g_h1cat);
    cudaGetSymbolAddress((void**)&wh2cat,g_wh2cat);
    cudaGetSymbolAddress((void**)&h2cat, g_h2cat);
    cudaGetSymbolAddress((void**)&wycat, g_wycat);
    cudaGetSymbolAddress((void**)&gacat, g_gacat);
    cudaGetSymbolAddress((void**)&bacat, g_bacat);
    cudaGetSymbolAddress((void**)&gpacat,g_gpacat);
    cudaGetSymbolAddress((void**)&wytcat,g_wytcat);
    cudaGetSymbolAddress((void**)&wg,    g_wg);
    cudaGetSymbolAddress((void**)&wgcat, g_wgcat);
    cudaGetSymbolAddress((void**)&bg,    g_bg);
    cudaGetSymbolAddress((void**)&t,     g_t);
    cudaGetSymbolAddress((void**)&pph,   g_pph);
    cudaGetSymbolAddress((void**)&qph,   g_qph);
    cudaGetSymbolAddress((void**)&wph,   g_wph);
    cudaGetSymbolAddress((void**)&wqh,   g_wqh);

    cudaFuncSetAttribute(gemm_mma<1, true,  true >, cudaFuncAttributeMaxDynamicSharedMemorySize, SMEM_BYTES);
    cudaFuncSetAttribute(gemm_mma<0, false, false>, cudaFuncAttributeMaxDynamicSharedMemorySize, SMEM_BYTES);
    cudaFuncSetAttribute(gemm_mma<0, false, true >, cudaFuncAttributeMaxDynamicSharedMemorySize, SMEM_BYTES);

    // ---- packs (SEGS=2 where the consumer GEMM is 2-term) ----
    pack2<false, 2><<<(8192L * 4096 / 4 + 255) / 256, 256>>>(x,    xcat,   12, 8192L * 4096);
    pack2<true,  2><<<(1024L * 4096 / 4 + 255) / 256, 256>>>(W_h,  whcat,  12, 1024L * 4096);
    pack2<true,  2><<<(1024L * 1024 / 4 + 255) / 256, 256>>>(W_h2, wh2cat, 10, 1024L * 1024);
    pack2<true,  2><<<(4096L * 1024 / 4 + 255) / 256, 256>>>(W_y,  wycat,  10, 4096L * 1024);
    pack2<false, 3><<<(2048L * 2048 / 4 + 255) / 256, 256>>>(G,    gacat,  11, 2048L * 2048);
    pack2<false, 3><<<(2048L * 2048 / 4 + 255) / 256, 256>>>(Bm,   bacat,  11, 2048L * 2048);
    packadd2<<<(2048L * 2048 / 4 + 255) / 256, 256>>>(G, Bm, gpacat, 11, 2048L * 2048);
    transpack<<<dim3(32, 64, 3), 256>>>(W_y, wytcat);
    biasdot<<<2048, 256>>>(G, Bm, b_y, bg);
    packh<<<(2048L * 2048 / 4 + 255) / 256, 256>>>(W_p, wph, 2048L * 2048);
    packh<<<(2048L * 2048 / 4 + 255) / 256, 256>>>(W_q, wqh, 2048L * 2048);

    const dim3 blk(256);
    // Weight composition (3-term, K'=6144): Wg=G@Wyu, Wb=Bm@Wyw, Ws=(G+Bm)@(Wyu+Wyw)
    {
        GemmArgs a0{gacat,  wytcat,                nullptr, wg,                 nullptr};
        GemmArgs a1{bacat,  wytcat + 1024L * 6144, nullptr, wg + 2048L * 1024,  nullptr};
        GemmArgs a2{gpacat, wytcat + 2048L * 6144, nullptr, wg + 2L * 2048 * 1024, nullptr};
        gemm_mma<0, false, false><<<dim3(1024 / 128, 2048 / 128, 3), blk, SMEM_BYTES>>>(
            a0, a1, a2, 6144, 6144, 1024, 1024, 6144);
    }
    // pack composed weights -> B-side, 2 segments (mixing is 2-term)
    pack2<true, 2><<<(6144L * 1024 / 4 + 255) / 256, 256>>>(wg, wgcat, 10, 6144L * 1024);

    // G1: h1 = relu(x @ W_h^T + b_h) -> 2-seg split h1cat.  2-TERM: K'=8192.
    {
        GemmArgs a{xcat, whcat, b_h, nullptr, h1cat};
        gemm_mma<1, true, true><<<dim3(1024 / 128, 8192 / 128, 1), blk, SMEM_BYTES>>>(
            a, a, a, 12288, 12288, 0, 1024, 8192);
    }
    // G2: h2 = relu(h1 @ W_h2^T + b_h2) -> 2-seg split h2cat.  2-TERM: K'=2048.
    {
        GemmArgs a{h1cat, wh2cat, b_h2, nullptr, h2cat};
        gemm_mma<1, true, true><<<dim3(1024 / 128, 8192 / 128, 1), blk, SMEM_BYTES>>>(
            a, a, a, 3072, 3072, 0, 1024, 2048);
    }
    // G3: uw = h2 @ W_y^T + b_y -> fp32 uw (d_out).  2-TERM: K'=2048.
    {
        GemmArgs a{h2cat, wycat, b_y, uw, nullptr};
        gemm_mma<0, false, true><<<dim3(4096 / 128, 8192 / 128, 1), blk, SMEM_BYTES>>>(
            a, a, a, 3072, 3072, 4096, 4096, 2048);
    }
    // Mixing (composed, 2-TERM K'=2048): t = h2 @ [Wg;Wb;Ws]^T + bg  [8192,6144]
    {
        GemmArgs a{h2cat, wgcat, bg, t, nullptr};
        gemm_mma<0, false, true><<<dim3(6144 / 128, 8192 / 128, 1), blk, SMEM_BYTES>>>(
            a, a, a, 3072, 3072, 6144, 6144, 2048);
    }
    // combine -> plain fp16 pp/qp
    combine<<<(8192L * 2048 / 4) / 256, 256>>>(uw, t, bias_p, bias_q, pph, qph);
    // G5/G6: final projections, plain fp16, K=2048 (one launch)
    {
        GemmArgs a0{pph, wph, b_p, p, nullptr};
        GemmArgs a1{qph, wqh, b_q, q, nullptr};
        gemm_mma<0, false, true><<<dim3(2048 / 128, 8192 / 128, 2), blk, SMEM_BYTES>>>(
            a0, a1, a0, 2048, 2048, 2048, 2048, 2048);
    }
}

// round 15
// speedup vs baseline: 2.7464x; 1.1105x over previous
#include <cuda_runtime.h>
#include <cuda_fp16.h>
#include <cstdint>

// ============================================================================
// AutoEncoder_BNN via mma.sync fp16, fp32 accumulate.
// fp32 GEMMs emulated with fp16 split operands:
//   3-term (K'=3K): A=[hi|lo|hi], B=[hi|hi|lo] -> residual ~eps^2 (negligible)
//   2-term (K'=2K): segs [hi|lo] x [hi|hi]     -> residual ~1.4e-4 per GEMM
// R5..R14: Karatsuba; 128x128x64 engine (2 CTA/SM, z-batch); weight
// composition; micro-opts; plain-fp16 finals; fp16 2-term trunk & mixing.
// R15: Karatsuba moved to WEIGHT level. Wre = m1-m2, Wim = m3-m1-m2 formed in
//      fp32 from the 3-term compositions (m1=G@Wyu, m2=Bm@Wyw,
//      m3=(G+Bm)@(Wyu+Wyw)); mixing becomes t' = h2@[Wre;Wim]^T (N=4096, not
//      6144): 365 -> 330.7 GMAC. No runtime cancellation (error flat/better).
//      G3 + mixing fused into one z=2 launch (same A, K'). t buffer 192->128MB.
// ============================================================================

// ---------------- device scratch (static; no runtime allocation) ------------
__device__ __half g_xcat [8192L  * 12288];
__device__ __half g_whcat[1024L  * 12288];
__device__ __half g_h1cat[8192L  * 3072];
__device__ __half g_wh2cat[1024L * 3072];
__device__ __half g_h2cat[8192L  * 3072];
__device__ __half g_wycat[4096L  * 3072];     // W_y B-side (G3, 2-seg)
__device__ __half g_gacat[2048L  * 6144];     // G    A-side (3-term)
__device__ __half g_bacat[2048L  * 6144];     // Bm   A-side (3-term)
__device__ __half g_gpacat[2048L * 6144];     // G+Bm A-side (3-term)
__device__ __half g_wytcat[3L * 1024 * 6144]; // WyuT | WywT | (Wyu+Wyw)T (3-term)
__device__ float  g_wg   [3L * 2048 * 1024];  // m1 | m2 | m3 (fp32, stacked rows)
__device__ __half g_wreim[4096L * 3072];      // [Wre;Wim] B-side 2-seg
__device__ float  g_bg   [3L * 2048];         // bg1 | bg2 | bg3
__device__ float  g_breim[4096];              // [bre | bim]
__device__ float  g_t    [8192L * 4096];      // [Re | Im] row-major
__device__ __half g_pph  [8192L * 2048];      // pp plain fp16
__device__ __half g_qph  [8192L * 2048];      // qp plain fp16
__device__ __half g_wph  [2048L * 2048];      // W_p plain fp16
__device__ __half g_wqh  [2048L * 2048];      // W_q plain fp16

// ---------------- PTX helpers ------------------------------------------------
__device__ __forceinline__ uint32_t smem_u32(const void* p) {
    uint32_t a;
    asm("{ .reg .u64 t; cvta.to.shared.u64 t, %1; cvt.u32.u64 %0, t; }" : "=r"(a) : "l"(p));
    return a;
}
__device__ __forceinline__ void cp_async16(uint32_t dst, const void* src) {
    asm volatile("cp.async.cg.shared.global [%0], [%1], 16;" :: "r"(dst), "l"(src) : "memory");
}
__device__ __forceinline__ void cp_commit() {
    asm volatile("cp.async.commit_group;" ::: "memory");
}
__device__ __forceinline__ void cp_wait1() {
    asm volatile("cp.async.wait_group 1;" ::: "memory");
}
__device__ __forceinline__ void ldsm4(uint32_t* r, uint32_t addr) {
    asm volatile("ldmatrix.sync.aligned.m8n8.x4.shared.b16 {%0,%1,%2,%3}, [%4];"
                 : "=r"(r[0]), "=r"(r[1]), "=r"(r[2]), "=r"(r[3]) : "r"(addr));
}
__device__ __forceinline__ void mma16816(float* c, const uint32_t* a, uint32_t b0, uint32_t b1) {
    asm volatile(
        "mma.sync.aligned.m16n8k16.row.col.f32.f16.f16.f32 "
        "{%0,%1,%2,%3}, {%4,%5,%6,%7}, {%8,%9}, {%0,%1,%2,%3};"
        : "+f"(c[0]), "+f"(c[1]), "+f"(c[2]), "+f"(c[3])
        : "r"(a[0]), "r"(a[1]), "r"(a[2]), "r"(a[3]), "r"(b0), "r"(b1));
}
__device__ __forceinline__ void split2h(float a, float b, __half2& h, __half2& l) {
    const __half ha = __float2half_rn(a);
    const __half hb = __float2half_rn(b);
    h = __halves2half2(ha, hb);
    l = __halves2half2(__float2half_rn(a - __half2float(ha)),
                       __float2half_rn(b - __half2float(hb)));
}
__device__ __forceinline__ uint2 pack8h(__half2 a, __half2 b) {
    uint2 r;
    r.x = *reinterpret_cast<uint32_t*>(&a);
    r.y = *reinterpret_cast<uint32_t*>(&b);
    return r;
}

// ---------------- mma.sync GEMM, tile 128x128x64, 256 threads ----------------
// C[M,N] = act(A[M,K'] @ B[N,K']^T + bias); fp16 K-major operands, fp32 accum.
// MODE 0: fp32 C.  MODE 1: fp16 2-seg split [hi|lo] to S, row stride 3*Nfull.
struct GemmArgs {
    const __half* A;
    const __half* B;
    const float* bias;
    float* C;
    __half* S;
};

constexpr int SMEM_BYTES = 3 * 32768;   // 3 stages x (A 16KB + B 16KB)

template <int MODE, bool RELU, bool BIAS>
__global__ __launch_bounds__(256, 2)
void gemm_mma(GemmArgs g0, GemmArgs g1, GemmArgs g2,
              int lda, int ldb, int ldc, int Nfull, int K)
{
    const GemmArgs& g = (blockIdx.z == 0) ? g0 : (blockIdx.z == 1) ? g1 : g2;
    extern __shared__ __align__(1024) char smem[];
    const uint32_t sb = smem_u32(smem);
    const int tid = threadIdx.x, lane = tid & 31, wid = tid >> 5;
    const int wm = wid & 1, wn = wid >> 1;            // warp grid 2(m) x 4(n)
    const int m0 = blockIdx.y * 128, n0 = blockIdx.x * 128;

    // ---- global->shared loader mapping (16B chunks, SW128 swizzle) ----
    const int lrow = tid >> 3;
    const int lc16 = tid & 7;
    uint32_t ld_off[4];
#pragma unroll
    for (int w2 = 0; w2 < 4; ++w2) {
        const int r = lrow + w2 * 32;
        ld_off[w2] = r * 128 + ((lc16 * 16) ^ ((r & 7) << 4));
    }
    const __half* Ag = g.A + (size_t)(m0 + lrow) * lda + lc16 * 8;
    const __half* Bg = g.B + (size_t)(n0 + lrow) * ldb + lc16 * 8;

    // ---- ldmatrix address precompute ----
    uint32_t aTerm[4], aXor[4];
#pragma unroll
    for (int mt = 0; mt < 4; ++mt) {
        const int r = wm * 64 + mt * 16 + ((lane >> 3) & 1) * 8 + (lane & 7);
        aTerm[mt] = r * 128; aXor[mt] = (r & 7) << 4;
    }
    const uint32_t aCol = (lane >> 4) * 16;
    uint32_t bTerm[2], bXor[2];
#pragma unroll
    for (int nt = 0; nt < 2; ++nt) {
        const int r = wn * 32 + nt * 16 + (lane >> 4) * 8 + (lane & 7);
        bTerm[nt] = r * 128; bXor[nt] = (r & 7) << 4;
    }
    const uint32_t bCol = ((lane >> 3) & 1) * 16;

    float acc[4][4][4];
#pragma unroll
    for (int mt = 0; mt < 4; ++mt)
#pragma unroll
        for (int n8 = 0; n8 < 4; ++n8)
#pragma unroll
            for (int j = 0; j < 4; ++j) acc[mt][n8][j] = 0.0f;

    const int nst = K / 64;

    auto issue = [&](int s, int kt) {
        const uint32_t sa = sb + (uint32_t)s * 32768u;
#pragma unroll
        for (int w2 = 0; w2 < 4; ++w2)
            cp_async16(sa + ld_off[w2], Ag + (size_t)w2 * 32 * lda + kt);
#pragma unroll
        for (int w2 = 0; w2 < 4; ++w2)
            cp_async16(sa + 16384u + ld_off[w2], Bg + (size_t)w2 * 32 * ldb + kt);
        cp_commit();
    };

    issue(0, 0);
    issue(1, 64);

    for (int i = 0; i < nst; ++i) {
        cp_wait1();
        __syncthreads();
        if (i + 2 < nst) issue((i + 2) % 3, (i + 2) * 64);
        else             cp_commit();

        const uint32_t sa = sb + (uint32_t)(i % 3) * 32768u;
        const uint32_t sB = sa + 16384u;
#pragma unroll
        for (int kk = 0; kk < 4; ++kk) {
            uint32_t a[4][4], b[2][4];
#pragma unroll
            for (int mt = 0; mt < 4; ++mt)
                ldsm4(a[mt], sa + aTerm[mt] + ((kk * 32 + aCol) ^ aXor[mt]));
#pragma unroll
            for (int nt = 0; nt < 2; ++nt)
                ldsm4(b[nt], sB + bTerm[nt] + ((kk * 32 + bCol) ^ bXor[nt]));
#pragma unroll
            for (int mt = 0; mt < 4; ++mt)
#pragma unroll
                for (int n8 = 0; n8 < 4; ++n8)
                    mma16816(acc[mt][n8], a[mt],
                             b[n8 >> 1][(n8 & 1) * 2], b[n8 >> 1][(n8 & 1) * 2 + 1]);
        }
        // no trailing sync (next iteration's sync orders stage reuse)
    }

    // ---- epilogue ----
    float bb[4][2];
#pragma unroll
    for (int n8 = 0; n8 < 4; ++n8) {
        if (BIAS) {
            const int col = n0 + wn * 32 + n8 * 8 + (lane & 3) * 2;
            bb[n8][0] = __ldg(&g.bias[col]);
            bb[n8][1] = __ldg(&g.bias[col + 1]);
        } else { bb[n8][0] = 0.0f; bb[n8][1] = 0.0f; }
    }

#pragma unroll
    for (int mt = 0; mt < 4; ++mt) {
#pragma unroll
        for (int half = 0; half < 2; ++half) {
            const int r = m0 + wm * 64 + mt * 16 + (lane >> 2) + half * 8;
#pragma unroll
            for (int n8 = 0; n8 < 4; ++n8) {
                const int col = n0 + wn * 32 + n8 * 8 + (lane & 3) * 2;
                float v0 = acc[mt][n8][half * 2 + 0] + bb[n8][0];
                float v1 = acc[mt][n8][half * 2 + 1] + bb[n8][1];
                if (RELU) { v0 = fmaxf(v0, 0.0f); v1 = fmaxf(v1, 0.0f); }
                if (MODE == 0)
                    *reinterpret_cast<float2*>(g.C + (size_t)r * ldc + col) = make_float2(v0, v1);
                if (MODE == 1) {   // 2-segment split: consumers are all 2-term
                    __half2 h, l; split2h(v0, v1, h, l);
                    __half* Sr = g.S + (size_t)r * (3 * Nfull) + col;
                    *reinterpret_cast<__half2*>(Sr)         = h;
                    *reinterpret_cast<__half2*>(Sr + Nfull) = l;
                }
            }
        }
    }
}

// ------- pack: fp32 [R,C] -> fp16 split, 4 elems/thread ----------------------
// B_SIDE=false: [hi | lo | (hi)].  B_SIDE=true: [hi | hi | (lo)].
// SEGS=2 skips the third segment store (consumer is 2-term).
template <bool B_SIDE, int SEGS>
__global__ __launch_bounds__(256)
void pack2(const float* __restrict__ src, __half* __restrict__ dst,
           int logC, long total)
{
    const long i = ((long)blockIdx.x * 256 + threadIdx.x) * 4;
    if (i >= total) return;
    const int  C = 1 << logC;
    const long r = i >> logC;
    const int  c = (int)(i & (C - 1));
    const float4 v = *reinterpret_cast<const float4*>(src + i);
    __half2 h0, l0, h1, l1;
    split2h(v.x, v.y, h0, l0);
    split2h(v.z, v.w, h1, l1);
    const uint2 H = pack8h(h0, h1), L = pack8h(l0, l1);
    __half* d = dst + r * (3L * C) + c;
    if (B_SIDE) {
        *reinterpret_cast<uint2*>(d)     = H;
        *reinterpret_cast<uint2*>(d + C) = H;
        if (SEGS == 3) *reinterpret_cast<uint2*>(d + 2 * C) = L;
    } else {
        *reinterpret_cast<uint2*>(d)     = H;
        *reinterpret_cast<uint2*>(d + C) = L;
        if (SEGS == 3) *reinterpret_cast<uint2*>(d + 2 * C) = H;
    }
}

// ------- packh: fp32 -> plain fp16, 4 elems/thread ---------------------------
__global__ __launch_bounds__(256)
void packh(const float* __restrict__ src, __half* __restrict__ dst, long total)
{
    const long i = ((long)blockIdx.x * 256 + threadIdx.x) * 4;
    if (i >= total) return;
    const float4 v = *reinterpret_cast<const float4*>(src + i);
    *reinterpret_cast<uint2*>(dst + i) =
        pack8h(__floats2half2_rn(v.x, v.y), __floats2half2_rn(v.z, v.w));
}

// ------- packadd2: (src0 + src1) -> A-side 3-term split, 4 elems/thread ------
__global__ __launch_bounds__(256)
void packadd2(const float* __restrict__ s0, const float* __restrict__ s1,
              __half* __restrict__ dst, int logC, long total)
{
    const long i = ((long)blockIdx.x * 256 + threadIdx.x) * 4;
    if (i >= total) return;
    const int  C = 1 << logC;
    const long r = i >> logC;
    const int  c = (int)(i & (C - 1));
    const float4 a = *reinterpret_cast<const float4*>(s0 + i);
    const float4 b = *reinterpret_cast<const float4*>(s1 + i);
    __half2 h0, l0, h1, l1;
    split2h(a.x + b.x, a.y + b.y, h0, l0);
    split2h(a.z + b.z, a.w + b.w, h1, l1);
    const uint2 H = pack8h(h0, h1), L = pack8h(l0, l1);
    __half* d = dst + r * (3L * C) + c;
    *reinterpret_cast<uint2*>(d)         = H;
    *reinterpret_cast<uint2*>(d + C)     = L;
    *reinterpret_cast<uint2*>(d + 2 * C) = H;
}

// ------- wrepack: Wre = m1-m2, Wim = m3-m1-m2 -> B-side 2-seg [4096, 3072] ---
// wg layout: m1 rows [0,2048) | m2 [2048,4096) | m3 [4096,6144), each 1024 wide.
__global__ __launch_bounds__(256)
void wrepack(const float* __restrict__ wg, __half* __restrict__ dst)
{
    const long i = ((long)blockIdx.x * 256 + threadIdx.x) * 4;   // [0, 2048*1024)
    const long r = i >> 10;
    const int  c = (int)(i & 1023);
    const float4 m1 = *reinterpret_cast<const float4*>(wg + i);
    const float4 m2 = *reinterpret_cast<const float4*>(wg + 2048L * 1024 + i);
    const float4 m3 = *reinterpret_cast<const float4*>(wg + 2L * 2048 * 1024 + i);
    const float re[4] = {m1.x - m2.x, m1.y - m2.y, m1.z - m2.z, m1.w - m2.w};
    const float im[4] = {m3.x - m1.x - m2.x, m3.y - m1.y - m2.y,
                         m3.z - m1.z - m2.z, m3.w - m1.w - m2.w};
    __half2 h0, l0, h1, l1;
    // Wre row r
    split2h(re[0], re[1], h0, l0); split2h(re[2], re[3], h1, l1);
    {
        const uint2 H = pack8h(h0, h1);
        __half* d = dst + r * 3072 + c;
        *reinterpret_cast<uint2*>(d)        = H;
        *reinterpret_cast<uint2*>(d + 1024) = H;
    }
    // Wim row 2048 + r
    split2h(im[0], im[1], h0, l0); split2h(im[2], im[3], h1, l1);
    {
        const uint2 H = pack8h(h0, h1);
        __half* d = dst + (2048 + r) * 3072 + c;
        *reinterpret_cast<uint2*>(d)        = H;
        *reinterpret_cast<uint2*>(d + 1024) = H;
    }
}

// ------- transpack: W_y halves -> transposed B-side 3-term split --------------
__global__ __launch_bounds__(256)
void transpack(const float* __restrict__ Wy, __half* __restrict__ dst)
{
    __shared__ float tile[32][33];
    const int z  = blockIdx.z;
    const int j0 = blockIdx.x * 32;
    const int k0 = blockIdx.y * 32;
    const int tx = threadIdx.x & 31, ty = threadIdx.x >> 5;

#pragma unroll
    for (int rr = ty; rr < 32; rr += 8) {
        const int k = k0 + rr, j = j0 + tx;
        float v;
        if (z == 0)      v = Wy[(size_t)k * 1024 + j];
        else if (z == 1) v = Wy[(size_t)(k + 2048) * 1024 + j];
        else             v = Wy[(size_t)k * 1024 + j] + Wy[(size_t)(k + 2048) * 1024 + j];
        tile[rr][tx] = v;
    }
    __syncthreads();
#pragma unroll
    for (int rr = ty; rr < 32; rr += 8) {
        const int j = j0 + rr;
        const float v = tile[tx][rr];
        const __half h = __float2half_rn(v);
        const __half l = __float2half_rn(v - __half2float(h));
        __half* d = dst + (size_t)z * 1024 * 6144 + (size_t)j * 6144 + k0 + tx;
        d[0] = h; d[2048] = h; d[4096] = l;
    }
}

// ------- biasdot -> [bre | bim] directly --------------------------------------
__global__ __launch_bounds__(256)
void biasdot(const float* __restrict__ G, const float* __restrict__ Bm,
             const float* __restrict__ b_y, float* __restrict__ breim)
{
    const int c = blockIdx.x, tid = threadIdx.x, lane = tid & 31, w = tid >> 5;
    float s1 = 0, s2 = 0, s3 = 0;
    for (int k = tid; k < 2048; k += 256) {
        const float g = G[(size_t)c * 2048 + k], bm = Bm[(size_t)c * 2048 + k];
        const float byu = b_y[k], byw = b_y[2048 + k];
        s1 += g * byu; s2 += bm * byw; s3 += (g + bm) * (byu + byw);
    }
#pragma unroll
    for (int o = 16; o; o >>= 1) {
        s1 += __shfl_down_sync(0xFFFFFFFFu, s1, o);
        s2 += __shfl_down_sync(0xFFFFFFFFu, s2, o);
        s3 += __shfl_down_sync(0xFFFFFFFFu, s3, o);
    }
    __shared__ float sh[3][8];
    if (lane == 0) { sh[0][w] = s1; sh[1][w] = s2; sh[2][w] = s3; }
    __syncthreads();
    if (tid == 0) {
        float a = 0, b = 0, d = 0;
#pragma unroll
        for (int i = 0; i < 8; ++i) { a += sh[0][i]; b += sh[1][i]; d += sh[2][i]; }
        breim[c] = a - b;                 // bre = bg1 - bg2
        breim[2048 + c] = d - a - b;      // bim = bg3 - bg1 - bg2
    }
}

// ---------------- polar combine -> plain fp16 pp/qp ---------------------------
// t layout: [8192, 4096] with Re = cols [0,2048), Im = cols [2048,4096)
__global__ __launch_bounds__(256)
void combine(const float* __restrict__ uw, const float* __restrict__ t,
             const float* __restrict__ bias_p, const float* __restrict__ bias_q,
             __half* __restrict__ pph, __half* __restrict__ qph)
{
    const long i = ((long)blockIdx.x * 256 + threadIdx.x) * 4;   // [0, 8192*2048)
    const long r = i >> 11;
    const int  c = (int)(i & 2047);
    const float4 u4 = *reinterpret_cast<const float4*>(uw + r * 4096 + c);
    const float4 w4 = *reinterpret_cast<const float4*>(uw + r * 4096 + 2048 + c);
    const float4 re = *reinterpret_cast<const float4*>(t + r * 4096 + c);
    const float4 im = *reinterpret_cast<const float4*>(t + r * 4096 + 2048 + c);
    const float4 bp = *reinterpret_cast<const float4*>(bias_p + c);
    const float4 bq = *reinterpret_cast<const float4*>(bias_q + c);

    float pv[4], qv[4];
    const float uu[4] = {u4.x, u4.y, u4.z, u4.w};
    const float ww[4] = {w4.x, w4.y, w4.z, w4.w};
    const float rr[4] = {re.x, re.y, re.z, re.w};
    const float ii[4] = {im.x, im.y, im.z, im.w};
    const float bpv[4] = {bp.x, bp.y, bp.z, bp.w};
    const float bqv[4] = {bq.x, bq.y, bq.z, bq.w};
#pragma unroll
    for (int j = 0; j < 4; ++j) {
        pv[j] = uu[j] * rr[j] + ww[j] * ii[j] + bpv[j];
        qv[j] = ww[j] * rr[j] - uu[j] * ii[j] + bqv[j];
    }
    *reinterpret_cast<uint2*>(pph + i) =
        pack8h(__floats2half2_rn(pv[0], pv[1]), __floats2half2_rn(pv[2], pv[3]));
    *reinterpret_cast<uint2*>(qph + i) =
        pack8h(__floats2half2_rn(qv[0], qv[1]), __floats2half2_rn(qv[2], qv[3]));
}

// ---------------- host side --------------------------------------------------
extern "C" void kernel_launch(void* const* d_in, const int* in_sizes, int n_in,
                              void* d_out, int out_size)
{
    const float* x      = (const float*)d_in[0];
    const float* W_h    = (const float*)d_in[1];
    const float* b_h    = (const float*)d_in[2];
    const float* W_h2   = (const float*)d_in[3];
    const float* b_h2   = (const float*)d_in[4];
    const float* W_y    = (const float*)d_in[5];
    const float* b_y    = (const float*)d_in[6];
    const float* G      = (const float*)d_in[7];
    const float* Bm     = (const float*)d_in[8];
    const float* bias_p = (const float*)d_in[9];
    const float* bias_q = (const float*)d_in[10];
    const float* W_p    = (const float*)d_in[11];
    const float* b_p    = (const float*)d_in[12];
    const float* W_q    = (const float*)d_in[13];
    const float* b_q    = (const float*)d_in[14];

    float* out = (float*)d_out;
    float* uw  = out;
    float* p   = out + (size_t)8192 * 4096;
    float* q   = p   + (size_t)8192 * 2048;

    __half *xcat, *whcat, *h1cat, *wh2cat, *h2cat, *wycat,
           *gacat, *bacat, *gpacat, *wytcat, *wreim,
           *pph, *qph, *wph, *wqh;
    float *t, *wg, *breim;
    cudaGetSymbolAddress((void**)&xcat,  g_xcat);
    cudaGetSymbolAddress((void**)&whcat, g_whcat);
    cudaGetSymbolAddress((void**)&h1cat, g_h1cat);
    cudaGetSymbolAddress((void**)&wh2cat,g_wh2cat);
    cudaGetSymbolAddress((void**)&h2cat, g_h2cat);
    cudaGetSymbolAddress((void**)&wycat, g_wycat);
    cudaGetSymbolAddress((void**)&gacat, g_gacat);
    cudaGetSymbolAddress((void**)&bacat, g_bacat);
    cudaGetSymbolAddress((void**)&gpacat,g_gpacat);
    cudaGetSymbolAddress((void**)&wytcat,g_wytcat);
    cudaGetSymbolAddress((void**)&wg,    g_wg);
    cudaGetSymbolAddress((void**)&wreim, g_wreim);
    cudaGetSymbolAddress((void**)&breim, g_breim);
    cudaGetSymbolAddress((void**)&t,     g_t);
    cudaGetSymbolAddress((void**)&pph,   g_pph);
    cudaGetSymbolAddress((void**)&qph,   g_qph);
    cudaGetSymbolAddress((void**)&wph,   g_wph);
    cudaGetSymbolAddress((void**)&wqh,   g_wqh);

    cudaFuncSetAttribute(gemm_mma<1, true,  true >, cudaFuncAttributeMaxDynamicSharedMemorySize, SMEM_BYTES);
    cudaFuncSetAttribute(gemm_mma<0, false, false>, cudaFuncAttributeMaxDynamicSharedMemorySize, SMEM_BYTES);
    cudaFuncSetAttribute(gemm_mma<0, false, true >, cudaFuncAttributeMaxDynamicSharedMemorySize, SMEM_BYTES);

    // ---- packs (SEGS=2 where the consumer GEMM is 2-term) ----
    pack2<false, 2><<<(8192L * 4096 / 4 + 255) / 256, 256>>>(x,    xcat,   12, 8192L * 4096);
    pack2<true,  2><<<(1024L * 4096 / 4 + 255) / 256, 256>>>(W_h,  whcat,  12, 1024L * 4096);
    pack2<true,  2><<<(1024L * 1024 / 4 + 255) / 256, 256>>>(W_h2, wh2cat, 10, 1024L * 1024);
    pack2<true,  2><<<(4096L * 1024 / 4 + 255) / 256, 256>>>(W_y,  wycat,  10, 4096L * 1024);
    pack2<false, 3><<<(2048L * 2048 / 4 + 255) / 256, 256>>>(G,    gacat,  11, 2048L * 2048);
    pack2<false, 3><<<(2048L * 2048 / 4 + 255) / 256, 256>>>(Bm,   bacat,  11, 2048L * 2048);
    packadd2<<<(2048L * 2048 / 4 + 255) / 256, 256>>>(G, Bm, gpacat, 11, 2048L * 2048);
    transpack<<<dim3(32, 64, 3), 256>>>(W_y, wytcat);
    biasdot<<<2048, 256>>>(G, Bm, b_y, breim);
    packh<<<(2048L * 2048 / 4 + 255) / 256, 256>>>(W_p, wph, 2048L * 2048);
    packh<<<(2048L * 2048 / 4 + 255) / 256, 256>>>(W_q, wqh, 2048L * 2048);

    const dim3 blk(256);
    // Weight composition (3-term, K'=6144): m1=G@Wyu, m2=Bm@Wyw, m3=(G+Bm)@(Wyu+Wyw)
    {
        GemmArgs a0{gacat,  wytcat,                nullptr, wg,                 nullptr};
        GemmArgs a1{bacat,  wytcat + 1024L * 6144, nullptr, wg + 2048L * 1024,  nullptr};
        GemmArgs a2{gpacat, wytcat + 2048L * 6144, nullptr, wg + 2L * 2048 * 1024, nullptr};
        gemm_mma<0, false, false><<<dim3(1024 / 128, 2048 / 128, 3), blk, SMEM_BYTES>>>(
            a0, a1, a2, 6144, 6144, 1024, 1024, 6144);
    }
    // Weight-level Karatsuba: Wre = m1-m2, Wim = m3-m1-m2 -> 2-seg B-side pack
    wrepack<<<(2048L * 1024 / 4 + 255) / 256, 256>>>(wg, wreim);

    // G1: h1 = relu(x @ W_h^T + b_h) -> 2-seg split h1cat.  2-TERM: K'=8192.
    {
        GemmArgs a{xcat, whcat, b_h, nullptr, h1cat};
        gemm_mma<1, true, true><<<dim3(1024 / 128, 8192 / 128, 1), blk, SMEM_BYTES>>>(
            a, a, a, 12288, 12288, 0, 1024, 8192);
    }
    // G2: h2 = relu(h1 @ W_h2^T + b_h2) -> 2-seg split h2cat.  2-TERM: K'=2048.
    {
        GemmArgs a{h1cat, wh2cat, b_h2, nullptr, h2cat};
        gemm_mma<1, true, true><<<dim3(1024 / 128, 8192 / 128, 1), blk, SMEM_BYTES>>>(
            a, a, a, 3072, 3072, 0, 1024, 2048);
    }
    // G3 + mixing fused (z=2), both [8192,4096], K'=2048:
    //   z=0: uw = h2 @ W_y^T + b_y          -> fp32 uw (d_out)
    //   z=1: [Re|Im] = h2 @ [Wre;Wim]^T + breim -> fp32 t
    {
        GemmArgs a0{h2cat, wycat, b_y,   uw, nullptr};
        GemmArgs a1{h2cat, wreim, breim, t,  nullptr};
        gemm_mma<0, false, true><<<dim3(4096 / 128, 8192 / 128, 2), blk, SMEM_BYTES>>>(
            a0, a1, a0, 3072, 3072, 4096, 4096, 2048);
    }
    // combine -> plain fp16 pp/qp
    combine<<<(8192L * 2048 / 4) / 256, 256>>>(uw, t, bias_p, bias_q, pph, qph);
    // G5/G6: final projections, plain fp16, K=2048 (one launch)
    {
        GemmArgs a0{pph, wph, b_p, p, nullptr};
        GemmArgs a1{qph, wqh, b_q, q, nullptr};
        gemm_mma<0, false, true><<<dim3(2048 / 128, 8192 / 128, 2), blk, SMEM_BYTES>>>(
            a0, a1, a0, 2048, 2048, 2048, 2048, 2048);
    }
}

// round 16
// speedup vs baseline: 2.8480x; 1.0370x over previous
#include <cuda_runtime.h>
#include <cuda_fp16.h>
#include <cstdint>

// ============================================================================
// AutoEncoder_BNN via mma.sync fp16, fp32 accumulate.
// fp32 GEMMs emulated with fp16 split operands:
//   3-term (K'=3K): A=[hi|lo|hi], B=[hi|hi|lo] -> residual ~eps^2 (negligible)
//   2-term (K'=2K): segs [hi|lo] x [hi|hi]     -> residual ~1.4e-4 per GEMM
// R5..R15: Karatsuba -> weight-level Karatsuba; 128x128x64 engine (2 CTA/SM);
// weight composition; plain-fp16 finals; fp16 2-term trunk & mixing.
// R16: (a) compositions 2-term (K'=4096): error only touches p/q via Wre/Wim
//      (~+1.4e-4 there), saves 12.9 GMAC and a third of comp block work;
//      (b) GemmArgs made runtime-parameterized (lda/ldb/ldc/K/nby/mode/relu)
//      so the 3 composition slices FUSE into the G1 launch (z=0 G1, z=1..3
//      comps): 896 useful blocks in one launch vs 2x quantized 2-wave
//      launches -> ~150us of wave-tail removed total.
// ============================================================================

// ---------------- device scratch (static; no runtime allocation) ------------
__device__ __half g_xcat [8192L  * 12288];
__device__ __half g_whcat[1024L  * 12288];
__device__ __half g_h1cat[8192L  * 3072];
__device__ __half g_wh2cat[1024L * 3072];
__device__ __half g_h2cat[8192L  * 3072];
__device__ __half g_wycat[4096L  * 3072];     // W_y B-side (G3, 2-seg)
__device__ __half g_gacat[2048L  * 6144];     // G    A-side (2-seg used)
__device__ __half g_bacat[2048L  * 6144];     // Bm   A-side (2-seg used)
__device__ __half g_gpacat[2048L * 6144];     // G+Bm A-side (2-seg used)
__device__ __half g_wytcat[3L * 1024 * 6144]; // WyuT | WywT | (Wyu+Wyw)T (2-seg used)
__device__ float  g_wg   [3L * 2048 * 1024];  // m1 | m2 | m3 (fp32, stacked rows)
__device__ __half g_wreim[4096L * 3072];      // [Wre;Wim] B-side 2-seg
__device__ float  g_breim[4096];              // [bre | bim]
__device__ float  g_t    [8192L * 4096];      // [Re | Im] row-major
__device__ __half g_pph  [8192L * 2048];      // pp plain fp16
__device__ __half g_qph  [8192L * 2048];      // qp plain fp16
__device__ __half g_wph  [2048L * 2048];      // W_p plain fp16
__device__ __half g_wqh  [2048L * 2048];      // W_q plain fp16

// ---------------- PTX helpers ------------------------------------------------
__device__ __forceinline__ uint32_t smem_u32(const void* p) {
    uint32_t a;
    asm("{ .reg .u64 t; cvta.to.shared.u64 t, %1; cvt.u32.u64 %0, t; }" : "=r"(a) : "l"(p));
    return a;
}
__device__ __forceinline__ void cp_async16(uint32_t dst, const void* src) {
    asm volatile("cp.async.cg.shared.global [%0], [%1], 16;" :: "r"(dst), "l"(src) : "memory");
}
__device__ __forceinline__ void cp_commit() {
    asm volatile("cp.async.commit_group;" ::: "memory");
}
__device__ __forceinline__ void cp_wait1() {
    asm volatile("cp.async.wait_group 1;" ::: "memory");
}
__device__ __forceinline__ void ldsm4(uint32_t* r, uint32_t addr) {
    asm volatile("ldmatrix.sync.aligned.m8n8.x4.shared.b16 {%0,%1,%2,%3}, [%4];"
                 : "=r"(r[0]), "=r"(r[1]), "=r"(r[2]), "=r"(r[3]) : "r"(addr));
}
__device__ __forceinline__ void mma16816(float* c, const uint32_t* a, uint32_t b0, uint32_t b1) {
    asm volatile(
        "mma.sync.aligned.m16n8k16.row.col.f32.f16.f16.f32 "
        "{%0,%1,%2,%3}, {%4,%5,%6,%7}, {%8,%9}, {%0,%1,%2,%3};"
        : "+f"(c[0]), "+f"(c[1]), "+f"(c[2]), "+f"(c[3])
        : "r"(a[0]), "r"(a[1]), "r"(a[2]), "r"(a[3]), "r"(b0), "r"(b1));
}
__device__ __forceinline__ void split2h(float a, float b, __half2& h, __half2& l) {
    const __half ha = __float2half_rn(a);
    const __half hb = __float2half_rn(b);
    h = __halves2half2(ha, hb);
    l = __halves2half2(__float2half_rn(a - __half2float(ha)),
                       __float2half_rn(b - __half2float(hb)));
}
__device__ __forceinline__ uint2 pack8h(__half2 a, __half2 b) {
    uint2 r;
    r.x = *reinterpret_cast<uint32_t*>(&a);
    r.y = *reinterpret_cast<uint32_t*>(&b);
    return r;
}

// ---------------- mma.sync GEMM, tile 128x128x64, 256 threads ----------------
// Runtime-parameterized: one kernel serves heterogeneous z-slices.
// C[M,N] = act(A[M,K'] @ B[N,K']^T + bias); fp16 K-major operands, fp32 accum.
// mode 0: fp32 C.  mode 1: fp16 2-seg split [hi|lo] to S, row stride 3*Nfull.
struct GemmArgs {
    const __half* A;
    const __half* B;
    const float* bias;    // nullptr = no bias
    float* C;
    __half* S;
    int lda, ldb, ldc, Nfull, K;
    int nby;              // valid y-blocks for this slice (early-exit above)
    int mode, relu;
};

constexpr int SMEM_BYTES = 3 * 32768;   // 3 stages x (A 16KB + B 16KB)

__global__ __launch_bounds__(256, 2)
void gemm_mma(GemmArgs g0, GemmArgs g1, GemmArgs g2, GemmArgs g3)
{
    const GemmArgs& g = (blockIdx.z == 0) ? g0 : (blockIdx.z == 1) ? g1 :
                        (blockIdx.z == 2) ? g2 : g3;
    if ((int)blockIdx.y >= g.nby) return;
    extern __shared__ __align__(1024) char smem[];
    const uint32_t sb = smem_u32(smem);
    const int tid = threadIdx.x, lane = tid & 31, wid = tid >> 5;
    const int wm = wid & 1, wn = wid >> 1;            // warp grid 2(m) x 4(n)
    const int m0 = blockIdx.y * 128, n0 = blockIdx.x * 128;

    // ---- global->shared loader mapping (16B chunks, SW128 swizzle) ----
    const int lrow = tid >> 3;
    const int lc16 = tid & 7;
    uint32_t ld_off[4];
#pragma unroll
    for (int w2 = 0; w2 < 4; ++w2) {
        const int r = lrow + w2 * 32;
        ld_off[w2] = r * 128 + ((lc16 * 16) ^ ((r & 7) << 4));
    }
    const __half* Ag = g.A + (size_t)(m0 + lrow) * g.lda + lc16 * 8;
    const __half* Bg = g.B + (size_t)(n0 + lrow) * g.ldb + lc16 * 8;

    // ---- ldmatrix address precompute ----
    uint32_t aTerm[4], aXor[4];
#pragma unroll
    for (int mt = 0; mt < 4; ++mt) {
        const int r = wm * 64 + mt * 16 + ((lane >> 3) & 1) * 8 + (lane & 7);
        aTerm[mt] = r * 128; aXor[mt] = (r & 7) << 4;
    }
    const uint32_t aCol = (lane >> 4) * 16;
    uint32_t bTerm[2], bXor[2];
#pragma unroll
    for (int nt = 0; nt < 2; ++nt) {
        const int r = wn * 32 + nt * 16 + (lane >> 4) * 8 + (lane & 7);
        bTerm[nt] = r * 128; bXor[nt] = (r & 7) << 4;
    }
    const uint32_t bCol = ((lane >> 3) & 1) * 16;

    float acc[4][4][4];
#pragma unroll
    for (int mt = 0; mt < 4; ++mt)
#pragma unroll
        for (int n8 = 0; n8 < 4; ++n8)
#pragma unroll
            for (int j = 0; j < 4; ++j) acc[mt][n8][j] = 0.0f;

    const int nst = g.K / 64;
    const int lda = g.lda, ldb = g.ldb;

    auto issue = [&](int s, int kt) {
        const uint32_t sa = sb + (uint32_t)s * 32768u;
#pragma unroll
        for (int w2 = 0; w2 < 4; ++w2)
            cp_async16(sa + ld_off[w2], Ag + (size_t)w2 * 32 * lda + kt);
#pragma unroll
        for (int w2 = 0; w2 < 4; ++w2)
            cp_async16(sa + 16384u + ld_off[w2], Bg + (size_t)w2 * 32 * ldb + kt);
        cp_commit();
    };

    issue(0, 0);
    issue(1, 64);

    for (int i = 0; i < nst; ++i) {
        cp_wait1();
        __syncthreads();
        if (i + 2 < nst) issue((i + 2) % 3, (i + 2) * 64);
        else             cp_commit();

        const uint32_t sa = sb + (uint32_t)(i % 3) * 32768u;
        const uint32_t sB = sa + 16384u;
#pragma unroll
        for (int kk = 0; kk < 4; ++kk) {
            uint32_t a[4][4], b[2][4];
#pragma unroll
            for (int mt = 0; mt < 4; ++mt)
                ldsm4(a[mt], sa + aTerm[mt] + ((kk * 32 + aCol) ^ aXor[mt]));
#pragma unroll
            for (int nt = 0; nt < 2; ++nt)
                ldsm4(b[nt], sB + bTerm[nt] + ((kk * 32 + bCol) ^ bXor[nt]));
#pragma unroll
            for (int mt = 0; mt < 4; ++mt)
#pragma unroll
                for (int n8 = 0; n8 < 4; ++n8)
                    mma16816(acc[mt][n8], a[mt],
                             b[n8 >> 1][(n8 & 1) * 2], b[n8 >> 1][(n8 & 1) * 2 + 1]);
        }
        // no trailing sync (next iteration's sync orders stage reuse)
    }

    // ---- epilogue (runtime mode/relu/bias branches; cost ~3% of kernel) ----
    float bb[4][2];
#pragma unroll
    for (int n8 = 0; n8 < 4; ++n8) {
        if (g.bias) {
            const int col = n0 + wn * 32 + n8 * 8 + (lane & 3) * 2;
            bb[n8][0] = __ldg(&g.bias[col]);
            bb[n8][1] = __ldg(&g.bias[col + 1]);
        } else { bb[n8][0] = 0.0f; bb[n8][1] = 0.0f; }
    }

#pragma unroll
    for (int mt = 0; mt < 4; ++mt) {
#pragma unroll
        for (int half = 0; half < 2; ++half) {
            const int r = m0 + wm * 64 + mt * 16 + (lane >> 2) + half * 8;
#pragma unroll
            for (int n8 = 0; n8 < 4; ++n8) {
                const int col = n0 + wn * 32 + n8 * 8 + (lane & 3) * 2;
                float v0 = acc[mt][n8][half * 2 + 0] + bb[n8][0];
                float v1 = acc[mt][n8][half * 2 + 1] + bb[n8][1];
                if (g.relu) { v0 = fmaxf(v0, 0.0f); v1 = fmaxf(v1, 0.0f); }
                if (g.mode == 0) {
                    *reinterpret_cast<float2*>(g.C + (size_t)r * g.ldc + col) = make_float2(v0, v1);
                } else {           // 2-segment split: consumers are all 2-term
                    __half2 h, l; split2h(v0, v1, h, l);
                    __half* Sr = g.S + (size_t)r * (3 * g.Nfull) + col;
                    *reinterpret_cast<__half2*>(Sr)           = h;
                    *reinterpret_cast<__half2*>(Sr + g.Nfull) = l;
                }
            }
        }
    }
}

// ------- pack: fp32 [R,C] -> fp16 split, 4 elems/thread ----------------------
// B_SIDE=false: [hi | lo].  B_SIDE=true: [hi | hi].  (2-seg; stride stays 3C)
template <bool B_SIDE>
__global__ __launch_bounds__(256)
void pack2(const float* __restrict__ src, __half* __restrict__ dst,
           int logC, long total)
{
    const long i = ((long)blockIdx.x * 256 + threadIdx.x) * 4;
    if (i >= total) return;
    const int  C = 1 << logC;
    const long r = i >> logC;
    const int  c = (int)(i & (C - 1));
    const float4 v = *reinterpret_cast<const float4*>(src + i);
    __half2 h0, l0, h1, l1;
    split2h(v.x, v.y, h0, l0);
    split2h(v.z, v.w, h1, l1);
    const uint2 H = pack8h(h0, h1), L = pack8h(l0, l1);
    __half* d = dst + r * (3L * C) + c;
    *reinterpret_cast<uint2*>(d)     = H;
    *reinterpret_cast<uint2*>(d + C) = B_SIDE ? H : L;
}

// ------- packh: fp32 -> plain fp16, 4 elems/thread ---------------------------
__global__ __launch_bounds__(256)
void packh(const float* __restrict__ src, __half* __restrict__ dst, long total)
{
    const long i = ((long)blockIdx.x * 256 + threadIdx.x) * 4;
    if (i >= total) return;
    const float4 v = *reinterpret_cast<const float4*>(src + i);
    *reinterpret_cast<uint2*>(dst + i) =
        pack8h(__floats2half2_rn(v.x, v.y), __floats2half2_rn(v.z, v.w));
}

// ------- packadd2: (src0 + src1) -> A-side 2-seg split, 4 elems/thread -------
__global__ __launch_bounds__(256)
void packadd2(const float* __restrict__ s0, const float* __restrict__ s1,
              __half* __restrict__ dst, int logC, long total)
{
    const long i = ((long)blockIdx.x * 256 + threadIdx.x) * 4;
    if (i >= total) return;
    const int  C = 1 << logC;
    const long r = i >> logC;
    const int  c = (int)(i & (C - 1));
    const float4 a = *reinterpret_cast<const float4*>(s0 + i);
    const float4 b = *reinterpret_cast<const float4*>(s1 + i);
    __half2 h0, l0, h1, l1;
    split2h(a.x + b.x, a.y + b.y, h0, l0);
    split2h(a.z + b.z, a.w + b.w, h1, l1);
    __half* d = dst + r * (3L * C) + c;
    *reinterpret_cast<uint2*>(d)     = pack8h(h0, h1);
    *reinterpret_cast<uint2*>(d + C) = pack8h(l0, l1);
}

// ------- wrepack: Wre = m1-m2, Wim = m3-m1-m2 -> B-side 2-seg [4096, 3072] ---
__global__ __launch_bounds__(256)
void wrepack(const float* __restrict__ wg, __half* __restrict__ dst)
{
    const long i = ((long)blockIdx.x * 256 + threadIdx.x) * 4;   // [0, 2048*1024)
    const long r = i >> 10;
    const int  c = (int)(i & 1023);
    const float4 m1 = *reinterpret_cast<const float4*>(wg + i);
    const float4 m2 = *reinterpret_cast<const float4*>(wg + 2048L * 1024 + i);
    const float4 m3 = *reinterpret_cast<const float4*>(wg + 2L * 2048 * 1024 + i);
    const float re[4] = {m1.x - m2.x, m1.y - m2.y, m1.z - m2.z, m1.w - m2.w};
    const float im[4] = {m3.x - m1.x - m2.x, m3.y - m1.y - m2.y,
                         m3.z - m1.z - m2.z, m3.w - m1.w - m2.w};
    __half2 h0, l0, h1, l1;
    split2h(re[0], re[1], h0, l0); split2h(re[2], re[3], h1, l1);
    {
        const uint2 H = pack8h(h0, h1);
        __half* d = dst + r * 3072 + c;
        *reinterpret_cast<uint2*>(d)        = H;
        *reinterpret_cast<uint2*>(d + 1024) = H;
    }
    split2h(im[0], im[1], h0, l0); split2h(im[2], im[3], h1, l1);
    {
        const uint2 H = pack8h(h0, h1);
        __half* d = dst + (2048 + r) * 3072 + c;
        *reinterpret_cast<uint2*>(d)        = H;
        *reinterpret_cast<uint2*>(d + 1024) = H;
    }
}

// ------- transpack: W_y halves -> transposed B-side 2-seg split ---------------
__global__ __launch_bounds__(256)
void transpack(const float* __restrict__ Wy, __half* __restrict__ dst)
{
    __shared__ float tile[32][33];
    const int z  = blockIdx.z;
    const int j0 = blockIdx.x * 32;
    const int k0 = blockIdx.y * 32;
    const int tx = threadIdx.x & 31, ty = threadIdx.x >> 5;

#pragma unroll
    for (int rr = ty; rr < 32; rr += 8) {
        const int k = k0 + rr, j = j0 + tx;
        float v;
        if (z == 0)      v = Wy[(size_t)k * 1024 + j];
        else if (z == 1) v = Wy[(size_t)(k + 2048) * 1024 + j];
        else             v = Wy[(size_t)k * 1024 + j] + Wy[(size_t)(k + 2048) * 1024 + j];
        tile[rr][tx] = v;
    }
    __syncthreads();
#pragma unroll
    for (int rr = ty; rr < 32; rr += 8) {
        const int j = j0 + rr;
        const float v = tile[tx][rr];
        const __half h = __float2half_rn(v);
        __half* d = dst + (size_t)z * 1024 * 6144 + (size_t)j * 6144 + k0 + tx;
        d[0] = h; d[2048] = h;       // 2-seg B-side [hi|hi]
    }
}

// ------- biasdot -> [bre | bim] ------------------------------------------------
__global__ __launch_bounds__(256)
void biasdot(const float* __restrict__ G, const float* __restrict__ Bm,
             const float* __restrict__ b_y, float* __restrict__ breim)
{
    const int c = blockIdx.x, tid = threadIdx.x, lane = tid & 31, w = tid >> 5;
    float s1 = 0, s2 = 0, s3 = 0;
    for (int k = tid; k < 2048; k += 256) {
        const float g = G[(size_t)c * 2048 + k], bm = Bm[(size_t)c * 2048 + k];
        const float byu = b_y[k], byw = b_y[2048 + k];
        s1 += g * byu; s2 += bm * byw; s3 += (g + bm) * (byu + byw);
    }
#pragma unroll
    for (int o = 16; o; o >>= 1) {
        s1 += __shfl_down_sync(0xFFFFFFFFu, s1, o);
        s2 += __shfl_down_sync(0xFFFFFFFFu, s2, o);
        s3 += __shfl_down_sync(0xFFFFFFFFu, s3, o);
    }
    __shared__ float sh[3][8];
    if (lane == 0) { sh[0][w] = s1; sh[1][w] = s2; sh[2][w] = s3; }
    __syncthreads();
    if (tid == 0) {
        float a = 0, b = 0, d = 0;
#pragma unroll
        for (int i = 0; i < 8; ++i) { a += sh[0][i]; b += sh[1][i]; d += sh[2][i]; }
        breim[c] = a - b;                 // bre = bg1 - bg2
        breim[2048 + c] = d - a - b;      // bim = bg3 - bg1 - bg2
    }
}

// ---------------- polar combine -> plain fp16 pp/qp ---------------------------
__global__ __launch_bounds__(256)
void combine(const float* __restrict__ uw, const float* __restrict__ t,
             const float* __restrict__ bias_p, const float* __restrict__ bias_q,
             __half* __restrict__ pph, __half* __restrict__ qph)
{
    const long i = ((long)blockIdx.x * 256 + threadIdx.x) * 4;   // [0, 8192*2048)
    const long r = i >> 11;
    const int  c = (int)(i & 2047);
    const float4 u4 = *reinterpret_cast<const float4*>(uw + r * 4096 + c);
    const float4 w4 = *reinterpret_cast<const float4*>(uw + r * 4096 + 2048 + c);
    const float4 re = *reinterpret_cast<const float4*>(t + r * 4096 + c);
    const float4 im = *reinterpret_cast<const float4*>(t + r * 4096 + 2048 + c);
    const float4 bp = *reinterpret_cast<const float4*>(bias_p + c);
    const float4 bq = *reinterpret_cast<const float4*>(bias_q + c);

    float pv[4], qv[4];
    const float uu[4] = {u4.x, u4.y, u4.z, u4.w};
    const float ww[4] = {w4.x, w4.y, w4.z, w4.w};
    const float rr[4] = {re.x, re.y, re.z, re.w};
    const float ii[4] = {im.x, im.y, im.z, im.w};
    const float bpv[4] = {bp.x, bp.y, bp.z, bp.w};
    const float bqv[4] = {bq.x, bq.y, bq.z, bq.w};
#pragma unroll
    for (int j = 0; j < 4; ++j) {
        pv[j] = uu[j] * rr[j] + ww[j] * ii[j] + bpv[j];
        qv[j] = ww[j] * rr[j] - uu[j] * ii[j] + bqv[j];
    }
    *reinterpret_cast<uint2*>(pph + i) =
        pack8h(__floats2half2_rn(pv[0], pv[1]), __floats2half2_rn(pv[2], pv[3]));
    *reinterpret_cast<uint2*>(qph + i) =
        pack8h(__floats2half2_rn(qv[0], qv[1]), __floats2half2_rn(qv[2], qv[3]));
}

// ---------------- host side --------------------------------------------------
extern "C" void kernel_launch(void* const* d_in, const int* in_sizes, int n_in,
                              void* d_out, int out_size)
{
    const float* x      = (const float*)d_in[0];
    const float* W_h    = (const float*)d_in[1];
    const float* b_h    = (const float*)d_in[2];
    const float* W_h2   = (const float*)d_in[3];
    const float* b_h2   = (const float*)d_in[4];
    const float* W_y    = (const float*)d_in[5];
    const float* b_y    = (const float*)d_in[6];
    const float* G      = (const float*)d_in[7];
    const float* Bm     = (const float*)d_in[8];
    const float* bias_p = (const float*)d_in[9];
    const float* bias_q = (const float*)d_in[10];
    const float* W_p    = (const float*)d_in[11];
    const float* b_p    = (const float*)d_in[12];
    const float* W_q    = (const float*)d_in[13];
    const float* b_q    = (const float*)d_in[14];

    float* out = (float*)d_out;
    float* uw  = out;
    float* p   = out + (size_t)8192 * 4096;
    float* q   = p   + (size_t)8192 * 2048;

    __half *xcat, *whcat, *h1cat, *wh2cat, *h2cat, *wycat,
           *gacat, *bacat, *gpacat, *wytcat, *wreim,
           *pph, *qph, *wph, *wqh;
    float *t, *wg, *breim;
    cudaGetSymbolAddress((void**)&xcat,  g_xcat);
    cudaGetSymbolAddress((void**)&whcat, g_whcat);
    cudaGetSymbolAddress((void**)&h1cat, g_h1cat);
    cudaGetSymbolAddress((void**)&wh2cat,g_wh2cat);
    cudaGetSymbolAddress((void**)&h2cat, g_h2cat);
    cudaGetSymbolAddress((void**)&wycat, g_wycat);
    cudaGetSymbolAddress((void**)&gacat, g_gacat);
    cudaGetSymbolAddress((void**)&bacat, g_bacat);
    cudaGetSymbolAddress((void**)&gpacat,g_gpacat);
    cudaGetSymbolAddress((void**)&wytcat,g_wytcat);
    cudaGetSymbolAddress((void**)&wg,    g_wg);
    cudaGetSymbolAddress((void**)&wreim, g_wreim);
    cudaGetSymbolAddress((void**)&breim, g_breim);
    cudaGetSymbolAddress((void**)&t,     g_t);
    cudaGetSymbolAddress((void**)&pph,   g_pph);
    cudaGetSymbolAddress((void**)&qph,   g_qph);
    cudaGetSymbolAddress((void**)&wph,   g_wph);
    cudaGetSymbolAddress((void**)&wqh,   g_wqh);

    cudaFuncSetAttribute(gemm_mma, cudaFuncAttributeMaxDynamicSharedMemorySize, SMEM_BYTES);

    // ---- packs (all splits 2-seg now) ----
    pack2<false><<<(8192L * 4096 / 4 + 255) / 256, 256>>>(x,    xcat,   12, 8192L * 4096);
    pack2<true ><<<(1024L * 4096 / 4 + 255) / 256, 256>>>(W_h,  whcat,  12, 1024L * 4096);
    pack2<true ><<<(1024L * 1024 / 4 + 255) / 256, 256>>>(W_h2, wh2cat, 10, 1024L * 1024);
    pack2<true ><<<(4096L * 1024 / 4 + 255) / 256, 256>>>(W_y,  wycat,  10, 4096L * 1024);
    pack2<false><<<(2048L * 2048 / 4 + 255) / 256, 256>>>(G,    gacat,  11, 2048L * 2048);
    pack2<false><<<(2048L * 2048 / 4 + 255) / 256, 256>>>(Bm,   bacat,  11, 2048L * 2048);
    packadd2<<<(2048L * 2048 / 4 + 255) / 256, 256>>>(G, Bm, gpacat, 11, 2048L * 2048);
    transpack<<<dim3(32, 64, 3), 256>>>(W_y, wytcat);
    biasdot<<<2048, 256>>>(G, Bm, b_y, breim);
    packh<<<(2048L * 2048 / 4 + 255) / 256, 256>>>(W_p, wph, 2048L * 2048);
    packh<<<(2048L * 2048 / 4 + 255) / 256, 256>>>(W_q, wqh, 2048L * 2048);

    const dim3 blk(256);
    // FUSED launch: z=0 G1 (M=8192,N=1024,K'=8192 2-term, relu+bias -> split h1cat)
    //               z=1..3 compositions (M=2048,N=1024,K'=4096 2-term -> fp32 wg)
    {
        GemmArgs a0{xcat,   whcat,                 b_h,     nullptr, h1cat,
                    12288, 12288, 0,    1024, 8192, 64, 1, 1};
        GemmArgs a1{gacat,  wytcat,                nullptr, wg,                    nullptr,
                    6144,  6144,  1024, 0,    4096, 16, 0, 0};
        GemmArgs a2{bacat,  wytcat + 1024L * 6144, nullptr, wg + 2048L * 1024,     nullptr,
                    6144,  6144,  1024, 0,    4096, 16, 0, 0};
        GemmArgs a3{gpacat, wytcat + 2048L * 6144, nullptr, wg + 2L * 2048 * 1024, nullptr,
                    6144,  6144,  1024, 0,    4096, 16, 0, 0};
        gemm_mma<<<dim3(8, 64, 4), blk, SMEM_BYTES>>>(a0, a1, a2, a3);
    }
    // Weight-level Karatsuba: Wre = m1-m2, Wim = m3-m1-m2 -> 2-seg B-side pack
    wrepack<<<(2048L * 1024 / 4 + 255) / 256, 256>>>(wg, wreim);

    // G2: h2 = relu(h1 @ W_h2^T + b_h2) -> 2-seg split h2cat.  K'=2048.
    {
        GemmArgs a{h1cat, wh2cat, b_h2, nullptr, h2cat,
                   3072, 3072, 0, 1024, 2048, 64, 1, 1};
        gemm_mma<<<dim3(8, 64, 1), blk, SMEM_BYTES>>>(a, a, a, a);
    }
    // G3 + mixing (z=2), both [8192,4096], K'=2048:
    //   z=0: uw = h2 @ W_y^T + b_y              -> fp32 uw (d_out)
    //   z=1: [Re|Im] = h2 @ [Wre;Wim]^T + breim -> fp32 t
    {
        GemmArgs a0{h2cat, wycat, b_y,   uw, nullptr, 3072, 3072, 4096, 0, 2048, 64, 0, 0};
        GemmArgs a1{h2cat, wreim, breim, t,  nullptr, 3072, 3072, 4096, 0, 2048, 64, 0, 0};
        gemm_mma<<<dim3(32, 64, 2), blk, SMEM_BYTES>>>(a0, a1, a0, a0);
    }
    // combine -> plain fp16 pp/qp
    combine<<<(8192L * 2048 / 4) / 256, 256>>>(uw, t, bias_p, bias_q, pph, qph);
    // G5/G6: final projections, plain fp16, K=2048 (one launch)
    {
        GemmArgs a0{pph, wph, b_p, p, nullptr, 2048, 2048, 2048, 0, 2048, 64, 0, 0};
        GemmArgs a1{qph, wqh, b_q, q, nullptr, 2048, 2048, 2048, 0, 2048, 64, 0, 0};
        gemm_mma<<<dim3(16, 64, 2), blk, SMEM_BYTES>>>(a0, a1, a0, a0);
    }
}